// round 7
// baseline (speedup 1.0000x reference)
#include <cuda_runtime.h>
#include <cuda_fp16.h>
#include <math.h>
#include <stdint.h>

#define NB   32
#define NS   256
#define ND   512
#define NH   8
#define NE   8
#define NHID 2048
#define NPD  588
#define NPDP 608
#define NTOK 8192
#define NA   16384

#define SZ_LN   ((size_t)NTOK * ND)
#define SZ_P    ((size_t)NTOK * NPDP)
#define SZ_ATTN ((size_t)NB * NH * NS * NS)
#define SZ_H    ((size_t)NA * NHID)
#define SZ_W    ((size_t)NE * ND * NHID)
#define SZ_DD   ((size_t)ND * ND)

// ---------------- fp32 scratch -------------------------------------------------
__device__ float g_e[NTOK * ND];
__device__ float g_ln[NTOK * ND];
__device__ float g_attn[NB * NH * NS * NS];
__device__ float g_probs[NTOK * NE];
__device__ float g_gate[NA];
__device__ int   g_perm[NE * NA];
__device__ int   g_cnt[NE];
__device__ float g_imp[NE];
__device__ float g_contrib[NA * ND];
__device__ float g_o1[NTOK * ND];
__device__ float g_o2[NTOK * ND];
__device__ float g_fv[NB * ND];
__device__ float g_bqkv[3 * ND];

// ---------------- split fp16 buffers (hi at [0], lo at [SIZE] per segment) -----
__device__ __half g_p16[2 * SZ_P];
__device__ __half g_ln16[2 * SZ_LN];
__device__ __half g_qkv16[6 * SZ_LN];
__device__ __half g_attn16[2 * SZ_ATTN];
__device__ __half g_ctx16[2 * SZ_LN];
__device__ __half g_h16[2 * SZ_H];
__device__ __half g_pew16[2 * NPDP * ND];
__device__ __half g_wqkv16[6 * SZ_DD];
__device__ __half g_wo16[2 * SZ_DD];
__device__ __half g_w1a16[2 * SZ_W];
__device__ __half g_w2a16[2 * SZ_W];
__device__ __half g_w1b16[2 * SZ_W];
__device__ __half g_w2b16[2 * SZ_W];

// ---------------- persistent side stream ---------------------------------------
struct SideStream {
    cudaStream_t s;
    cudaEvent_t fork, join;
    SideStream() {
        cudaStreamCreateWithFlags(&s, cudaStreamNonBlocking);
        cudaEventCreateWithFlags(&fork, cudaEventDisableTiming);
        cudaEventCreateWithFlags(&join, cudaEventDisableTiming);
    }
};
static SideStream g_ss;

__device__ __forceinline__ float gelu_exact(float v) {
    return 0.5f * v * (1.0f + erff(v * 0.70710678118654752440f));
}
__device__ __forceinline__ void split2(float v0, float v1, __half* oh, __half* ol) {
    __half h0 = __float2half_rn(v0), h1 = __float2half_rn(v1);
    *(__half2*)oh = __halves2half2(h0, h1);
    *(__half2*)ol = __halves2half2(__float2half_rn(v0 - __half2float(h0)),
                                   __float2half_rn(v1 - __half2float(h1)));
}

// ---------------- mma.sync helpers ----------------------------------------------
__device__ __forceinline__ void ldsm4(unsigned* r, unsigned addr) {
    asm volatile("ldmatrix.sync.aligned.m8n8.x4.shared.b16 {%0,%1,%2,%3}, [%4];\n"
        : "=r"(r[0]), "=r"(r[1]), "=r"(r[2]), "=r"(r[3]) : "r"(addr));
}
__device__ __forceinline__ void ldsm4t(unsigned* r, unsigned addr) {
    asm volatile("ldmatrix.sync.aligned.m8n8.x4.trans.shared.b16 {%0,%1,%2,%3}, [%4];\n"
        : "=r"(r[0]), "=r"(r[1]), "=r"(r[2]), "=r"(r[3]) : "r"(addr));
}
__device__ __forceinline__ void mma16816(float* c, const unsigned* a, const unsigned* b) {
    asm volatile("mma.sync.aligned.m16n8k16.row.col.f32.f16.f16.f32 "
        "{%0,%1,%2,%3}, {%4,%5,%6,%7}, {%8,%9}, {%0,%1,%2,%3};\n"
        : "+f"(c[0]), "+f"(c[1]), "+f"(c[2]), "+f"(c[3])
        : "r"(a[0]), "r"(a[1]), "r"(a[2]), "r"(a[3]), "r"(b[0]), "r"(b[1]));
}
__device__ __forceinline__ void cpa16(unsigned dst, const void* src, bool p) {
    int sz = p ? 16 : 0;
    asm volatile("cp.async.cg.shared.global [%0], [%1], 16, %2;\n"
        :: "r"(dst), "l"(src), "r"(sz));
}

// ================= FF grouped GEMM (mma.sync, BM=256 x BN=128) ==================
// 256 threads, 8 warps as 4(m) x 2(n); warp tile 64x64; 3-pass split fp16.
// Dynamic smem 64KB:
//   A(buf,hl): halves offset (buf*2+hl)*6144   (256 rows x 24-stride)
//   B(buf,hl): 24576 + (buf*2+hl)*2048         (16 x 128)
template <int KTOT, int NTOT, int SHIFT, bool GELU>
__global__ __launch_bounds__(256, 1) void ff16_k(
    const __half* __restrict__ Xh, size_t alo,
    const __half* __restrict__ Wh, size_t blo,
    const float* __restrict__ bias, void* __restrict__ Out)
{
    constexpr int KT = KTOT / 16;
    extern __shared__ __half smemh[];
    __shared__ int s_idx[256];

    int e = blockIdx.z;
    int cnt = g_cnt[e];
    int row0 = blockIdx.y * 256;
    if (row0 >= cnt) return;
    int col0 = blockIdx.x * 128;

    int tid = threadIdx.x;
    {
        int r = row0 + tid;
        s_idx[tid] = (r < cnt) ? g_perm[e * NA + r] : -1;
    }
    __syncthreads();

    const __half* We = Wh + (size_t)e * KTOT * NTOT;

    // A: 2 items/thread (item = tid + it*256): row=item>>1, ch=item&1
    unsigned a_dst[2];
    const __half* a_srch[2]; const __half* a_srcl[2]; bool a_pred[2];
#pragma unroll
    for (int it = 0; it < 2; it++) {
        int item = tid + it * 256;
        int arow = item >> 1, ch = item & 1;
        a_dst[it] = (unsigned)((arow * 24 + ch * 8) * 2);
        int a = s_idx[arow];
        a_pred[it] = (a >= 0);
        size_t off = a_pred[it] ? (size_t)(a >> SHIFT) * KTOT + ch * 8 : 0;
        a_srch[it] = Xh + off;
        a_srcl[it] = Xh + alo + off;
    }
    // B: 1 item/thread: row=tid/16 (0..15), cn=tid%16
    int brow = tid >> 4, bcn = tid & 15;
    int bsw = bcn ^ (brow & 7);
    unsigned b_dst = (unsigned)((brow * 128 + bsw * 8) * 2);
    size_t boff0 = (size_t)brow * NTOT + col0 + bcn * 8;
    const __half* b_srch = We + boff0;
    const __half* b_srcl = We + blo + boff0;

    unsigned sbase = (unsigned)__cvta_generic_to_shared(smemh);

    auto issue = [&](int kt, int buf) {
        unsigned abh = sbase + (unsigned)(buf * 2 + 0) * 12288u;
        unsigned abl = sbase + (unsigned)(buf * 2 + 1) * 12288u;
#pragma unroll
        for (int it = 0; it < 2; it++) {
            cpa16(abh + a_dst[it], a_srch[it] + (size_t)kt * 16, a_pred[it]);
            cpa16(abl + a_dst[it], a_srcl[it] + (size_t)kt * 16, a_pred[it]);
        }
        unsigned bbh = sbase + 49152u + (unsigned)(buf * 2 + 0) * 4096u;
        unsigned bbl = sbase + 49152u + (unsigned)(buf * 2 + 1) * 4096u;
        size_t ko = (size_t)kt * 16 * NTOT;
        cpa16(bbh + b_dst, b_srch + ko, true);
        cpa16(bbl + b_dst, b_srcl + ko, true);
        asm volatile("cp.async.commit_group;\n");
    };

    int lane = tid & 31;
    int warp = tid >> 5;
    int wm = warp >> 1, wn = warp & 1;

    float acc[4][8][4];
#pragma unroll
    for (int i = 0; i < 4; i++)
#pragma unroll
        for (int j = 0; j < 8; j++)
#pragma unroll
            for (int t = 0; t < 4; t++) acc[i][j][t] = 0.f;

    issue(0, 0);
#pragma unroll 1
    for (int kt = 0; kt < KT; kt++) {
        int buf = kt & 1;
        if (kt + 1 < KT) {
            issue(kt + 1, buf ^ 1);
            asm volatile("cp.async.wait_group 1;\n");
        } else {
            asm volatile("cp.async.wait_group 0;\n");
        }
        __syncthreads();
        unsigned abh = sbase + (unsigned)(buf * 2 + 0) * 12288u;
        unsigned abl = sbase + (unsigned)(buf * 2 + 1) * 12288u;
        unsigned bbh = sbase + 49152u + (unsigned)(buf * 2 + 0) * 4096u;
        unsigned bbl = sbase + 49152u + (unsigned)(buf * 2 + 1) * 4096u;

        unsigned ah[4][4], al[4][4];
#pragma unroll
        for (int i = 0; i < 4; i++) {
            int m = wm * 64 + i * 16 + (lane & 15);
            int ch = lane >> 4;
            unsigned ad = (unsigned)((m * 24 + ch * 8) * 2);
            ldsm4(ah[i], abh + ad);
            ldsm4(al[i], abl + ad);
        }
#pragma unroll
        for (int jj = 0; jj < 4; jj++) {
            int n0 = wn * 64 + jj * 16;
            int k = lane & 15;
            int cn = (n0 >> 3) + (lane >> 4);
            int sw = cn ^ (k & 7);
            unsigned bd = (unsigned)((k * 128 + sw * 8) * 2);
            unsigned brh[4], brl[4];
            ldsm4t(brh, bbh + bd);
            ldsm4t(brl, bbl + bd);
#pragma unroll
            for (int i = 0; i < 4; i++) {
                mma16816(acc[i][jj * 2 + 0], ah[i], &brh[0]);
                mma16816(acc[i][jj * 2 + 0], al[i], &brh[0]);
                mma16816(acc[i][jj * 2 + 0], ah[i], &brl[0]);
                mma16816(acc[i][jj * 2 + 1], ah[i], &brh[2]);
                mma16816(acc[i][jj * 2 + 1], al[i], &brh[2]);
                mma16816(acc[i][jj * 2 + 1], ah[i], &brl[2]);
            }
        }
        __syncthreads();
    }

    // epilogue
    int rl = lane >> 2, cp2 = (lane & 3) * 2;
    const float* bi = bias + (size_t)e * NTOT;
#pragma unroll
    for (int i = 0; i < 4; i++) {
#pragma unroll
        for (int hh = 0; hh < 2; hh++) {
            int rr = wm * 64 + i * 16 + rl + hh * 8;
            int aidx = s_idx[rr];
            if (aidx < 0) continue;
#pragma unroll
            for (int j = 0; j < 8; j++) {
                int c = col0 + wn * 64 + j * 8 + cp2;
                float v0 = acc[i][j][hh * 2 + 0] + bi[c];
                float v1 = acc[i][j][hh * 2 + 1] + bi[c + 1];
                size_t o = (size_t)aidx * NTOT + c;
                if (GELU) {
                    v0 = gelu_exact(v0); v1 = gelu_exact(v1);
                    __half* O = (__half*)Out;
                    split2(v0, v1, O + o, O + SZ_H + o);
                } else {
                    float* O = (float*)Out;
                    *(float2*)(O + o) = make_float2(v0, v1);
                }
            }
        }
    }
}

// ---------------- modes (mma.sync kernel, attention path) -----------------------
#define M_PE   0
#define M_QKV  1
#define M_PROJ 2
#define M_SC   3
#define M_AV   4

template <int MODE>
__global__ __launch_bounds__(256) void mm_k(
    const __half* __restrict__ Ag, const __half* __restrict__ Bg,
    const float* __restrict__ bias, const float* __restrict__ extra,
    void* __restrict__ Og)
{
    constexpr int K   = (MODE == M_PE) ? NPDP : (MODE == M_SC) ? 64 :
                        (MODE == M_AV) ? 256 : 512;
    constexpr int LDA = K;
    constexpr int LDB = (MODE == M_SC || MODE == M_AV) ? 64 : 512;
    constexpr bool NT = (MODE == M_SC);
    constexpr int BN = (MODE == M_AV || MODE == M_SC) ? 64 : 128;
    constexpr int WN = BN / 4;
    constexpr int NF = WN / 8;
    constexpr int KT = K / 16;
    constexpr size_t ALO =
        (MODE == M_PE)  ? SZ_P :
        (MODE == M_AV)  ? SZ_ATTN : SZ_LN;
    constexpr size_t BLO =
        (MODE == M_PE)  ? (size_t)NPDP * ND :
        (MODE == M_QKV || MODE == M_PROJ) ? SZ_DD : SZ_LN;
    constexpr size_t OLO = SZ_LN;
    constexpr int AST = 128 * 24;
    constexpr int BST = NT ? BN * 24 : 16 * BN;

    __shared__ __align__(16) __half As[2][2][AST];
    __shared__ __align__(16) __half Bs[2][2][BST];

    int tid = threadIdx.x;
    int bz = blockIdx.z;
    int row0 = blockIdx.y * 128, col0 = blockIdx.x * BN;

    const __half* Ah = Ag;
    const __half* Bh = Bg;
    if (MODE == M_SC)  { Ah += (size_t)bz * 256 * 64; Bh += (size_t)bz * 256 * 64; }
    if (MODE == M_AV)  { Ah += (size_t)bz * 65536;    Bh += (size_t)bz * 256 * 64; }
    if (MODE == M_QKV) { Bh += (size_t)bz * 2 * SZ_DD; }
    const __half* Al = Ah + ALO;
    const __half* Bl = Bh + BLO;

    int a_row = tid >> 1, a_ch = tid & 1;
    unsigned a_dst = (unsigned)((a_row * 24 + a_ch * 8) * 2);
    size_t aoff = (size_t)(row0 + a_row) * LDA + a_ch * 8;
    const __half* a_srch = Ah + aoff;
    const __half* a_srcl = Al + aoff;

    unsigned b_dst = 0; const __half* b_srch = Bh; const __half* b_srcl = Bh;
    bool b_val;
    if (!NT) {
        b_val = tid < (16 * BN / 8);
        int row = tid / (BN / 8), cn = tid % (BN / 8);
        int sw = cn ^ (row & 7);
        b_dst = (unsigned)((row * BN + sw * 8) * 2);
        size_t off = (size_t)row * LDB + col0 + cn * 8;
        b_srch = Bh + off; b_srcl = Bl + off;
    } else {
        b_val = tid < (BN * 2);
        int nr = tid >> 1, ch = tid & 1;
        b_dst = (unsigned)((nr * 24 + ch * 8) * 2);
        size_t off = (size_t)(col0 + nr) * LDB + ch * 8;
        b_srch = Bh + off; b_srcl = Bl + off;
    }

    unsigned as_base = (unsigned)__cvta_generic_to_shared(&As[0][0][0]);
    unsigned bs_base = (unsigned)__cvta_generic_to_shared(&Bs[0][0][0]);

    auto issue = [&](int kt, int buf) {
        unsigned abh = as_base + (buf * 2 + 0) * AST * 2;
        unsigned abl = as_base + (buf * 2 + 1) * AST * 2;
        cpa16(abh + a_dst, a_srch + (size_t)kt * 16, true);
        cpa16(abl + a_dst, a_srcl + (size_t)kt * 16, true);
        if (b_val) {
            unsigned bbh = bs_base + (buf * 2 + 0) * BST * 2;
            unsigned bbl = bs_base + (buf * 2 + 1) * BST * 2;
            size_t off = NT ? (size_t)kt * 16 : (size_t)kt * 16 * LDB;
            cpa16(bbh + b_dst, b_srch + off, true);
            cpa16(bbl + b_dst, b_srcl + off, true);
        }
        asm volatile("cp.async.commit_group;\n");
    };

    int lane = tid & 31;
    int warp = tid >> 5;
    int wm = warp >> 2, wn = warp & 3;

    float acc[4][NF][4];
#pragma unroll
    for (int i = 0; i < 4; i++)
#pragma unroll
        for (int j = 0; j < NF; j++)
#pragma unroll
            for (int t = 0; t < 4; t++) acc[i][j][t] = 0.f;

    issue(0, 0);
#pragma unroll 1
    for (int kt = 0; kt < KT; kt++) {
        int buf = kt & 1;
        if (kt + 1 < KT) {
            issue(kt + 1, buf ^ 1);
            asm volatile("cp.async.wait_group 1;\n");
        } else {
            asm volatile("cp.async.wait_group 0;\n");
        }
        __syncthreads();
        unsigned abh = as_base + (buf * 2 + 0) * AST * 2;
        unsigned abl = as_base + (buf * 2 + 1) * AST * 2;
        unsigned bbh = bs_base + (buf * 2 + 0) * BST * 2;
        unsigned bbl = bs_base + (buf * 2 + 1) * BST * 2;

        unsigned ah[4][4], al[4][4];
#pragma unroll
        for (int i = 0; i < 4; i++) {
            int m = wm * 64 + i * 16 + (lane & 15);
            int ch = lane >> 4;
            unsigned ad = (unsigned)((m * 24 + ch * 8) * 2);
            ldsm4(ah[i], abh + ad);
            ldsm4(al[i], abl + ad);
        }
        unsigned brh[2 * NF], brl[2 * NF];
#pragma unroll
        for (int jj = 0; jj < NF / 2; jj++) {
            int n0 = wn * WN + jj * 16;
            if (!NT) {
                int k = lane & 15;
                int cn = (n0 >> 3) + (lane >> 4);
                int sw = cn ^ (k & 7);
                unsigned bd = (unsigned)((k * BN + sw * 8) * 2);
                ldsm4t(&brh[jj * 4], bbh + bd);
                ldsm4t(&brl[jj * 4], bbl + bd);
            } else {
                int n = n0 + ((lane >> 4) << 3) + (lane & 7);
                int ch = (lane >> 3) & 1;
                unsigned bd = (unsigned)((n * 24 + ch * 8) * 2);
                ldsm4(&brh[jj * 4], bbh + bd);
                ldsm4(&brl[jj * 4], bbl + bd);
            }
        }
#pragma unroll
        for (int i = 0; i < 4; i++)
#pragma unroll
            for (int j = 0; j < NF; j++) {
                mma16816(acc[i][j], ah[i], &brh[j * 2]);
                mma16816(acc[i][j], al[i], &brh[j * 2]);
                mma16816(acc[i][j], ah[i], &brl[j * 2]);
            }
        __syncthreads();
    }

    int rl = lane >> 2, cp2 = (lane & 3) * 2;
#pragma unroll
    for (int i = 0; i < 4; i++) {
#pragma unroll
        for (int hh = 0; hh < 2; hh++) {
            int rr = wm * 64 + i * 16 + rl + hh * 8;
            int r = row0 + rr;
#pragma unroll
            for (int j = 0; j < NF; j++) {
                int c = col0 + wn * WN + j * 8 + cp2;
                float v0 = acc[i][j][hh * 2 + 0];
                float v1 = acc[i][j][hh * 2 + 1];
                if (MODE == M_PE) {
                    float* O = (float*)Og;
                    v0 += bias[c]     + extra[(size_t)(r & 255) * 512 + c];
                    v1 += bias[c + 1] + extra[(size_t)(r & 255) * 512 + c + 1];
                    O[(size_t)r * 512 + c] = v0;
                    O[(size_t)r * 512 + c + 1] = v1;
                } else if (MODE == M_QKV) {
                    __half* O = (__half*)Og + (size_t)bz * 2 * SZ_LN;
                    const float* bi = bias + bz * 512;
                    v0 += bi[c]; v1 += bi[c + 1];
                    int b = r >> 8, s = r & 255, hd = c >> 6, ii = c & 63;
                    size_t o = (size_t)(((b << 3) + hd) * 256 + s) * 64 + ii;
                    split2(v0, v1, O + o, O + OLO + o);
                } else if (MODE == M_PROJ) {
                    float* O = (float*)Og;
                    v0 += bias[c]     + extra[(size_t)r * 512 + c];
                    v1 += bias[c + 1] + extra[(size_t)r * 512 + c + 1];
                    O[(size_t)r * 512 + c] = v0;
                    O[(size_t)r * 512 + c + 1] = v1;
                } else if (MODE == M_SC) {
                    float* O = (float*)Og + (size_t)bz * 65536;
                    O[(size_t)r * 256 + c] = v0 * 0.125f;
                    O[(size_t)r * 256 + c + 1] = v1 * 0.125f;
                } else { // M_AV
                    __half* O = (__half*)Og;
                    int b = bz >> 3, hd = bz & 7;
                    size_t o = (size_t)((b << 8) + r) * 512 + (hd << 6) + c;
                    split2(v0, v1, O + o, O + OLO + o);
                }
            }
        }
    }
}

// ---------------- conversions ---------------------------------------------------
struct __align__(8) h2x2 { __half2 a, b; };

__device__ __forceinline__ void conv_elem4(const float* in, __half* outh, size_t n,
                                           size_t i) {
    float4 f = *(const float4*)(in + i);
    h2x2 H, L;
    H.a = __floats2half2_rn(f.x, f.y);
    H.b = __floats2half2_rn(f.z, f.w);
    float2 f0 = __half22float2(H.a), f1 = __half22float2(H.b);
    L.a = __floats2half2_rn(f.x - f0.x, f.y - f0.y);
    L.b = __floats2half2_rn(f.z - f1.x, f.w - f1.y);
    *(h2x2*)(outh + i) = H;
    *(h2x2*)(outh + n + i) = L;
}

__global__ __launch_bounds__(256) void conv4_k(
    const float* __restrict__ s0, const float* __restrict__ s1,
    const float* __restrict__ s2, const float* __restrict__ s3,
    __half* __restrict__ d0, __half* __restrict__ d1,
    __half* __restrict__ d2, __half* __restrict__ d3, size_t n)
{
    const float* src = (blockIdx.z == 0) ? s0 : (blockIdx.z == 1) ? s1 :
                       (blockIdx.z == 2) ? s2 : s3;
    __half* dst = (blockIdx.z == 0) ? d0 : (blockIdx.z == 1) ? d1 :
                  (blockIdx.z == 2) ? d2 : d3;
    size_t i = ((size_t)blockIdx.x * 256 + threadIdx.x) * 4;
    if (i < n) conv_elem4(src, dst, n, i);
}

__global__ __launch_bounds__(256) void convpe_k(const float* __restrict__ w) {
    int i = (blockIdx.x * 256 + threadIdx.x) * 4;
    if (i >= NPDP * ND) return;
    int j = i >> 9;
    float4 f = make_float4(0.f, 0.f, 0.f, 0.f);
    if (j < NPD) f = *(const float4*)(w + i);
    h2x2 H, L;
    H.a = __floats2half2_rn(f.x, f.y);
    H.b = __floats2half2_rn(f.z, f.w);
    float2 f0 = __half22float2(H.a), f1 = __half22float2(H.b);
    L.a = __floats2half2_rn(f.x - f0.x, f.y - f0.y);
    L.b = __floats2half2_rn(f.z - f1.x, f.w - f1.y);
    *(h2x2*)(g_pew16 + i) = H;
    *(h2x2*)(g_pew16 + NPDP * ND + i) = L;
}

__global__ void bqkv_k(const float* __restrict__ bq, const float* __restrict__ bk,
                       const float* __restrict__ bv) {
    int i = blockIdx.x * 256 + threadIdx.x;
    if (i >= 1536) return;
    g_bqkv[i] = (i < 512) ? bq[i] : (i < 1024) ? bk[i - 512] : bv[i - 1024];
}

// ---------------- patch gather --------------------------------------------------
__global__ void patch_k(const float* __restrict__ x) {
    size_t idx = (size_t)blockIdx.x * 256 + threadIdx.x;
    if (idx >= SZ_P) return;
    int j = (int)(idx % NPDP);
    int rs = (int)(idx / NPDP);
    float f = 0.f;
    if (j < NPD) {
        int b = rs >> 8, s = rs & 255;
        int hi = s >> 4, wi = s & 15;
        int c = j % 3;
        int pp = j / 3;
        int p1 = pp / 14, p2 = pp % 14;
        f = x[(((size_t)(b * 3 + c)) * 224 + hi * 14 + p1) * 224 + wi * 14 + p2];
    }
    __half h = __float2half_rn(f);
    g_p16[idx] = h;
    g_p16[SZ_P + idx] = __float2half_rn(f - __half2float(h));
}

// ---------------- LayerNorm -----------------------------------------------------
__global__ __launch_bounds__(128) void ln_k(
    const float* __restrict__ in, const float* __restrict__ gw,
    const float* __restrict__ bw, float* __restrict__ out,
    __half* __restrict__ out16)
{
    int row = blockIdx.x, tid = threadIdx.x;
    const float4* ir = (const float4*)(in + (size_t)row * 512);
    float4 v = ir[tid];
    float s = v.x + v.y + v.z + v.w;
    float q = v.x * v.x + v.y * v.y + v.z * v.z + v.w * v.w;
    __shared__ float ss[4], sq[4];
    for (int o = 16; o > 0; o >>= 1) {
        s += __shfl_xor_sync(0xffffffffu, s, o);
        q += __shfl_xor_sync(0xffffffffu, q, o);
    }
    if ((tid & 31) == 0) { ss[tid >> 5] = s; sq[tid >> 5] = q; }
    __syncthreads();
    s = ss[0] + ss[1] + ss[2] + ss[3];
    q = sq[0] + sq[1] + sq[2] + sq[3];
    float mean = s * (1.f / 512.f);
    float var  = q * (1.f / 512.f) - mean * mean;
    float inv  = rsqrtf(var + 1e-5f);
    float4 g4 = ((const float4*)gw)[tid];
    float4 b4 = ((const float4*)bw)[tid];
    float4 o;
    o.x = (v.x - mean) * inv * g4.x + b4.x;
    o.y = (v.y - mean) * inv * g4.y + b4.y;
    o.z = (v.z - mean) * inv * g4.z + b4.z;
    o.w = (v.w - mean) * inv * g4.w + b4.w;
    if (out) ((float4*)(out + (size_t)row * 512))[tid] = o;
    size_t base = (size_t)row * 512 + tid * 4;
    split2(o.x, o.y, out16 + base,     out16 + SZ_LN + base);
    split2(o.z, o.w, out16 + base + 2, out16 + SZ_LN + base + 2);
}

// ---------------- softmax over attn rows ----------------------------------------
__global__ __launch_bounds__(256) void softmax_attn_k() {
    int row  = (blockIdx.x << 3) + (threadIdx.x >> 5);
    int lane = threadIdx.x & 31;
    const float4* p = (const float4*)(g_attn + (size_t)row * 256);
    float4 a = p[lane], b = p[lane + 32];
    float m = fmaxf(fmaxf(fmaxf(a.x, a.y), fmaxf(a.z, a.w)),
                    fmaxf(fmaxf(b.x, b.y), fmaxf(b.z, b.w)));
    for (int o = 16; o > 0; o >>= 1) m = fmaxf(m, __shfl_xor_sync(0xffffffffu, m, o));
    a.x = __expf(a.x - m); a.y = __expf(a.y - m);
    a.z = __expf(a.z - m); a.w = __expf(a.w - m);
    b.x = __expf(b.x - m); b.y = __expf(b.y - m);
    b.z = __expf(b.z - m); b.w = __expf(b.w - m);
    float s = a.x + a.y + a.z + a.w + b.x + b.y + b.z + b.w;
    for (int o = 16; o > 0; o >>= 1) s += __shfl_xor_sync(0xffffffffu, s, o);
    float inv = 1.f / s;
    a.x *= inv; a.y *= inv; a.z *= inv; a.w *= inv;
    b.x *= inv; b.y *= inv; b.z *= inv; b.w *= inv;
    size_t base = (size_t)row * 256;
    split2(a.x, a.y, g_attn16 + base + lane * 4,     g_attn16 + SZ_ATTN + base + lane * 4);
    split2(a.z, a.w, g_attn16 + base + lane * 4 + 2, g_attn16 + SZ_ATTN + base + lane * 4 + 2);
    split2(b.x, b.y, g_attn16 + base + 128 + lane * 4,     g_attn16 + SZ_ATTN + base + 128 + lane * 4);
    split2(b.z, b.w, g_attn16 + base + 128 + lane * 4 + 2, g_attn16 + SZ_ATTN + base + 128 + lane * 4 + 2);
}

// ---------------- attn_w --------------------------------------------------------
__global__ __launch_bounds__(256) void attnw_k(float* __restrict__ out) {
    int bq = blockIdx.x, tid = threadIdx.x;
    int b = bq >> 8, qr = bq & 255;
    float s = 0.f;
#pragma unroll
    for (int h = 0; h < 8; h++) {
        size_t off = ((size_t)((b << 3) + h)) * 65536 + (qr << 8) + tid;
        s += __half2float(g_attn16[off]) + __half2float(g_attn16[SZ_ATTN + off]);
    }
    s *= 0.125f;
    __shared__ float red[8];
    float m = s;
    for (int o = 16; o > 0; o >>= 1) m = fmaxf(m, __shfl_xor_sync(0xffffffffu, m, o));
    if ((tid & 31) == 0) red[tid >> 5] = m;
    __syncthreads();
    m = red[0];
#pragma unroll
    for (int w = 1; w < 8; w++) m = fmaxf(m, red[w]);
    float ex = __expf(s - m);
    float sum = ex;
    __syncthreads();
    for (int o = 16; o > 0; o >>= 1) sum += __shfl_xor_sync(0xffffffffu, sum, o);
    if ((tid & 31) == 0) red[tid >> 5] = sum;
    __syncthreads();
    sum = red[0] + red[1] + red[2] + red[3] + red[4] + red[5] + red[6] + red[7];
    out[(size_t)bq * 256 + tid] = ex / sum;
}

// ---------------- router / dispatch / combine / loss ----------------------------
__global__ __launch_bounds__(256) void router_k(const float* __restrict__ rw,
                                                const float* __restrict__ rb) {
    __shared__ float s_rw[8][512];
    __shared__ float s_rb[8];
    int tid = threadIdx.x;
    for (int i = tid; i < 4096; i += 256) s_rw[i >> 9][i & 511] = rw[(i & 511) * 8 + (i >> 9)];
    if (tid < 8) s_rb[tid] = rb[tid];
    __syncthreads();
    int t = (blockIdx.x << 3) + (tid >> 5);
    int lane = tid & 31;
    const float* x = g_ln + (size_t)t * 512;
    float acc[8] = {};
    for (int k = lane; k < 512; k += 32) {
        float xv = x[k];
#pragma unroll
        for (int e = 0; e < 8; e++) acc[e] += xv * s_rw[e][k];
    }
#pragma unroll
    for (int e = 0; e < 8; e++)
        for (int o = 16; o > 0; o >>= 1) acc[e] += __shfl_xor_sync(0xffffffffu, acc[e], o);
    if (lane == 0) {
        float mx = -1e30f;
#pragma unroll
        for (int e = 0; e < 8; e++) { acc[e] += s_rb[e]; mx = fmaxf(mx, acc[e]); }
        float sum = 0.f;
#pragma unroll
        for (int e = 0; e < 8; e++) { acc[e] = __expf(acc[e] - mx); sum += acc[e]; }
        float inv = 1.f / sum;
#pragma unroll
        for (int e = 0; e < 8; e++) g_probs[t * 8 + e] = acc[e] * inv;
    }
}

__global__ __launch_bounds__(256) void dispatch_k() {
    __shared__ int   s_cnt[8];
    __shared__ float s_imp[8];
    __shared__ int   s_base[8];
    int tid = threadIdx.x;
    if (tid < 8) { s_cnt[tid] = 0; s_imp[tid] = 0.f; }
    __syncthreads();
    int t = blockIdx.x * 256 + tid;
    float p[8];
#pragma unroll
    for (int e = 0; e < 8; e++) { p[e] = g_probs[t * 8 + e]; atomicAdd(&s_imp[e], p[e]); }
    int e1 = 0; float v1 = p[0];
#pragma unroll
    for (int e = 1; e < 8; e++) if (p[e] > v1) { v1 = p[e]; e1 = e; }
    int e2 = -1; float v2 = -1e30f;
#pragma unroll
    for (int e = 0; e < 8; e++) if (e != e1 && p[e] > v2) { v2 = p[e]; e2 = e; }
    int lp1 = atomicAdd(&s_cnt[e1], 1);
    int lp2 = atomicAdd(&s_cnt[e2], 1);
    __syncthreads();
    if (tid < 8) {
        s_base[tid] = atomicAdd(&g_cnt[tid], s_cnt[tid]);
        atomicAdd(&g_imp[tid], s_imp[tid]);
    }
    __syncthreads();
    g_perm[e1 * NA + s_base[e1] + lp1] = t * 2;
    g_perm[e2 * NA + s_base[e2] + lp2] = t * 2 + 1;
    g_gate[t * 2]     = v1;
    g_gate[t * 2 + 1] = v2;
}

__global__ __launch_bounds__(128) void combine_k(float* __restrict__ OUT) {
    int t = blockIdx.x, tid = threadIdx.x;
    float gg1 = g_gate[2 * t], gg2 = g_gate[2 * t + 1];
    const float4* c1 = (const float4*)(g_contrib + (size_t)(2 * t) * 512);
    const float4* c2 = (const float4*)(g_contrib + (size_t)(2 * t + 1) * 512);
    float4 a = c1[tid], b = c2[tid];
    float4 o;
    o.x = gg1 * a.x + gg2 * b.x; o.y = gg1 * a.y + gg2 * b.y;
    o.z = gg1 * a.z + gg2 * b.z; o.w = gg1 * a.w + gg2 * b.w;
    ((float4*)(OUT + (size_t)t * 512))[tid] = o;
}

__global__ void init_k(float* out_loss) {
    int tid = threadIdx.x;
    if (tid < 8) { g_cnt[tid] = 0; g_imp[tid] = 0.f; }
    if (tid == 0) out_loss[0] = 0.f;
}
__global__ void loss_k(float* out_loss) {
    int tid = threadIdx.x;
    float v = 0.f;
    if (tid < 8)
        v = 8.f * ((float)g_cnt[tid] * (1.f / 8192.f)) * (g_imp[tid] * (1.f / 8192.f));
    for (int o = 16; o > 0; o >>= 1) v += __shfl_xor_sync(0xffffffffu, v, o);
    if (tid == 0) out_loss[0] += v;
    if (tid < 8) { g_cnt[tid] = 0; g_imp[tid] = 0.f; }
}

// ---------------- fv + logits ---------------------------------------------------
__global__ __launch_bounds__(512) void fv1_k(float* __restrict__ part) {
    int b = blockIdx.x, seg = blockIdx.y, d = threadIdx.x;
    float s = 0.f;
    int s0 = seg * 32;
    for (int ss = 0; ss < 32; ss++)
        s += g_o2[(size_t)(b * 256 + s0 + ss) * 512 + d];
    part[(size_t)(b * 8 + seg) * 512 + d] = s;
}
__global__ __launch_bounds__(512) void fv2_k(const float* __restrict__ part,
                                             float* __restrict__ out_fv) {
    int b = blockIdx.x, d = threadIdx.x;
    float s = 0.f;
#pragma unroll
    for (int seg = 0; seg < 8; seg++)
        s += part[(size_t)(b * 8 + seg) * 512 + d];
    s *= (1.f / 256.f);
    g_fv[b * 512 + d] = s;
    out_fv[b * 512 + d] = s;
}
__global__ __launch_bounds__(512) void logits_k(const float* __restrict__ W,
                                                const float* __restrict__ bias,
                                                float* __restrict__ out) {
    __shared__ float sf[512];
    int b = blockIdx.x, n = threadIdx.x;
    sf[n] = g_fv[b * 512 + n];
    __syncthreads();
    float acc = 0.f;
    for (int k = 0; k < 512; k++) acc += sf[k] * W[k * 512 + n];
    out[b * 512 + n] = acc + bias[n];
}

// ---------------- host launch ---------------------------------------------------
extern "C" void kernel_launch(void* const* d_in, const int* in_sizes, int n_in,
                              void* d_out, int out_size) {
    const float* x     = (const float*)d_in[0];
    const float* pe_w  = (const float*)d_in[1];
    const float* pe_b  = (const float*)d_in[2];
    const float* pos   = (const float*)d_in[3];
    const float* ln1_g = (const float*)d_in[4];
    const float* ln1_b = (const float*)d_in[5];
    const float* ln2_g = (const float*)d_in[6];
    const float* ln2_b = (const float*)d_in[7];
    const float* ln3_g = (const float*)d_in[8];
    const float* ln3_b = (const float*)d_in[9];
    const float* wq = (const float*)d_in[10];
    const float* bq = (const float*)d_in[11];
    const float* wk = (const float*)d_in[12];
    const float* bk = (const float*)d_in[13];
    const float* wv = (const float*)d_in[14];
    const float* bv = (const float*)d_in[15];
    const float* wo = (const float*)d_in[16];
    const float* bo = (const float*)d_in[17];
    const float* m1_rw = (const float*)d_in[18];
    const float* m1_rb = (const float*)d_in[19];
    const float* m1_w1 = (const float*)d_in[20];
    const float* m1_b1 = (const float*)d_in[21];
    const float* m1_w2 = (const float*)d_in[22];
    const float* m1_b2 = (const float*)d_in[23];
    const float* m2_rw = (const float*)d_in[24];
    const float* m2_rb = (const float*)d_in[25];
    const float* m2_w1 = (const float*)d_in[26];
    const float* m2_b1 = (const float*)d_in[27];
    const float* m2_w2 = (const float*)d_in[28];
    const float* m2_b2 = (const float*)d_in[29];
    const float* cls_w = (const float*)d_in[30];
    const float* cls_b = (const float*)d_in[31];

    float* out = (float*)d_out;
    float* out_logits = out;
    float* out_fv     = out + 16384;
    float* out_loss   = out + 32768;
    float* out_attnw  = out + 32769;

    float *p_e, *p_ln, *p_attn, *p_contrib, *p_o1, *p_o2;
    __half *p_p16, *p_ln16, *p_qkv16, *p_attn16, *p_ctx16, *p_h16;
    __half *p_pew16, *p_wqkv16, *p_wo16;
    __half *p_w1a, *p_w2a, *p_w1b, *p_w2b;
    cudaGetSymbolAddress((void**)&p_e,       g_e);
    cudaGetSymbolAddress((void**)&p_ln,      g_ln);
    cudaGetSymbolAddress((void**)&p_attn,    g_attn);
    cudaGetSymbolAddress((void**)&p_contrib, g_contrib);
    cudaGetSymbolAddress((void**)&p_o1,      g_o1);
    cudaGetSymbolAddress((void**)&p_o2,      g_o2);
    cudaGetSymbolAddress((void**)&p_p16,     g_p16);
    cudaGetSymbolAddress((void**)&p_ln16,    g_ln16);
    cudaGetSymbolAddress((void**)&p_qkv16,   g_qkv16);
    cudaGetSymbolAddress((void**)&p_attn16,  g_attn16);
    cudaGetSymbolAddress((void**)&p_ctx16,   g_ctx16);
    cudaGetSymbolAddress((void**)&p_h16,     g_h16);
    cudaGetSymbolAddress((void**)&p_pew16,   g_pew16);
    cudaGetSymbolAddress((void**)&p_wqkv16,  g_wqkv16);
    cudaGetSymbolAddress((void**)&p_wo16,    g_wo16);
    cudaGetSymbolAddress((void**)&p_w1a,     g_w1a16);
    cudaGetSymbolAddress((void**)&p_w2a,     g_w2a16);
    cudaGetSymbolAddress((void**)&p_w1b,     g_w1b16);
    cudaGetSymbolAddress((void**)&p_w2b,     g_w2b16);
    float* p_bqkv; cudaGetSymbolAddress((void**)&p_bqkv, g_bqkv);

    cudaFuncSetAttribute(ff16_k<512, 2048, 1, true>,
                         cudaFuncAttributeMaxDynamicSharedMemorySize, 65536);
    cudaFuncSetAttribute(ff16_k<2048, 512, 0, false>,
                         cudaFuncAttributeMaxDynamicSharedMemorySize, 65536);

    init_k<<<1, 32>>>(out_loss);

    // fork: big MoE weight conversions on side stream (overlaps with attention)
    cudaEventRecord(g_ss.fork, 0);
    cudaStreamWaitEvent(g_ss.s, g_ss.fork, 0);
    conv4_k<<<dim3(8192, 1, 4), 256, 0, g_ss.s>>>(
        m1_w1, m1_w2, m2_w1, m2_w2, p_w1a, p_w2a, p_w1b, p_w2b, SZ_W);
    cudaEventRecord(g_ss.join, g_ss.s);

    convpe_k<<<(NPDP * ND / 4 + 255) / 256, 256>>>(pe_w);
    conv4_k<<<dim3(256, 1, 4), 256>>>(
        wq, wk, wv, wo,
        p_wqkv16, p_wqkv16 + 2 * SZ_DD, p_wqkv16 + 4 * SZ_DD, p_wo16, SZ_DD);

    patch_k<<<(int)((SZ_P + 255) / 256), 256>>>(x);
    mm_k<M_PE><<<dim3(4, 64), 256>>>(p_p16, p_pew16, pe_b, pos, p_e);

    bqkv_k<<<6, 256>>>(bq, bk, bv);
    ln_k<<<NTOK, 128>>>(p_e, ln1_g, ln1_b, nullptr, p_ln16);
    mm_k<M_QKV><<<dim3(4, 64, 3), 256>>>(p_ln16, p_wqkv16, p_bqkv, nullptr, p_qkv16);
    mm_k<M_SC><<<dim3(4, 2, 256), 256>>>(p_qkv16, p_qkv16 + 2 * SZ_LN,
                                         nullptr, nullptr, p_attn);
    softmax_attn_k<<<8192, 256>>>();
    mm_k<M_AV><<<dim3(1, 2, 256), 256>>>(p_attn16, p_qkv16 + 4 * SZ_LN,
                                         nullptr, nullptr, p_ctx16);
    mm_k<M_PROJ><<<dim3(4, 64), 256>>>(p_ctx16, p_wo16, bo, p_e, p_e);
    attnw_k<<<NTOK, 256>>>(out_attnw);

    // MoE layer 1
    ln_k<<<NTOK, 128>>>(p_e, ln2_g, ln2_b, p_ln, p_ln16);
    router_k<<<1024, 256>>>(m1_rw, m1_rb);
    dispatch_k<<<32, 256>>>();
    cudaStreamWaitEvent(0, g_ss.join, 0);
    ff16_k<512, 2048, 1, true><<<dim3(16, 64, 8), 256, 65536>>>(
        p_ln16, SZ_LN, p_w1a, SZ_W, m1_b1, p_h16);
    ff16_k<2048, 512, 0, false><<<dim3(4, 64, 8), 256, 65536>>>(
        p_h16, SZ_H, p_w2a, SZ_W, m1_b2, p_contrib);
    combine_k<<<NTOK, 128>>>(p_o1);
    loss_k<<<1, 32>>>(out_loss);

    // MoE layer 2
    ln_k<<<NTOK, 128>>>(p_o1, ln3_g, ln3_b, p_ln, p_ln16);
    router_k<<<1024, 256>>>(m2_rw, m2_rb);
    dispatch_k<<<32, 256>>>();
    ff16_k<512, 2048, 1, true><<<dim3(16, 64, 8), 256, 65536>>>(
        p_ln16, SZ_LN, p_w1b, SZ_W, m2_b1, p_h16);
    ff16_k<2048, 512, 0, false><<<dim3(4, 64, 8), 256, 65536>>>(
        p_h16, SZ_H, p_w2b, SZ_W, m2_b2, p_contrib);
    combine_k<<<NTOK, 128>>>(p_o2);
    loss_k<<<1, 32>>>(out_loss);

    fv1_k<<<dim3(NB, 8), 512>>>(p_contrib);
    fv2_k<<<NB, 512>>>(p_contrib, out_fv);
    logits_k<<<NB, 512>>>(cls_w, cls_b, out_logits);
}

// round 8
// speedup vs baseline: 1.0563x; 1.0563x over previous
#include <cuda_runtime.h>
#include <cuda_fp16.h>
#include <math.h>
#include <stdint.h>

#define NB   32
#define NS   256
#define ND   512
#define NH   8
#define NE   8
#define NHID 2048
#define NPD  588
#define NPDP 608
#define NTOK 8192
#define NA   16384

#define SZ_LN   ((size_t)NTOK * ND)
#define SZ_P    ((size_t)NTOK * NPDP)
#define SZ_ATTN ((size_t)NB * NH * NS * NS)
#define SZ_H    ((size_t)NA * NHID)
#define SZ_W    ((size_t)NE * ND * NHID)
#define SZ_DD   ((size_t)ND * ND)

// ---------------- fp32 scratch -------------------------------------------------
__device__ float g_e[NTOK * ND];
__device__ float g_ln[NTOK * ND];
__device__ float g_attn[NB * NH * NS * NS];
__device__ float g_probs[NTOK * NE];
__device__ float g_gate[NA];
__device__ int   g_perm[NE * NA];
__device__ int   g_cnt[NE];
__device__ float g_imp[NE];
__device__ float g_contrib[NA * ND];
__device__ float g_o1[NTOK * ND];
__device__ float g_o2[NTOK * ND];
__device__ float g_fv[NB * ND];
__device__ float g_bqkv[3 * ND];

// ---------------- split fp16 buffers (hi at [0], lo at [SIZE] per segment) -----
__device__ __half g_p16[2 * SZ_P];
__device__ __half g_ln16[2 * SZ_LN];
__device__ __half g_qkv16[6 * SZ_LN];
__device__ __half g_attn16[2 * SZ_ATTN];
__device__ __half g_ctx16[2 * SZ_LN];
__device__ __half g_h16[2 * SZ_H];
__device__ __half g_pew16[2 * NPDP * ND];
__device__ __half g_wqkv16[6 * SZ_DD];
__device__ __half g_wo16[2 * SZ_DD];
__device__ __half g_w1a16[2 * SZ_W];
__device__ __half g_w2a16[2 * SZ_W];
__device__ __half g_w1b16[2 * SZ_W];
__device__ __half g_w2b16[2 * SZ_W];

// ---------------- persistent side stream ---------------------------------------
struct SideStream {
    cudaStream_t s;
    cudaEvent_t fork, join, attnev;
    SideStream() {
        cudaStreamCreateWithFlags(&s, cudaStreamNonBlocking);
        cudaEventCreateWithFlags(&fork, cudaEventDisableTiming);
        cudaEventCreateWithFlags(&join, cudaEventDisableTiming);
        cudaEventCreateWithFlags(&attnev, cudaEventDisableTiming);
    }
};
static SideStream g_ss;

__device__ __forceinline__ float gelu_exact(float v) {
    return 0.5f * v * (1.0f + erff(v * 0.70710678118654752440f));
}
__device__ __forceinline__ void split2(float v0, float v1, __half* oh, __half* ol) {
    __half h0 = __float2half_rn(v0), h1 = __float2half_rn(v1);
    *(__half2*)oh = __halves2half2(h0, h1);
    *(__half2*)ol = __halves2half2(__float2half_rn(v0 - __half2float(h0)),
                                   __float2half_rn(v1 - __half2float(h1)));
}

// ---------------- mma.sync helpers ----------------------------------------------
__device__ __forceinline__ void ldsm4(unsigned* r, unsigned addr) {
    asm volatile("ldmatrix.sync.aligned.m8n8.x4.shared.b16 {%0,%1,%2,%3}, [%4];\n"
        : "=r"(r[0]), "=r"(r[1]), "=r"(r[2]), "=r"(r[3]) : "r"(addr));
}
__device__ __forceinline__ void ldsm4t(unsigned* r, unsigned addr) {
    asm volatile("ldmatrix.sync.aligned.m8n8.x4.trans.shared.b16 {%0,%1,%2,%3}, [%4];\n"
        : "=r"(r[0]), "=r"(r[1]), "=r"(r[2]), "=r"(r[3]) : "r"(addr));
}
__device__ __forceinline__ void mma16816(float* c, const unsigned* a, const unsigned* b) {
    asm volatile("mma.sync.aligned.m16n8k16.row.col.f32.f16.f16.f32 "
        "{%0,%1,%2,%3}, {%4,%5,%6,%7}, {%8,%9}, {%0,%1,%2,%3};\n"
        : "+f"(c[0]), "+f"(c[1]), "+f"(c[2]), "+f"(c[3])
        : "r"(a[0]), "r"(a[1]), "r"(a[2]), "r"(a[3]), "r"(b[0]), "r"(b[1]));
}
__device__ __forceinline__ void cpa16(unsigned dst, const void* src, bool p) {
    int sz = p ? 16 : 0;
    asm volatile("cp.async.cg.shared.global [%0], [%1], 16, %2;\n"
        :: "r"(dst), "l"(src), "r"(sz));
}

// ================= FF grouped GEMM (BM=128 x BN=128, BK=32) =====================
// 256 threads, 8 warps as 2(m) x 4(n); warp tile 64x32; acc 64 floats/thread.
// Dynamic smem 72KB:
//   A[buf][hl]: (buf*2+hl)*5120 halves (128 rows x 40-stride, 32 K + 8 pad)
//   B[buf][hl]: 20480 + (buf*2+hl)*4096 halves (32 x 128 swizzled)
template <int KTOT, int NTOT, int SHIFT, bool GELU>
__global__ __launch_bounds__(256) void ffb_k(
    const __half* __restrict__ Xh, size_t alo,
    const __half* __restrict__ Wh, size_t blo,
    const float* __restrict__ bias, void* __restrict__ Out)
{
    constexpr int KT = KTOT / 32;
    constexpr unsigned ABUF = 128 * 40;   // halves
    constexpr unsigned BBUF = 32 * 128;   // halves
    extern __shared__ __half sm[];
    __shared__ int s_idx[128];

    int e = blockIdx.z;
    int cnt = g_cnt[e];
    int row0 = blockIdx.y * 128;
    if (row0 >= cnt) return;
    int col0 = blockIdx.x * 128;

    int tid = threadIdx.x;
    if (tid < 128) {
        int r = row0 + tid;
        s_idx[tid] = (r < cnt) ? g_perm[e * NA + r] : -1;
    }
    __syncthreads();

    const __half* We = Wh + (size_t)e * KTOT * NTOT;

    // A: 2 items/thread: item = tid + it*256, arow=item>>2 (0..127), ch=item&3
    unsigned a_dst[2]; const __half *a_h[2], *a_l[2]; bool a_p[2];
#pragma unroll
    for (int it = 0; it < 2; it++) {
        int item = tid + it * 256;
        int arow = item >> 2, ch = item & 3;
        a_dst[it] = (unsigned)((arow * 40 + ch * 8) * 2);
        int a = s_idx[arow];
        a_p[it] = (a >= 0);
        size_t off = a_p[it] ? (size_t)(a >> SHIFT) * KTOT + ch * 8 : 0;
        a_h[it] = Xh + off;
        a_l[it] = Xh + alo + off;
    }
    // B: 2 items/thread: brow=item>>4 (0..31), cn=item&15
    unsigned b_dst[2]; const __half *b_h[2], *b_l[2];
#pragma unroll
    for (int it = 0; it < 2; it++) {
        int item = tid + it * 256;
        int brow = item >> 4, cn = item & 15;
        int sw = cn ^ (brow & 7);
        b_dst[it] = (unsigned)((brow * 128 + sw * 8) * 2);
        size_t off = (size_t)brow * NTOT + col0 + cn * 8;
        b_h[it] = We + off;
        b_l[it] = We + blo + off;
    }

    unsigned sbase = (unsigned)__cvta_generic_to_shared(sm);
    unsigned bbase = sbase + 4 * ABUF * 2;

    auto issue = [&](int kt, int buf) {
        unsigned abh = sbase + (unsigned)(buf * 2 + 0) * ABUF * 2;
        unsigned abl = sbase + (unsigned)(buf * 2 + 1) * ABUF * 2;
#pragma unroll
        for (int it = 0; it < 2; it++) {
            cpa16(abh + a_dst[it], a_h[it] + (size_t)kt * 32, a_p[it]);
            cpa16(abl + a_dst[it], a_l[it] + (size_t)kt * 32, a_p[it]);
        }
        unsigned bbh = bbase + (unsigned)(buf * 2 + 0) * BBUF * 2;
        unsigned bbl = bbase + (unsigned)(buf * 2 + 1) * BBUF * 2;
        size_t ko = (size_t)kt * 32 * NTOT;
#pragma unroll
        for (int it = 0; it < 2; it++) {
            cpa16(bbh + b_dst[it], b_h[it] + ko, true);
            cpa16(bbl + b_dst[it], b_l[it] + ko, true);
        }
        asm volatile("cp.async.commit_group;\n");
    };

    int lane = tid & 31;
    int warp = tid >> 5;
    int wm = warp >> 2, wn = warp & 3;   // 2 x 4

    float acc[4][4][4];
#pragma unroll
    for (int i = 0; i < 4; i++)
#pragma unroll
        for (int j = 0; j < 4; j++)
#pragma unroll
            for (int t = 0; t < 4; t++) acc[i][j][t] = 0.f;

    issue(0, 0);
#pragma unroll 1
    for (int kt = 0; kt < KT; kt++) {
        int buf = kt & 1;
        if (kt + 1 < KT) {
            issue(kt + 1, buf ^ 1);
            asm volatile("cp.async.wait_group 1;\n");
        } else {
            asm volatile("cp.async.wait_group 0;\n");
        }
        __syncthreads();
        unsigned abh = sbase + (unsigned)(buf * 2 + 0) * ABUF * 2;
        unsigned abl = sbase + (unsigned)(buf * 2 + 1) * ABUF * 2;
        unsigned bbh = bbase + (unsigned)(buf * 2 + 0) * BBUF * 2;
        unsigned bbl = bbase + (unsigned)(buf * 2 + 1) * BBUF * 2;

#pragma unroll
        for (int ks = 0; ks < 2; ks++) {
            unsigned ah[4][4], al[4][4];
#pragma unroll
            for (int i = 0; i < 4; i++) {
                int m = wm * 64 + i * 16 + (lane & 15);
                int ch = ks * 2 + (lane >> 4);
                unsigned ad = (unsigned)((m * 40 + ch * 8) * 2);
                ldsm4(ah[i], abh + ad);
                ldsm4(al[i], abl + ad);
            }
            {
                int n0 = wn * 32;
                int k = ks * 16 + (lane & 15);
                int cn = (n0 >> 3) + (lane >> 4);
                int sw = cn ^ (k & 7);
                unsigned bd = (unsigned)((k * 128 + sw * 8) * 2);
                unsigned brh[4], brl[4];
                ldsm4t(brh, bbh + bd);
                ldsm4t(brl, bbl + bd);
#pragma unroll
                for (int i = 0; i < 4; i++) {
                    mma16816(acc[i][0], ah[i], &brh[0]);
                    mma16816(acc[i][0], al[i], &brh[0]);
                    mma16816(acc[i][0], ah[i], &brl[0]);
                    mma16816(acc[i][1], ah[i], &brh[2]);
                    mma16816(acc[i][1], al[i], &brh[2]);
                    mma16816(acc[i][1], ah[i], &brl[2]);
                }
            }
            {
                int n0 = wn * 32 + 16;
                int k = ks * 16 + (lane & 15);
                int cn = (n0 >> 3) + (lane >> 4);
                int sw = cn ^ (k & 7);
                unsigned bd = (unsigned)((k * 128 + sw * 8) * 2);
                unsigned brh[4], brl[4];
                ldsm4t(brh, bbh + bd);
                ldsm4t(brl, bbl + bd);
#pragma unroll
                for (int i = 0; i < 4; i++) {
                    mma16816(acc[i][2], ah[i], &brh[0]);
                    mma16816(acc[i][2], al[i], &brh[0]);
                    mma16816(acc[i][2], ah[i], &brl[0]);
                    mma16816(acc[i][3], ah[i], &brh[2]);
                    mma16816(acc[i][3], al[i], &brh[2]);
                    mma16816(acc[i][3], ah[i], &brl[2]);
                }
            }
        }
        __syncthreads();
    }

    // epilogue
    int rl = lane >> 2, cp2 = (lane & 3) * 2;
    const float* bi = bias + (size_t)e * NTOT;
#pragma unroll
    for (int i = 0; i < 4; i++) {
#pragma unroll
        for (int hh = 0; hh < 2; hh++) {
            int rr = wm * 64 + i * 16 + rl + hh * 8;
            int aidx = s_idx[rr];
            if (aidx < 0) continue;
#pragma unroll
            for (int j = 0; j < 4; j++) {
                int c = col0 + wn * 32 + j * 8 + cp2;
                float v0 = acc[i][j][hh * 2 + 0] + bi[c];
                float v1 = acc[i][j][hh * 2 + 1] + bi[c + 1];
                size_t o = (size_t)aidx * NTOT + c;
                if (GELU) {
                    v0 = gelu_exact(v0); v1 = gelu_exact(v1);
                    __half* O = (__half*)Out;
                    split2(v0, v1, O + o, O + SZ_H + o);
                } else {
                    float* O = (float*)Out;
                    *(float2*)(O + o) = make_float2(v0, v1);
                }
            }
        }
    }
}

// ---------------- modes (mma.sync kernel, attention path) -----------------------
#define M_PE   0
#define M_QKV  1
#define M_PROJ 2
#define M_SC   3
#define M_AV   4

template <int MODE>
__global__ __launch_bounds__(256) void mm_k(
    const __half* __restrict__ Ag, const __half* __restrict__ Bg,
    const float* __restrict__ bias, const float* __restrict__ extra,
    void* __restrict__ Og)
{
    constexpr int K   = (MODE == M_PE) ? NPDP : (MODE == M_SC) ? 64 :
                        (MODE == M_AV) ? 256 : 512;
    constexpr int LDA = K;
    constexpr int LDB = (MODE == M_SC || MODE == M_AV) ? 64 : 512;
    constexpr bool NT = (MODE == M_SC);
    constexpr int BN = (MODE == M_AV || MODE == M_SC) ? 64 : 128;
    constexpr int WN = BN / 4;
    constexpr int NF = WN / 8;
    constexpr int KT = K / 16;
    constexpr size_t ALO =
        (MODE == M_PE)  ? SZ_P :
        (MODE == M_AV)  ? SZ_ATTN : SZ_LN;
    constexpr size_t BLO =
        (MODE == M_PE)  ? (size_t)NPDP * ND :
        (MODE == M_QKV || MODE == M_PROJ) ? SZ_DD : SZ_LN;
    constexpr size_t OLO = SZ_LN;
    constexpr int AST = 128 * 24;
    constexpr int BST = NT ? BN * 24 : 16 * BN;

    __shared__ __align__(16) __half As[2][2][AST];
    __shared__ __align__(16) __half Bs[2][2][BST];

    int tid = threadIdx.x;
    int bz = blockIdx.z;
    int row0 = blockIdx.y * 128, col0 = blockIdx.x * BN;

    const __half* Ah = Ag;
    const __half* Bh = Bg;
    if (MODE == M_SC)  { Ah += (size_t)bz * 256 * 64; Bh += (size_t)bz * 256 * 64; }
    if (MODE == M_AV)  { Ah += (size_t)bz * 65536;    Bh += (size_t)bz * 256 * 64; }
    if (MODE == M_QKV) { Bh += (size_t)bz * 2 * SZ_DD; }
    const __half* Al = Ah + ALO;
    const __half* Bl = Bh + BLO;

    int a_row = tid >> 1, a_ch = tid & 1;
    unsigned a_dst = (unsigned)((a_row * 24 + a_ch * 8) * 2);
    size_t aoff = (size_t)(row0 + a_row) * LDA + a_ch * 8;
    const __half* a_srch = Ah + aoff;
    const __half* a_srcl = Al + aoff;

    unsigned b_dst = 0; const __half* b_srch = Bh; const __half* b_srcl = Bh;
    bool b_val;
    if (!NT) {
        b_val = tid < (16 * BN / 8);
        int row = tid / (BN / 8), cn = tid % (BN / 8);
        int sw = cn ^ (row & 7);
        b_dst = (unsigned)((row * BN + sw * 8) * 2);
        size_t off = (size_t)row * LDB + col0 + cn * 8;
        b_srch = Bh + off; b_srcl = Bl + off;
    } else {
        b_val = tid < (BN * 2);
        int nr = tid >> 1, ch = tid & 1;
        b_dst = (unsigned)((nr * 24 + ch * 8) * 2);
        size_t off = (size_t)(col0 + nr) * LDB + ch * 8;
        b_srch = Bh + off; b_srcl = Bl + off;
    }

    unsigned as_base = (unsigned)__cvta_generic_to_shared(&As[0][0][0]);
    unsigned bs_base = (unsigned)__cvta_generic_to_shared(&Bs[0][0][0]);

    auto issue = [&](int kt, int buf) {
        unsigned abh = as_base + (buf * 2 + 0) * AST * 2;
        unsigned abl = as_base + (buf * 2 + 1) * AST * 2;
        cpa16(abh + a_dst, a_srch + (size_t)kt * 16, true);
        cpa16(abl + a_dst, a_srcl + (size_t)kt * 16, true);
        if (b_val) {
            unsigned bbh = bs_base + (buf * 2 + 0) * BST * 2;
            unsigned bbl = bs_base + (buf * 2 + 1) * BST * 2;
            size_t off = NT ? (size_t)kt * 16 : (size_t)kt * 16 * LDB;
            cpa16(bbh + b_dst, b_srch + off, true);
            cpa16(bbl + b_dst, b_srcl + off, true);
        }
        asm volatile("cp.async.commit_group;\n");
    };

    int lane = tid & 31;
    int warp = tid >> 5;
    int wm = warp >> 2, wn = warp & 3;

    float acc[4][NF][4];
#pragma unroll
    for (int i = 0; i < 4; i++)
#pragma unroll
        for (int j = 0; j < NF; j++)
#pragma unroll
            for (int t = 0; t < 4; t++) acc[i][j][t] = 0.f;

    issue(0, 0);
#pragma unroll 1
    for (int kt = 0; kt < KT; kt++) {
        int buf = kt & 1;
        if (kt + 1 < KT) {
            issue(kt + 1, buf ^ 1);
            asm volatile("cp.async.wait_group 1;\n");
        } else {
            asm volatile("cp.async.wait_group 0;\n");
        }
        __syncthreads();
        unsigned abh = as_base + (buf * 2 + 0) * AST * 2;
        unsigned abl = as_base + (buf * 2 + 1) * AST * 2;
        unsigned bbh = bs_base + (buf * 2 + 0) * BST * 2;
        unsigned bbl = bs_base + (buf * 2 + 1) * BST * 2;

        unsigned ah[4][4], al[4][4];
#pragma unroll
        for (int i = 0; i < 4; i++) {
            int m = wm * 64 + i * 16 + (lane & 15);
            int ch = lane >> 4;
            unsigned ad = (unsigned)((m * 24 + ch * 8) * 2);
            ldsm4(ah[i], abh + ad);
            ldsm4(al[i], abl + ad);
        }
        unsigned brh[2 * NF], brl[2 * NF];
#pragma unroll
        for (int jj = 0; jj < NF / 2; jj++) {
            int n0 = wn * WN + jj * 16;
            if (!NT) {
                int k = lane & 15;
                int cn = (n0 >> 3) + (lane >> 4);
                int sw = cn ^ (k & 7);
                unsigned bd = (unsigned)((k * BN + sw * 8) * 2);
                ldsm4t(&brh[jj * 4], bbh + bd);
                ldsm4t(&brl[jj * 4], bbl + bd);
            } else {
                int n = n0 + ((lane >> 4) << 3) + (lane & 7);
                int ch = (lane >> 3) & 1;
                unsigned bd = (unsigned)((n * 24 + ch * 8) * 2);
                ldsm4(&brh[jj * 4], bbh + bd);
                ldsm4(&brl[jj * 4], bbl + bd);
            }
        }
#pragma unroll
        for (int i = 0; i < 4; i++)
#pragma unroll
            for (int j = 0; j < NF; j++) {
                mma16816(acc[i][j], ah[i], &brh[j * 2]);
                mma16816(acc[i][j], al[i], &brh[j * 2]);
                mma16816(acc[i][j], ah[i], &brl[j * 2]);
            }
        __syncthreads();
    }

    int rl = lane >> 2, cp2 = (lane & 3) * 2;
#pragma unroll
    for (int i = 0; i < 4; i++) {
#pragma unroll
        for (int hh = 0; hh < 2; hh++) {
            int rr = wm * 64 + i * 16 + rl + hh * 8;
            int r = row0 + rr;
#pragma unroll
            for (int j = 0; j < NF; j++) {
                int c = col0 + wn * WN + j * 8 + cp2;
                float v0 = acc[i][j][hh * 2 + 0];
                float v1 = acc[i][j][hh * 2 + 1];
                if (MODE == M_PE) {
                    float* O = (float*)Og;
                    v0 += bias[c]     + extra[(size_t)(r & 255) * 512 + c];
                    v1 += bias[c + 1] + extra[(size_t)(r & 255) * 512 + c + 1];
                    O[(size_t)r * 512 + c] = v0;
                    O[(size_t)r * 512 + c + 1] = v1;
                } else if (MODE == M_QKV) {
                    __half* O = (__half*)Og + (size_t)bz * 2 * SZ_LN;
                    const float* bi = bias + bz * 512;
                    v0 += bi[c]; v1 += bi[c + 1];
                    int b = r >> 8, s = r & 255, hd = c >> 6, ii = c & 63;
                    size_t o = (size_t)(((b << 3) + hd) * 256 + s) * 64 + ii;
                    split2(v0, v1, O + o, O + OLO + o);
                } else if (MODE == M_PROJ) {
                    float* O = (float*)Og;
                    v0 += bias[c]     + extra[(size_t)r * 512 + c];
                    v1 += bias[c + 1] + extra[(size_t)r * 512 + c + 1];
                    O[(size_t)r * 512 + c] = v0;
                    O[(size_t)r * 512 + c + 1] = v1;
                } else if (MODE == M_SC) {
                    float* O = (float*)Og + (size_t)bz * 65536;
                    O[(size_t)r * 256 + c] = v0 * 0.125f;
                    O[(size_t)r * 256 + c + 1] = v1 * 0.125f;
                } else { // M_AV
                    __half* O = (__half*)Og;
                    int b = bz >> 3, hd = bz & 7;
                    size_t o = (size_t)((b << 8) + r) * 512 + (hd << 6) + c;
                    split2(v0, v1, O + o, O + OLO + o);
                }
            }
        }
    }
}

// ---------------- conversions ---------------------------------------------------
struct __align__(8) h2x2 { __half2 a, b; };

__device__ __forceinline__ void conv_elem4(const float* in, __half* outh, size_t n,
                                           size_t i) {
    float4 f = *(const float4*)(in + i);
    h2x2 H, L;
    H.a = __floats2half2_rn(f.x, f.y);
    H.b = __floats2half2_rn(f.z, f.w);
    float2 f0 = __half22float2(H.a), f1 = __half22float2(H.b);
    L.a = __floats2half2_rn(f.x - f0.x, f.y - f0.y);
    L.b = __floats2half2_rn(f.z - f1.x, f.w - f1.y);
    *(h2x2*)(outh + i) = H;
    *(h2x2*)(outh + n + i) = L;
}

__global__ __launch_bounds__(256) void conv4_k(
    const float* __restrict__ s0, const float* __restrict__ s1,
    const float* __restrict__ s2, const float* __restrict__ s3,
    __half* __restrict__ d0, __half* __restrict__ d1,
    __half* __restrict__ d2, __half* __restrict__ d3, size_t n)
{
    const float* src = (blockIdx.z == 0) ? s0 : (blockIdx.z == 1) ? s1 :
                       (blockIdx.z == 2) ? s2 : s3;
    __half* dst = (blockIdx.z == 0) ? d0 : (blockIdx.z == 1) ? d1 :
                  (blockIdx.z == 2) ? d2 : d3;
    size_t i = ((size_t)blockIdx.x * 256 + threadIdx.x) * 4;
    if (i < n) conv_elem4(src, dst, n, i);
}

__global__ __launch_bounds__(256) void convpe_k(const float* __restrict__ w) {
    int i = (blockIdx.x * 256 + threadIdx.x) * 4;
    if (i >= NPDP * ND) return;
    int j = i >> 9;
    float4 f = make_float4(0.f, 0.f, 0.f, 0.f);
    if (j < NPD) f = *(const float4*)(w + i);
    h2x2 H, L;
    H.a = __floats2half2_rn(f.x, f.y);
    H.b = __floats2half2_rn(f.z, f.w);
    float2 f0 = __half22float2(H.a), f1 = __half22float2(H.b);
    L.a = __floats2half2_rn(f.x - f0.x, f.y - f0.y);
    L.b = __floats2half2_rn(f.z - f1.x, f.w - f1.y);
    *(h2x2*)(g_pew16 + i) = H;
    *(h2x2*)(g_pew16 + NPDP * ND + i) = L;
}

__global__ void bqkv_k(const float* __restrict__ bq, const float* __restrict__ bk,
                       const float* __restrict__ bv) {
    int i = blockIdx.x * 256 + threadIdx.x;
    if (i >= 1536) return;
    g_bqkv[i] = (i < 512) ? bq[i] : (i < 1024) ? bk[i - 512] : bv[i - 1024];
}

// ---------------- patch gather --------------------------------------------------
__global__ void patch_k(const float* __restrict__ x) {
    size_t idx = (size_t)blockIdx.x * 256 + threadIdx.x;
    if (idx >= SZ_P) return;
    int j = (int)(idx % NPDP);
    int rs = (int)(idx / NPDP);
    float f = 0.f;
    if (j < NPD) {
        int b = rs >> 8, s = rs & 255;
        int hi = s >> 4, wi = s & 15;
        int c = j % 3;
        int pp = j / 3;
        int p1 = pp / 14, p2 = pp % 14;
        f = x[(((size_t)(b * 3 + c)) * 224 + hi * 14 + p1) * 224 + wi * 14 + p2];
    }
    __half h = __float2half_rn(f);
    g_p16[idx] = h;
    g_p16[SZ_P + idx] = __float2half_rn(f - __half2float(h));
}

// ---------------- LayerNorm -----------------------------------------------------
__global__ __launch_bounds__(128) void ln_k(
    const float* __restrict__ in, const float* __restrict__ gw,
    const float* __restrict__ bw, float* __restrict__ out,
    __half* __restrict__ out16)
{
    int row = blockIdx.x, tid = threadIdx.x;
    const float4* ir = (const float4*)(in + (size_t)row * 512);
    float4 v = ir[tid];
    float s = v.x + v.y + v.z + v.w;
    float q = v.x * v.x + v.y * v.y + v.z * v.z + v.w * v.w;
    __shared__ float ss[4], sq[4];
    for (int o = 16; o > 0; o >>= 1) {
        s += __shfl_xor_sync(0xffffffffu, s, o);
        q += __shfl_xor_sync(0xffffffffu, q, o);
    }
    if ((tid & 31) == 0) { ss[tid >> 5] = s; sq[tid >> 5] = q; }
    __syncthreads();
    s = ss[0] + ss[1] + ss[2] + ss[3];
    q = sq[0] + sq[1] + sq[2] + sq[3];
    float mean = s * (1.f / 512.f);
    float var  = q * (1.f / 512.f) - mean * mean;
    float inv  = rsqrtf(var + 1e-5f);
    float4 g4 = ((const float4*)gw)[tid];
    float4 b4 = ((const float4*)bw)[tid];
    float4 o;
    o.x = (v.x - mean) * inv * g4.x + b4.x;
    o.y = (v.y - mean) * inv * g4.y + b4.y;
    o.z = (v.z - mean) * inv * g4.z + b4.z;
    o.w = (v.w - mean) * inv * g4.w + b4.w;
    if (out) ((float4*)(out + (size_t)row * 512))[tid] = o;
    size_t base = (size_t)row * 512 + tid * 4;
    split2(o.x, o.y, out16 + base,     out16 + SZ_LN + base);
    split2(o.z, o.w, out16 + base + 2, out16 + SZ_LN + base + 2);
}

// ---------------- softmax over attn rows ----------------------------------------
__global__ __launch_bounds__(256) void softmax_attn_k() {
    int row  = (blockIdx.x << 3) + (threadIdx.x >> 5);
    int lane = threadIdx.x & 31;
    const float4* p = (const float4*)(g_attn + (size_t)row * 256);
    float4 a = p[lane], b = p[lane + 32];
    float m = fmaxf(fmaxf(fmaxf(a.x, a.y), fmaxf(a.z, a.w)),
                    fmaxf(fmaxf(b.x, b.y), fmaxf(b.z, b.w)));
    for (int o = 16; o > 0; o >>= 1) m = fmaxf(m, __shfl_xor_sync(0xffffffffu, m, o));
    a.x = __expf(a.x - m); a.y = __expf(a.y - m);
    a.z = __expf(a.z - m); a.w = __expf(a.w - m);
    b.x = __expf(b.x - m); b.y = __expf(b.y - m);
    b.z = __expf(b.z - m); b.w = __expf(b.w - m);
    float s = a.x + a.y + a.z + a.w + b.x + b.y + b.z + b.w;
    for (int o = 16; o > 0; o >>= 1) s += __shfl_xor_sync(0xffffffffu, s, o);
    float inv = 1.f / s;
    a.x *= inv; a.y *= inv; a.z *= inv; a.w *= inv;
    b.x *= inv; b.y *= inv; b.z *= inv; b.w *= inv;
    size_t base = (size_t)row * 256;
    split2(a.x, a.y, g_attn16 + base + lane * 4,     g_attn16 + SZ_ATTN + base + lane * 4);
    split2(a.z, a.w, g_attn16 + base + lane * 4 + 2, g_attn16 + SZ_ATTN + base + lane * 4 + 2);
    split2(b.x, b.y, g_attn16 + base + 128 + lane * 4,     g_attn16 + SZ_ATTN + base + 128 + lane * 4);
    split2(b.z, b.w, g_attn16 + base + 128 + lane * 4 + 2, g_attn16 + SZ_ATTN + base + 128 + lane * 4 + 2);
}

// ---------------- attn_w --------------------------------------------------------
__global__ __launch_bounds__(256) void attnw_k(float* __restrict__ out) {
    int bq = blockIdx.x, tid = threadIdx.x;
    int b = bq >> 8, qr = bq & 255;
    float s = 0.f;
#pragma unroll
    for (int h = 0; h < 8; h++) {
        size_t off = ((size_t)((b << 3) + h)) * 65536 + (qr << 8) + tid;
        s += __half2float(g_attn16[off]) + __half2float(g_attn16[SZ_ATTN + off]);
    }
    s *= 0.125f;
    __shared__ float red[8];
    float m = s;
    for (int o = 16; o > 0; o >>= 1) m = fmaxf(m, __shfl_xor_sync(0xffffffffu, m, o));
    if ((tid & 31) == 0) red[tid >> 5] = m;
    __syncthreads();
    m = red[0];
#pragma unroll
    for (int w = 1; w < 8; w++) m = fmaxf(m, red[w]);
    float ex = __expf(s - m);
    float sum = ex;
    __syncthreads();
    for (int o = 16; o > 0; o >>= 1) sum += __shfl_xor_sync(0xffffffffu, sum, o);
    if ((tid & 31) == 0) red[tid >> 5] = sum;
    __syncthreads();
    sum = red[0] + red[1] + red[2] + red[3] + red[4] + red[5] + red[6] + red[7];
    out[(size_t)bq * 256 + tid] = ex / sum;
}

// ---------------- router / dispatch / combine / loss ----------------------------
__global__ __launch_bounds__(256) void router_k(const float* __restrict__ rw,
                                                const float* __restrict__ rb) {
    __shared__ float s_rw[8][512];
    __shared__ float s_rb[8];
    int tid = threadIdx.x;
    for (int i = tid; i < 4096; i += 256) s_rw[i >> 9][i & 511] = rw[(i & 511) * 8 + (i >> 9)];
    if (tid < 8) s_rb[tid] = rb[tid];
    __syncthreads();
    int t = (blockIdx.x << 3) + (tid >> 5);
    int lane = tid & 31;
    const float* x = g_ln + (size_t)t * 512;
    float acc[8] = {};
    for (int k = lane; k < 512; k += 32) {
        float xv = x[k];
#pragma unroll
        for (int e = 0; e < 8; e++) acc[e] += xv * s_rw[e][k];
    }
#pragma unroll
    for (int e = 0; e < 8; e++)
        for (int o = 16; o > 0; o >>= 1) acc[e] += __shfl_xor_sync(0xffffffffu, acc[e], o);
    if (lane == 0) {
        float mx = -1e30f;
#pragma unroll
        for (int e = 0; e < 8; e++) { acc[e] += s_rb[e]; mx = fmaxf(mx, acc[e]); }
        float sum = 0.f;
#pragma unroll
        for (int e = 0; e < 8; e++) { acc[e] = __expf(acc[e] - mx); sum += acc[e]; }
        float inv = 1.f / sum;
#pragma unroll
        for (int e = 0; e < 8; e++) g_probs[t * 8 + e] = acc[e] * inv;
    }
}

__global__ __launch_bounds__(256) void dispatch_k() {
    __shared__ int   s_cnt[8];
    __shared__ float s_imp[8];
    __shared__ int   s_base[8];
    int tid = threadIdx.x;
    if (tid < 8) { s_cnt[tid] = 0; s_imp[tid] = 0.f; }
    __syncthreads();
    int t = blockIdx.x * 256 + tid;
    float p[8];
#pragma unroll
    for (int e = 0; e < 8; e++) { p[e] = g_probs[t * 8 + e]; atomicAdd(&s_imp[e], p[e]); }
    int e1 = 0; float v1 = p[0];
#pragma unroll
    for (int e = 1; e < 8; e++) if (p[e] > v1) { v1 = p[e]; e1 = e; }
    int e2 = -1; float v2 = -1e30f;
#pragma unroll
    for (int e = 0; e < 8; e++) if (e != e1 && p[e] > v2) { v2 = p[e]; e2 = e; }
    int lp1 = atomicAdd(&s_cnt[e1], 1);
    int lp2 = atomicAdd(&s_cnt[e2], 1);
    __syncthreads();
    if (tid < 8) {
        s_base[tid] = atomicAdd(&g_cnt[tid], s_cnt[tid]);
        atomicAdd(&g_imp[tid], s_imp[tid]);
    }
    __syncthreads();
    g_perm[e1 * NA + s_base[e1] + lp1] = t * 2;
    g_perm[e2 * NA + s_base[e2] + lp2] = t * 2 + 1;
    g_gate[t * 2]     = v1;
    g_gate[t * 2 + 1] = v2;
}

__global__ __launch_bounds__(128) void combine_k(float* __restrict__ OUT) {
    int t = blockIdx.x, tid = threadIdx.x;
    float gg1 = g_gate[2 * t], gg2 = g_gate[2 * t + 1];
    const float4* c1 = (const float4*)(g_contrib + (size_t)(2 * t) * 512);
    const float4* c2 = (const float4*)(g_contrib + (size_t)(2 * t + 1) * 512);
    float4 a = c1[tid], b = c2[tid];
    float4 o;
    o.x = gg1 * a.x + gg2 * b.x; o.y = gg1 * a.y + gg2 * b.y;
    o.z = gg1 * a.z + gg2 * b.z; o.w = gg1 * a.w + gg2 * b.w;
    ((float4*)(OUT + (size_t)t * 512))[tid] = o;
}

__global__ void init_k(float* out_loss) {
    int tid = threadIdx.x;
    if (tid < 8) { g_cnt[tid] = 0; g_imp[tid] = 0.f; }
    if (tid == 0) out_loss[0] = 0.f;
}
__global__ void loss_k(float* out_loss) {
    int tid = threadIdx.x;
    float v = 0.f;
    if (tid < 8)
        v = 8.f * ((float)g_cnt[tid] * (1.f / 8192.f)) * (g_imp[tid] * (1.f / 8192.f));
    for (int o = 16; o > 0; o >>= 1) v += __shfl_xor_sync(0xffffffffu, v, o);
    if (tid == 0) out_loss[0] += v;
    if (tid < 8) { g_cnt[tid] = 0; g_imp[tid] = 0.f; }
}

// ---------------- fv + logits ---------------------------------------------------
__global__ __launch_bounds__(512) void fv1_k(float* __restrict__ part) {
    int b = blockIdx.x, seg = blockIdx.y, d = threadIdx.x;
    float s = 0.f;
    int s0 = seg * 32;
    for (int ss = 0; ss < 32; ss++)
        s += g_o2[(size_t)(b * 256 + s0 + ss) * 512 + d];
    part[(size_t)(b * 8 + seg) * 512 + d] = s;
}
__global__ __launch_bounds__(512) void fv2_k(const float* __restrict__ part,
                                             float* __restrict__ out_fv) {
    int b = blockIdx.x, d = threadIdx.x;
    float s = 0.f;
#pragma unroll
    for (int seg = 0; seg < 8; seg++)
        s += part[(size_t)(b * 8 + seg) * 512 + d];
    s *= (1.f / 256.f);
    g_fv[b * 512 + d] = s;
    out_fv[b * 512 + d] = s;
}
__global__ __launch_bounds__(512) void logits_k(const float* __restrict__ W,
                                                const float* __restrict__ bias,
                                                float* __restrict__ out) {
    __shared__ float sf[512];
    int b = blockIdx.x, n = threadIdx.x;
    sf[n] = g_fv[b * 512 + n];
    __syncthreads();
    float acc = 0.f;
    for (int k = 0; k < 512; k++) acc += sf[k] * W[k * 512 + n];
    out[b * 512 + n] = acc + bias[n];
}

// ---------------- host launch ---------------------------------------------------
extern "C" void kernel_launch(void* const* d_in, const int* in_sizes, int n_in,
                              void* d_out, int out_size) {
    const float* x     = (const float*)d_in[0];
    const float* pe_w  = (const float*)d_in[1];
    const float* pe_b  = (const float*)d_in[2];
    const float* pos   = (const float*)d_in[3];
    const float* ln1_g = (const float*)d_in[4];
    const float* ln1_b = (const float*)d_in[5];
    const float* ln2_g = (const float*)d_in[6];
    const float* ln2_b = (const float*)d_in[7];
    const float* ln3_g = (const float*)d_in[8];
    const float* ln3_b = (const float*)d_in[9];
    const float* wq = (const float*)d_in[10];
    const float* bq = (const float*)d_in[11];
    const float* wk = (const float*)d_in[12];
    const float* bk = (const float*)d_in[13];
    const float* wv = (const float*)d_in[14];
    const float* bv = (const float*)d_in[15];
    const float* wo = (const float*)d_in[16];
    const float* bo = (const float*)d_in[17];
    const float* m1_rw = (const float*)d_in[18];
    const float* m1_rb = (const float*)d_in[19];
    const float* m1_w1 = (const float*)d_in[20];
    const float* m1_b1 = (const float*)d_in[21];
    const float* m1_w2 = (const float*)d_in[22];
    const float* m1_b2 = (const float*)d_in[23];
    const float* m2_rw = (const float*)d_in[24];
    const float* m2_rb = (const float*)d_in[25];
    const float* m2_w1 = (const float*)d_in[26];
    const float* m2_b1 = (const float*)d_in[27];
    const float* m2_w2 = (const float*)d_in[28];
    const float* m2_b2 = (const float*)d_in[29];
    const float* cls_w = (const float*)d_in[30];
    const float* cls_b = (const float*)d_in[31];

    float* out = (float*)d_out;
    float* out_logits = out;
    float* out_fv     = out + 16384;
    float* out_loss   = out + 32768;
    float* out_attnw  = out + 32769;

    float *p_e, *p_ln, *p_attn, *p_contrib, *p_o1, *p_o2;
    __half *p_p16, *p_ln16, *p_qkv16, *p_attn16, *p_ctx16, *p_h16;
    __half *p_pew16, *p_wqkv16, *p_wo16;
    __half *p_w1a, *p_w2a, *p_w1b, *p_w2b;
    cudaGetSymbolAddress((void**)&p_e,       g_e);
    cudaGetSymbolAddress((void**)&p_ln,      g_ln);
    cudaGetSymbolAddress((void**)&p_attn,    g_attn);
    cudaGetSymbolAddress((void**)&p_contrib, g_contrib);
    cudaGetSymbolAddress((void**)&p_o1,      g_o1);
    cudaGetSymbolAddress((void**)&p_o2,      g_o2);
    cudaGetSymbolAddress((void**)&p_p16,     g_p16);
    cudaGetSymbolAddress((void**)&p_ln16,    g_ln16);
    cudaGetSymbolAddress((void**)&p_qkv16,   g_qkv16);
    cudaGetSymbolAddress((void**)&p_attn16,  g_attn16);
    cudaGetSymbolAddress((void**)&p_ctx16,   g_ctx16);
    cudaGetSymbolAddress((void**)&p_h16,     g_h16);
    cudaGetSymbolAddress((void**)&p_pew16,   g_pew16);
    cudaGetSymbolAddress((void**)&p_wqkv16,  g_wqkv16);
    cudaGetSymbolAddress((void**)&p_wo16,    g_wo16);
    cudaGetSymbolAddress((void**)&p_w1a,     g_w1a16);
    cudaGetSymbolAddress((void**)&p_w2a,     g_w2a16);
    cudaGetSymbolAddress((void**)&p_w1b,     g_w1b16);
    cudaGetSymbolAddress((void**)&p_w2b,     g_w2b16);
    float* p_bqkv; cudaGetSymbolAddress((void**)&p_bqkv, g_bqkv);

    cudaFuncSetAttribute(ffb_k<512, 2048, 1, true>,
                         cudaFuncAttributeMaxDynamicSharedMemorySize, 73728);
    cudaFuncSetAttribute(ffb_k<2048, 512, 0, false>,
                         cudaFuncAttributeMaxDynamicSharedMemorySize, 73728);

    init_k<<<1, 32>>>(out_loss);

    // fork: big MoE weight conversions on side stream (overlaps with attention)
    cudaEventRecord(g_ss.fork, 0);
    cudaStreamWaitEvent(g_ss.s, g_ss.fork, 0);
    conv4_k<<<dim3(8192, 1, 4), 256, 0, g_ss.s>>>(
        m1_w1, m1_w2, m2_w1, m2_w2, p_w1a, p_w2a, p_w1b, p_w2b, SZ_W);
    cudaEventRecord(g_ss.join, g_ss.s);

    convpe_k<<<(NPDP * ND / 4 + 255) / 256, 256>>>(pe_w);
    conv4_k<<<dim3(256, 1, 4), 256>>>(
        wq, wk, wv, wo,
        p_wqkv16, p_wqkv16 + 2 * SZ_DD, p_wqkv16 + 4 * SZ_DD, p_wo16, SZ_DD);

    patch_k<<<(int)((SZ_P + 255) / 256), 256>>>(x);
    mm_k<M_PE><<<dim3(4, 64), 256>>>(p_p16, p_pew16, pe_b, pos, p_e);

    bqkv_k<<<6, 256>>>(bq, bk, bv);
    ln_k<<<NTOK, 128>>>(p_e, ln1_g, ln1_b, nullptr, p_ln16);
    mm_k<M_QKV><<<dim3(4, 64, 3), 256>>>(p_ln16, p_wqkv16, p_bqkv, nullptr, p_qkv16);
    mm_k<M_SC><<<dim3(4, 2, 256), 256>>>(p_qkv16, p_qkv16 + 2 * SZ_LN,
                                         nullptr, nullptr, p_attn);
    softmax_attn_k<<<8192, 256>>>();

    // attn_w depends only on softmax output -> run off the critical path
    cudaEventRecord(g_ss.attnev, 0);
    cudaStreamWaitEvent(g_ss.s, g_ss.attnev, 0);
    attnw_k<<<NTOK, 256, 0, g_ss.s>>>(out_attnw);

    mm_k<M_AV><<<dim3(1, 2, 256), 256>>>(p_attn16, p_qkv16 + 4 * SZ_LN,
                                         nullptr, nullptr, p_ctx16);
    mm_k<M_PROJ><<<dim3(4, 64), 256>>>(p_ctx16, p_wo16, bo, p_e, p_e);

    // MoE layer 1
    ln_k<<<NTOK, 128>>>(p_e, ln2_g, ln2_b, p_ln, p_ln16);
    router_k<<<1024, 256>>>(m1_rw, m1_rb);
    dispatch_k<<<32, 256>>>();
    cudaStreamWaitEvent(0, g_ss.join, 0);
    ffb_k<512, 2048, 1, true><<<dim3(16, 64, 8), 256, 73728>>>(
        p_ln16, SZ_LN, p_w1a, SZ_W, m1_b1, p_h16);
    ffb_k<2048, 512, 0, false><<<dim3(4, 64, 8), 256, 73728>>>(
        p_h16, SZ_H, p_w2a, SZ_W, m1_b2, p_contrib);
    combine_k<<<NTOK, 128>>>(p_o1);
    loss_k<<<1, 32>>>(out_loss);

    // MoE layer 2
    ln_k<<<NTOK, 128>>>(p_o1, ln3_g, ln3_b, p_ln, p_ln16);
    router_k<<<1024, 256>>>(m2_rw, m2_rb);
    dispatch_k<<<32, 256>>>();
    ffb_k<512, 2048, 1, true><<<dim3(16, 64, 8), 256, 73728>>>(
        p_ln16, SZ_LN, p_w1b, SZ_W, m2_b1, p_h16);
    ffb_k<2048, 512, 0, false><<<dim3(4, 64, 8), 256, 73728>>>(
        p_h16, SZ_H, p_w2b, SZ_W, m2_b2, p_contrib);
    combine_k<<<NTOK, 128>>>(p_o2);
    loss_k<<<1, 32>>>(out_loss);

    fv1_k<<<dim3(NB, 8), 512>>>(p_contrib);
    fv2_k<<<NB, 512>>>(p_contrib, out_fv);
    logits_k<<<NB, 512>>>(cls_w, cls_b, out_logits);

    // main stream must not signal completion before side-stream attnw is done
    cudaEventRecord(g_ss.join, g_ss.s);
    cudaStreamWaitEvent(0, g_ss.join, 0);
}

// round 9
// speedup vs baseline: 1.1348x; 1.0744x over previous
#include <cuda_runtime.h>
#include <cuda_fp16.h>
#include <math.h>
#include <stdint.h>

#define NB   32
#define NS   256
#define ND   512
#define NH   8
#define NE   8
#define NHID 2048
#define NPD  588
#define NPDP 608
#define NTOK 8192
#define NA   16384

#define SZ_LN   ((size_t)NTOK * ND)
#define SZ_P    ((size_t)NTOK * NPDP)
#define SZ_ATTN ((size_t)NB * NH * NS * NS)
#define SZ_H    ((size_t)NA * NHID)
#define SZ_W    ((size_t)NE * ND * NHID)
#define SZ_DD   ((size_t)ND * ND)

// ---------------- fp32 scratch -------------------------------------------------
__device__ float g_e[NTOK * ND];
__device__ float g_attn[NB * NH * NS * NS];
__device__ float g_probs[NTOK * NE];
__device__ float g_gate[NA];
__device__ int   g_perm[NE * NA];
__device__ int   g_cnt[NE];
__device__ float g_imp[NE];
__device__ float g_contrib[NA * ND];
__device__ float g_o1[NTOK * ND];
__device__ float g_o2[NTOK * ND];
__device__ float g_fv[NB * ND];
__device__ float g_bqkv[3 * ND];

// ---------------- split fp16 buffers (hi at [0], lo at [SIZE] per segment) -----
__device__ __half g_p16[2 * SZ_P];
__device__ __half g_ln16[2 * SZ_LN];
__device__ __half g_qkv16[6 * SZ_LN];
__device__ __half g_attn16[2 * SZ_ATTN];
__device__ __half g_ctx16[2 * SZ_LN];
__device__ __half g_h16[2 * SZ_H];
__device__ __half g_pew16[2 * NPDP * ND];
__device__ __half g_wqkv16[6 * SZ_DD];
__device__ __half g_wo16[2 * SZ_DD];
__device__ __half g_w1a16[2 * SZ_W];
__device__ __half g_w2a16[2 * SZ_W];
__device__ __half g_w1b16[2 * SZ_W];
__device__ __half g_w2b16[2 * SZ_W];

// ---------------- persistent side stream ---------------------------------------
struct SideStream {
    cudaStream_t s;
    cudaEvent_t fork, join, attnev;
    SideStream() {
        cudaStreamCreateWithFlags(&s, cudaStreamNonBlocking);
        cudaEventCreateWithFlags(&fork, cudaEventDisableTiming);
        cudaEventCreateWithFlags(&join, cudaEventDisableTiming);
        cudaEventCreateWithFlags(&attnev, cudaEventDisableTiming);
    }
};
static SideStream g_ss;

__device__ __forceinline__ float gelu_exact(float v) {
    return 0.5f * v * (1.0f + erff(v * 0.70710678118654752440f));
}
__device__ __forceinline__ void split2(float v0, float v1, __half* oh, __half* ol) {
    __half h0 = __float2half_rn(v0), h1 = __float2half_rn(v1);
    *(__half2*)oh = __halves2half2(h0, h1);
    *(__half2*)ol = __halves2half2(__float2half_rn(v0 - __half2float(h0)),
                                   __float2half_rn(v1 - __half2float(h1)));
}

// ---------------- mma.sync helpers ----------------------------------------------
__device__ __forceinline__ void ldsm4(unsigned* r, unsigned addr) {
    asm volatile("ldmatrix.sync.aligned.m8n8.x4.shared.b16 {%0,%1,%2,%3}, [%4];\n"
        : "=r"(r[0]), "=r"(r[1]), "=r"(r[2]), "=r"(r[3]) : "r"(addr));
}
__device__ __forceinline__ void ldsm4t(unsigned* r, unsigned addr) {
    asm volatile("ldmatrix.sync.aligned.m8n8.x4.trans.shared.b16 {%0,%1,%2,%3}, [%4];\n"
        : "=r"(r[0]), "=r"(r[1]), "=r"(r[2]), "=r"(r[3]) : "r"(addr));
}
__device__ __forceinline__ void mma16816(float* c, const unsigned* a, const unsigned* b) {
    asm volatile("mma.sync.aligned.m16n8k16.row.col.f32.f16.f16.f32 "
        "{%0,%1,%2,%3}, {%4,%5,%6,%7}, {%8,%9}, {%0,%1,%2,%3};\n"
        : "+f"(c[0]), "+f"(c[1]), "+f"(c[2]), "+f"(c[3])
        : "r"(a[0]), "r"(a[1]), "r"(a[2]), "r"(a[3]), "r"(b[0]), "r"(b[1]));
}
__device__ __forceinline__ void cpa16(unsigned dst, const void* src, bool p) {
    int sz = p ? 16 : 0;
    asm volatile("cp.async.cg.shared.global [%0], [%1], 16, %2;\n"
        :: "r"(dst), "l"(src), "r"(sz));
}

// ---------------- modes --------------------------------------------------------
#define M_PE   0
#define M_QKV  1
#define M_PROJ 2
#define M_SC   3
#define M_AV   4
#define M_FF1  5
#define M_FF2  6

template <int MODE>
__global__ __launch_bounds__(256) void mm_k(
    const __half* __restrict__ Ag, const __half* __restrict__ Bg,
    const float* __restrict__ bias, const float* __restrict__ extra,
    void* __restrict__ Og)
{
    constexpr int K   = (MODE == M_PE) ? NPDP : (MODE == M_SC) ? 64 :
                        (MODE == M_AV) ? 256 : (MODE == M_FF2) ? 2048 : 512;
    constexpr int LDA = K;
    constexpr int LDB = (MODE == M_SC || MODE == M_AV) ? 64 :
                        (MODE == M_FF1) ? 2048 : 512;
    constexpr bool NT = (MODE == M_SC);
    constexpr bool GATHER = (MODE == M_FF1) || (MODE == M_FF2);
    constexpr int SHIFT = (MODE == M_FF1) ? 1 : 0;
    constexpr int BN = (MODE == M_AV || MODE == M_SC) ? 64 : 128;
    constexpr int WN = BN / 4;
    constexpr int NF = WN / 8;
    constexpr int KT = K / 16;
    constexpr size_t ALO =
        (MODE == M_PE)  ? SZ_P :
        (MODE == M_SC || MODE == M_QKV || MODE == M_PROJ || MODE == M_FF1) ? SZ_LN :
        (MODE == M_AV)  ? SZ_ATTN : SZ_H;
    constexpr size_t BLO =
        (MODE == M_PE)  ? (size_t)NPDP * ND :
        (MODE == M_QKV || MODE == M_PROJ) ? SZ_DD :
        (MODE == M_SC || MODE == M_AV) ? SZ_LN : SZ_W;
    constexpr size_t OLO =
        (MODE == M_QKV || MODE == M_AV) ? SZ_LN : SZ_H;
    constexpr int AST = 128 * 24;
    constexpr int BST = NT ? BN * 24 : 16 * BN;

    __shared__ __align__(16) __half As[2][2][AST];
    __shared__ __align__(16) __half Bs[2][2][BST];
    __shared__ int s_idx[128];

    int tid = threadIdx.x;
    int bz = blockIdx.z;
    int row0 = blockIdx.y * 128, col0 = blockIdx.x * BN;

    const __half* Ah = Ag;
    const __half* Bh = Bg;
    if (MODE == M_SC)  { Ah += (size_t)bz * 256 * 64; Bh += (size_t)bz * 256 * 64; }
    if (MODE == M_AV)  { Ah += (size_t)bz * 65536;    Bh += (size_t)bz * 256 * 64; }
    if (MODE == M_QKV) { Bh += (size_t)bz * 2 * SZ_DD; }
    if (MODE == M_FF1) { Bh += (size_t)bz * 512 * 2048; }
    if (MODE == M_FF2) { Bh += (size_t)bz * 2048 * 512; }
    const __half* Al = Ah + ALO;
    const __half* Bl = Bh + BLO;

    if (GATHER) {
        int cnt = g_cnt[bz];
        if (row0 >= cnt) return;
        if (tid < 128) {
            int r = row0 + tid;
            s_idx[tid] = (r < cnt) ? g_perm[bz * NA + r] : -1;
        }
        __syncthreads();
    }

    int a_row = tid >> 1, a_ch = tid & 1;
    unsigned a_dst = (unsigned)((a_row * 24 + a_ch * 8) * 2);
    const __half* a_srch; const __half* a_srcl; bool a_pred;
    if (GATHER) {
        int a = s_idx[a_row];
        a_pred = (a >= 0);
        size_t off = a_pred ? (size_t)(a >> SHIFT) * LDA + a_ch * 8 : 0;
        a_srch = Ah + off; a_srcl = Al + off;
    } else {
        a_pred = true;
        size_t off = (size_t)(row0 + a_row) * LDA + a_ch * 8;
        a_srch = Ah + off; a_srcl = Al + off;
    }
    unsigned b_dst = 0; const __half* b_srch = Bh; const __half* b_srcl = Bh;
    bool b_val;
    if (!NT) {
        b_val = tid < (16 * BN / 8);
        int row = tid / (BN / 8), cn = tid % (BN / 8);
        int sw = cn ^ (row & 7);
        b_dst = (unsigned)((row * BN + sw * 8) * 2);
        size_t off = (size_t)row * LDB + col0 + cn * 8;
        b_srch = Bh + off; b_srcl = Bl + off;
    } else {
        b_val = tid < (BN * 2);
        int nr = tid >> 1, ch = tid & 1;
        b_dst = (unsigned)((nr * 24 + ch * 8) * 2);
        size_t off = (size_t)(col0 + nr) * LDB + ch * 8;
        b_srch = Bh + off; b_srcl = Bl + off;
    }

    unsigned as_base = (unsigned)__cvta_generic_to_shared(&As[0][0][0]);
    unsigned bs_base = (unsigned)__cvta_generic_to_shared(&Bs[0][0][0]);

    auto issue = [&](int kt, int buf) {
        unsigned abh = as_base + (buf * 2 + 0) * AST * 2;
        unsigned abl = as_base + (buf * 2 + 1) * AST * 2;
        cpa16(abh + a_dst, a_srch + (size_t)kt * 16, a_pred);
        cpa16(abl + a_dst, a_srcl + (size_t)kt * 16, a_pred);
        if (b_val) {
            unsigned bbh = bs_base + (buf * 2 + 0) * BST * 2;
            unsigned bbl = bs_base + (buf * 2 + 1) * BST * 2;
            size_t off = NT ? (size_t)kt * 16 : (size_t)kt * 16 * LDB;
            cpa16(bbh + b_dst, b_srch + off, true);
            cpa16(bbl + b_dst, b_srcl + off, true);
        }
        asm volatile("cp.async.commit_group;\n");
    };

    int lane = tid & 31;
    int warp = tid >> 5;
    int wm = warp >> 2, wn = warp & 3;

    float acc[4][NF][4];
#pragma unroll
    for (int i = 0; i < 4; i++)
#pragma unroll
        for (int j = 0; j < NF; j++)
#pragma unroll
            for (int t = 0; t < 4; t++) acc[i][j][t] = 0.f;

    issue(0, 0);
#pragma unroll 1
    for (int kt = 0; kt < KT; kt++) {
        int buf = kt & 1;
        if (kt + 1 < KT) {
            issue(kt + 1, buf ^ 1);
            asm volatile("cp.async.wait_group 1;\n");
        } else {
            asm volatile("cp.async.wait_group 0;\n");
        }
        __syncthreads();
        unsigned abh = as_base + (buf * 2 + 0) * AST * 2;
        unsigned abl = as_base + (buf * 2 + 1) * AST * 2;
        unsigned bbh = bs_base + (buf * 2 + 0) * BST * 2;
        unsigned bbl = bs_base + (buf * 2 + 1) * BST * 2;

        unsigned ah[4][4], al[4][4];
#pragma unroll
        for (int i = 0; i < 4; i++) {
            int m = wm * 64 + i * 16 + (lane & 15);
            int ch = lane >> 4;
            unsigned ad = (unsigned)((m * 24 + ch * 8) * 2);
            ldsm4(ah[i], abh + ad);
            ldsm4(al[i], abl + ad);
        }
        unsigned brh[2 * NF], brl[2 * NF];
#pragma unroll
        for (int jj = 0; jj < NF / 2; jj++) {
            int n0 = wn * WN + jj * 16;
            if (!NT) {
                int k = lane & 15;
                int cn = (n0 >> 3) + (lane >> 4);
                int sw = cn ^ (k & 7);
                unsigned bd = (unsigned)((k * BN + sw * 8) * 2);
                ldsm4t(&brh[jj * 4], bbh + bd);
                ldsm4t(&brl[jj * 4], bbl + bd);
            } else {
                int n = n0 + ((lane >> 4) << 3) + (lane & 7);
                int ch = (lane >> 3) & 1;
                unsigned bd = (unsigned)((n * 24 + ch * 8) * 2);
                ldsm4(&brh[jj * 4], bbh + bd);
                ldsm4(&brl[jj * 4], bbl + bd);
            }
        }
#pragma unroll
        for (int i = 0; i < 4; i++)
#pragma unroll
            for (int j = 0; j < NF; j++) {
                mma16816(acc[i][j], ah[i], &brh[j * 2]);
                mma16816(acc[i][j], al[i], &brh[j * 2]);
                mma16816(acc[i][j], ah[i], &brl[j * 2]);
            }
        __syncthreads();
    }

    int rl = lane >> 2, cp2 = (lane & 3) * 2;
#pragma unroll
    for (int i = 0; i < 4; i++) {
#pragma unroll
        for (int hh = 0; hh < 2; hh++) {
            int rr = wm * 64 + i * 16 + rl + hh * 8;
            int r = row0 + rr;
            int aidx = 0;
            if (GATHER) {
                aidx = s_idx[rr];
                if (aidx < 0) continue;
            }
#pragma unroll
            for (int j = 0; j < NF; j++) {
                int c = col0 + wn * WN + j * 8 + cp2;
                float v0 = acc[i][j][hh * 2 + 0];
                float v1 = acc[i][j][hh * 2 + 1];
                if (MODE == M_PE) {
                    float* O = (float*)Og;
                    v0 += bias[c]     + extra[(size_t)(r & 255) * 512 + c];
                    v1 += bias[c + 1] + extra[(size_t)(r & 255) * 512 + c + 1];
                    O[(size_t)r * 512 + c] = v0;
                    O[(size_t)r * 512 + c + 1] = v1;
                } else if (MODE == M_QKV) {
                    __half* O = (__half*)Og + (size_t)bz * 2 * SZ_LN;
                    const float* bi = bias + bz * 512;
                    v0 += bi[c]; v1 += bi[c + 1];
                    int b = r >> 8, s = r & 255, hd = c >> 6, ii = c & 63;
                    size_t o = (size_t)(((b << 3) + hd) * 256 + s) * 64 + ii;
                    split2(v0, v1, O + o, O + OLO + o);
                } else if (MODE == M_PROJ) {
                    float* O = (float*)Og;
                    v0 += bias[c]     + extra[(size_t)r * 512 + c];
                    v1 += bias[c + 1] + extra[(size_t)r * 512 + c + 1];
                    O[(size_t)r * 512 + c] = v0;
                    O[(size_t)r * 512 + c + 1] = v1;
                } else if (MODE == M_SC) {
                    float* O = (float*)Og + (size_t)bz * 65536;
                    O[(size_t)r * 256 + c] = v0 * 0.125f;
                    O[(size_t)r * 256 + c + 1] = v1 * 0.125f;
                } else if (MODE == M_AV) {
                    __half* O = (__half*)Og;
                    int b = bz >> 3, hd = bz & 7;
                    size_t o = (size_t)((b << 8) + r) * 512 + (hd << 6) + c;
                    split2(v0, v1, O + o, O + OLO + o);
                } else if (MODE == M_FF1) {
                    __half* O = (__half*)Og;
                    const float* bi = bias + bz * 2048;
                    v0 = gelu_exact(v0 + bi[c]);
                    v1 = gelu_exact(v1 + bi[c + 1]);
                    size_t o = (size_t)aidx * 2048 + c;
                    split2(v0, v1, O + o, O + OLO + o);
                } else {
                    float* O = (float*)Og;
                    const float* bi = bias + bz * 512;
                    O[(size_t)aidx * 512 + c] = v0 + bi[c];
                    O[(size_t)aidx * 512 + c + 1] = v1 + bi[c + 1];
                }
            }
        }
    }
}

// ---------------- conversions ---------------------------------------------------
struct __align__(8) h2x2 { __half2 a, b; };

__device__ __forceinline__ void conv_elem4(const float* in, __half* outh, size_t n,
                                           size_t i) {
    float4 f = *(const float4*)(in + i);
    h2x2 H, L;
    H.a = __floats2half2_rn(f.x, f.y);
    H.b = __floats2half2_rn(f.z, f.w);
    float2 f0 = __half22float2(H.a), f1 = __half22float2(H.b);
    L.a = __floats2half2_rn(f.x - f0.x, f.y - f0.y);
    L.b = __floats2half2_rn(f.z - f1.x, f.w - f1.y);
    *(h2x2*)(outh + i) = H;
    *(h2x2*)(outh + n + i) = L;
}

__global__ __launch_bounds__(256) void conv4_k(
    const float* __restrict__ s0, const float* __restrict__ s1,
    const float* __restrict__ s2, const float* __restrict__ s3,
    __half* __restrict__ d0, __half* __restrict__ d1,
    __half* __restrict__ d2, __half* __restrict__ d3, size_t n)
{
    const float* src = (blockIdx.z == 0) ? s0 : (blockIdx.z == 1) ? s1 :
                       (blockIdx.z == 2) ? s2 : s3;
    __half* dst = (blockIdx.z == 0) ? d0 : (blockIdx.z == 1) ? d1 :
                  (blockIdx.z == 2) ? d2 : d3;
    size_t i = ((size_t)blockIdx.x * 256 + threadIdx.x) * 4;
    if (i < n) conv_elem4(src, dst, n, i);
}

__global__ __launch_bounds__(256) void convpe_k(const float* __restrict__ w) {
    int i = (blockIdx.x * 256 + threadIdx.x) * 4;
    if (i >= NPDP * ND) return;
    int j = i >> 9;
    float4 f = make_float4(0.f, 0.f, 0.f, 0.f);
    if (j < NPD) f = *(const float4*)(w + i);
    h2x2 H, L;
    H.a = __floats2half2_rn(f.x, f.y);
    H.b = __floats2half2_rn(f.z, f.w);
    float2 f0 = __half22float2(H.a), f1 = __half22float2(H.b);
    L.a = __floats2half2_rn(f.x - f0.x, f.y - f0.y);
    L.b = __floats2half2_rn(f.z - f1.x, f.w - f1.y);
    *(h2x2*)(g_pew16 + i) = H;
    *(h2x2*)(g_pew16 + NPDP * ND + i) = L;
}

// bqkv gather + global init (counters, loss)
__global__ void bqkv_k(const float* __restrict__ bq, const float* __restrict__ bk,
                       const float* __restrict__ bv, float* out_loss) {
    int i = blockIdx.x * 256 + threadIdx.x;
    if (blockIdx.x == 0 && threadIdx.x < 8) { g_cnt[threadIdx.x] = 0; g_imp[threadIdx.x] = 0.f; }
    if (i == 0) out_loss[0] = 0.f;
    if (i >= 1536) return;
    g_bqkv[i] = (i < 512) ? bq[i] : (i < 1024) ? bk[i - 512] : bv[i - 1024];
}

// ---------------- patch gather --------------------------------------------------
__global__ void patch_k(const float* __restrict__ x) {
    size_t idx = (size_t)blockIdx.x * 256 + threadIdx.x;
    if (idx >= SZ_P) return;
    int j = (int)(idx % NPDP);
    int rs = (int)(idx / NPDP);
    float f = 0.f;
    if (j < NPD) {
        int b = rs >> 8, s = rs & 255;
        int hi = s >> 4, wi = s & 15;
        int c = j % 3;
        int pp = j / 3;
        int p1 = pp / 14, p2 = pp % 14;
        f = x[(((size_t)(b * 3 + c)) * 224 + hi * 14 + p1) * 224 + wi * 14 + p2];
    }
    __half h = __float2half_rn(f);
    g_p16[idx] = h;
    g_p16[SZ_P + idx] = __float2half_rn(f - __half2float(h));
}

// ---------------- LayerNorm (+ fused MoE router when ROUTER) --------------------
template <bool ROUTER>
__global__ __launch_bounds__(128) void ln_k(
    const float* __restrict__ in, const float* __restrict__ gw,
    const float* __restrict__ bw, __half* __restrict__ out16,
    const float* __restrict__ rw, const float* __restrict__ rb)
{
    int row = blockIdx.x, tid = threadIdx.x;
    const float4* ir = (const float4*)(in + (size_t)row * 512);
    float4 v = ir[tid];
    float s = v.x + v.y + v.z + v.w;
    float q = v.x * v.x + v.y * v.y + v.z * v.z + v.w * v.w;
    __shared__ float ss[4], sq[4];
    for (int o = 16; o > 0; o >>= 1) {
        s += __shfl_xor_sync(0xffffffffu, s, o);
        q += __shfl_xor_sync(0xffffffffu, q, o);
    }
    if ((tid & 31) == 0) { ss[tid >> 5] = s; sq[tid >> 5] = q; }
    __syncthreads();
    s = ss[0] + ss[1] + ss[2] + ss[3];
    q = sq[0] + sq[1] + sq[2] + sq[3];
    float mean = s * (1.f / 512.f);
    float var  = q * (1.f / 512.f) - mean * mean;
    float inv  = rsqrtf(var + 1e-5f);
    float4 g4 = ((const float4*)gw)[tid];
    float4 b4 = ((const float4*)bw)[tid];
    float4 o;
    o.x = (v.x - mean) * inv * g4.x + b4.x;
    o.y = (v.y - mean) * inv * g4.y + b4.y;
    o.z = (v.z - mean) * inv * g4.z + b4.z;
    o.w = (v.w - mean) * inv * g4.w + b4.w;
    size_t base = (size_t)row * 512 + tid * 4;
    split2(o.x, o.y, out16 + base,     out16 + SZ_LN + base);
    split2(o.z, o.w, out16 + base + 2, out16 + SZ_LN + base + 2);

    if (ROUTER) {
        int k0 = tid * 4;
        float acc[8];
        const float4* r0 = (const float4*)(rw + (size_t)(k0 + 0) * 8);
        const float4* r1 = (const float4*)(rw + (size_t)(k0 + 1) * 8);
        const float4* r2 = (const float4*)(rw + (size_t)(k0 + 2) * 8);
        const float4* r3 = (const float4*)(rw + (size_t)(k0 + 3) * 8);
        float4 w0a = r0[0], w0b = r0[1];
        float4 w1a = r1[0], w1b = r1[1];
        float4 w2a = r2[0], w2b = r2[1];
        float4 w3a = r3[0], w3b = r3[1];
        acc[0] = o.x * w0a.x + o.y * w1a.x + o.z * w2a.x + o.w * w3a.x;
        acc[1] = o.x * w0a.y + o.y * w1a.y + o.z * w2a.y + o.w * w3a.y;
        acc[2] = o.x * w0a.z + o.y * w1a.z + o.z * w2a.z + o.w * w3a.z;
        acc[3] = o.x * w0a.w + o.y * w1a.w + o.z * w2a.w + o.w * w3a.w;
        acc[4] = o.x * w0b.x + o.y * w1b.x + o.z * w2b.x + o.w * w3b.x;
        acc[5] = o.x * w0b.y + o.y * w1b.y + o.z * w2b.y + o.w * w3b.y;
        acc[6] = o.x * w0b.z + o.y * w1b.z + o.z * w2b.z + o.w * w3b.z;
        acc[7] = o.x * w0b.w + o.y * w1b.w + o.z * w2b.w + o.w * w3b.w;
#pragma unroll
        for (int e = 0; e < 8; e++)
            for (int of = 16; of > 0; of >>= 1)
                acc[e] += __shfl_xor_sync(0xffffffffu, acc[e], of);
        __shared__ float sred[4][8];
        if ((tid & 31) == 0)
#pragma unroll
            for (int e = 0; e < 8; e++) sred[tid >> 5][e] = acc[e];
        __syncthreads();
        if (tid == 0) {
            float l[8]; float mx = -1e30f;
#pragma unroll
            for (int e = 0; e < 8; e++) {
                l[e] = sred[0][e] + sred[1][e] + sred[2][e] + sred[3][e] + rb[e];
                mx = fmaxf(mx, l[e]);
            }
            float sum = 0.f;
#pragma unroll
            for (int e = 0; e < 8; e++) { l[e] = __expf(l[e] - mx); sum += l[e]; }
            float is = 1.f / sum;
#pragma unroll
            for (int e = 0; e < 8; e++) g_probs[row * 8 + e] = l[e] * is;
        }
    }
}

// ---------------- softmax over attn rows ----------------------------------------
__global__ __launch_bounds__(256) void softmax_attn_k() {
    int row  = (blockIdx.x << 3) + (threadIdx.x >> 5);
    int lane = threadIdx.x & 31;
    const float4* p = (const float4*)(g_attn + (size_t)row * 256);
    float4 a = p[lane], b = p[lane + 32];
    float m = fmaxf(fmaxf(fmaxf(a.x, a.y), fmaxf(a.z, a.w)),
                    fmaxf(fmaxf(b.x, b.y), fmaxf(b.z, b.w)));
    for (int o = 16; o > 0; o >>= 1) m = fmaxf(m, __shfl_xor_sync(0xffffffffu, m, o));
    a.x = __expf(a.x - m); a.y = __expf(a.y - m);
    a.z = __expf(a.z - m); a.w = __expf(a.w - m);
    b.x = __expf(b.x - m); b.y = __expf(b.y - m);
    b.z = __expf(b.z - m); b.w = __expf(b.w - m);
    float s = a.x + a.y + a.z + a.w + b.x + b.y + b.z + b.w;
    for (int o = 16; o > 0; o >>= 1) s += __shfl_xor_sync(0xffffffffu, s, o);
    float inv = 1.f / s;
    a.x *= inv; a.y *= inv; a.z *= inv; a.w *= inv;
    b.x *= inv; b.y *= inv; b.z *= inv; b.w *= inv;
    size_t base = (size_t)row * 256;
    split2(a.x, a.y, g_attn16 + base + lane * 4,     g_attn16 + SZ_ATTN + base + lane * 4);
    split2(a.z, a.w, g_attn16 + base + lane * 4 + 2, g_attn16 + SZ_ATTN + base + lane * 4 + 2);
    split2(b.x, b.y, g_attn16 + base + 128 + lane * 4,     g_attn16 + SZ_ATTN + base + 128 + lane * 4);
    split2(b.z, b.w, g_attn16 + base + 128 + lane * 4 + 2, g_attn16 + SZ_ATTN + base + 128 + lane * 4 + 2);
}

// ---------------- attn_w --------------------------------------------------------
__global__ __launch_bounds__(256) void attnw_k(float* __restrict__ out) {
    int bq = blockIdx.x, tid = threadIdx.x;
    int b = bq >> 8, qr = bq & 255;
    float s = 0.f;
#pragma unroll
    for (int h = 0; h < 8; h++) {
        size_t off = ((size_t)((b << 3) + h)) * 65536 + (qr << 8) + tid;
        s += __half2float(g_attn16[off]) + __half2float(g_attn16[SZ_ATTN + off]);
    }
    s *= 0.125f;
    __shared__ float red[8];
    float m = s;
    for (int o = 16; o > 0; o >>= 1) m = fmaxf(m, __shfl_xor_sync(0xffffffffu, m, o));
    if ((tid & 31) == 0) red[tid >> 5] = m;
    __syncthreads();
    m = red[0];
#pragma unroll
    for (int w = 1; w < 8; w++) m = fmaxf(m, red[w]);
    float ex = __expf(s - m);
    float sum = ex;
    __syncthreads();
    for (int o = 16; o > 0; o >>= 1) sum += __shfl_xor_sync(0xffffffffu, sum, o);
    if ((tid & 31) == 0) red[tid >> 5] = sum;
    __syncthreads();
    sum = red[0] + red[1] + red[2] + red[3] + red[4] + red[5] + red[6] + red[7];
    out[(size_t)bq * 256 + tid] = ex / sum;
}

// ---------------- dispatch / combine / loss -------------------------------------
__global__ __launch_bounds__(256) void dispatch_k() {
    __shared__ int   s_cnt[8];
    __shared__ float s_imp[8];
    __shared__ int   s_base[8];
    int tid = threadIdx.x;
    if (tid < 8) { s_cnt[tid] = 0; s_imp[tid] = 0.f; }
    __syncthreads();
    int t = blockIdx.x * 256 + tid;
    float p[8];
#pragma unroll
    for (int e = 0; e < 8; e++) { p[e] = g_probs[t * 8 + e]; atomicAdd(&s_imp[e], p[e]); }
    int e1 = 0; float v1 = p[0];
#pragma unroll
    for (int e = 1; e < 8; e++) if (p[e] > v1) { v1 = p[e]; e1 = e; }
    int e2 = -1; float v2 = -1e30f;
#pragma unroll
    for (int e = 0; e < 8; e++) if (e != e1 && p[e] > v2) { v2 = p[e]; e2 = e; }
    int lp1 = atomicAdd(&s_cnt[e1], 1);
    int lp2 = atomicAdd(&s_cnt[e2], 1);
    __syncthreads();
    if (tid < 8) {
        s_base[tid] = atomicAdd(&g_cnt[tid], s_cnt[tid]);
        atomicAdd(&g_imp[tid], s_imp[tid]);
    }
    __syncthreads();
    g_perm[e1 * NA + s_base[e1] + lp1] = t * 2;
    g_perm[e2 * NA + s_base[e2] + lp2] = t * 2 + 1;
    g_gate[t * 2]     = v1;
    g_gate[t * 2 + 1] = v2;
}

__global__ __launch_bounds__(128) void combine_k(float* __restrict__ OUT) {
    int t = blockIdx.x, tid = threadIdx.x;
    float gg1 = g_gate[2 * t], gg2 = g_gate[2 * t + 1];
    const float4* c1 = (const float4*)(g_contrib + (size_t)(2 * t) * 512);
    const float4* c2 = (const float4*)(g_contrib + (size_t)(2 * t + 1) * 512);
    float4 a = c1[tid], b = c2[tid];
    float4 o;
    o.x = gg1 * a.x + gg2 * b.x; o.y = gg1 * a.y + gg2 * b.y;
    o.z = gg1 * a.z + gg2 * b.z; o.w = gg1 * a.w + gg2 * b.w;
    ((float4*)(OUT + (size_t)t * 512))[tid] = o;
}

__global__ void loss_k(float* out_loss) {
    int tid = threadIdx.x;
    float v = 0.f;
    if (tid < 8)
        v = 8.f * ((float)g_cnt[tid] * (1.f / 8192.f)) * (g_imp[tid] * (1.f / 8192.f));
    for (int o = 16; o > 0; o >>= 1) v += __shfl_xor_sync(0xffffffffu, v, o);
    if (tid == 0) out_loss[0] += v;
    if (tid < 8) { g_cnt[tid] = 0; g_imp[tid] = 0.f; }
}

// ---------------- fv + logits ---------------------------------------------------
__global__ __launch_bounds__(512) void fv1_k(float* __restrict__ part) {
    int b = blockIdx.x, seg = blockIdx.y, d = threadIdx.x;
    float s = 0.f;
    int s0 = seg * 32;
    for (int ss = 0; ss < 32; ss++)
        s += g_o2[(size_t)(b * 256 + s0 + ss) * 512 + d];
    part[(size_t)(b * 8 + seg) * 512 + d] = s;
}
__global__ __launch_bounds__(512) void fv2_k(const float* __restrict__ part,
                                             float* __restrict__ out_fv) {
    int b = blockIdx.x, d = threadIdx.x;
    float s = 0.f;
#pragma unroll
    for (int seg = 0; seg < 8; seg++)
        s += part[(size_t)(b * 8 + seg) * 512 + d];
    s *= (1.f / 256.f);
    g_fv[b * 512 + d] = s;
    out_fv[b * 512 + d] = s;
}
__global__ __launch_bounds__(512) void logits_k(const float* __restrict__ W,
                                                const float* __restrict__ bias,
                                                float* __restrict__ out) {
    __shared__ float sf[512];
    int b = blockIdx.x, n = threadIdx.x;
    sf[n] = g_fv[b * 512 + n];
    __syncthreads();
    float acc = 0.f;
    for (int k = 0; k < 512; k++) acc += sf[k] * W[k * 512 + n];
    out[b * 512 + n] = acc + bias[n];
}

// ---------------- host launch ---------------------------------------------------
extern "C" void kernel_launch(void* const* d_in, const int* in_sizes, int n_in,
                              void* d_out, int out_size) {
    const float* x     = (const float*)d_in[0];
    const float* pe_w  = (const float*)d_in[1];
    const float* pe_b  = (const float*)d_in[2];
    const float* pos   = (const float*)d_in[3];
    const float* ln1_g = (const float*)d_in[4];
    const float* ln1_b = (const float*)d_in[5];
    const float* ln2_g = (const float*)d_in[6];
    const float* ln2_b = (const float*)d_in[7];
    const float* ln3_g = (const float*)d_in[8];
    const float* ln3_b = (const float*)d_in[9];
    const float* wq = (const float*)d_in[10];
    const float* bq = (const float*)d_in[11];
    const float* wk = (const float*)d_in[12];
    const float* bk = (const float*)d_in[13];
    const float* wv = (const float*)d_in[14];
    const float* bv = (const float*)d_in[15];
    const float* wo = (const float*)d_in[16];
    const float* bo = (const float*)d_in[17];
    const float* m1_rw = (const float*)d_in[18];
    const float* m1_rb = (const float*)d_in[19];
    const float* m1_w1 = (const float*)d_in[20];
    const float* m1_b1 = (const float*)d_in[21];
    const float* m1_w2 = (const float*)d_in[22];
    const float* m1_b2 = (const float*)d_in[23];
    const float* m2_rw = (const float*)d_in[24];
    const float* m2_rb = (const float*)d_in[25];
    const float* m2_w1 = (const float*)d_in[26];
    const float* m2_b1 = (const float*)d_in[27];
    const float* m2_w2 = (const float*)d_in[28];
    const float* m2_b2 = (const float*)d_in[29];
    const float* cls_w = (const float*)d_in[30];
    const float* cls_b = (const float*)d_in[31];

    float* out = (float*)d_out;
    float* out_logits = out;
    float* out_fv     = out + 16384;
    float* out_loss   = out + 32768;
    float* out_attnw  = out + 32769;

    float *p_e, *p_attn, *p_contrib, *p_o1, *p_o2;
    __half *p_p16, *p_ln16, *p_qkv16, *p_attn16, *p_ctx16, *p_h16;
    __half *p_pew16, *p_wqkv16, *p_wo16;
    __half *p_w1a, *p_w2a, *p_w1b, *p_w2b;
    cudaGetSymbolAddress((void**)&p_e,       g_e);
    cudaGetSymbolAddress((void**)&p_attn,    g_attn);
    cudaGetSymbolAddress((void**)&p_contrib, g_contrib);
    cudaGetSymbolAddress((void**)&p_o1,      g_o1);
    cudaGetSymbolAddress((void**)&p_o2,      g_o2);
    cudaGetSymbolAddress((void**)&p_p16,     g_p16);
    cudaGetSymbolAddress((void**)&p_ln16,    g_ln16);
    cudaGetSymbolAddress((void**)&p_qkv16,   g_qkv16);
    cudaGetSymbolAddress((void**)&p_attn16,  g_attn16);
    cudaGetSymbolAddress((void**)&p_ctx16,   g_ctx16);
    cudaGetSymbolAddress((void**)&p_h16,     g_h16);
    cudaGetSymbolAddress((void**)&p_pew16,   g_pew16);
    cudaGetSymbolAddress((void**)&p_wqkv16,  g_wqkv16);
    cudaGetSymbolAddress((void**)&p_wo16,    g_wo16);
    cudaGetSymbolAddress((void**)&p_w1a,     g_w1a16);
    cudaGetSymbolAddress((void**)&p_w2a,     g_w2a16);
    cudaGetSymbolAddress((void**)&p_w1b,     g_w1b16);
    cudaGetSymbolAddress((void**)&p_w2b,     g_w2b16);
    float* p_bqkv; cudaGetSymbolAddress((void**)&p_bqkv, g_bqkv);

    // fork: big MoE weight conversions on side stream (overlaps with attention)
    cudaEventRecord(g_ss.fork, 0);
    cudaStreamWaitEvent(g_ss.s, g_ss.fork, 0);
    conv4_k<<<dim3(8192, 1, 4), 256, 0, g_ss.s>>>(
        m1_w1, m1_w2, m2_w1, m2_w2, p_w1a, p_w2a, p_w1b, p_w2b, SZ_W);
    cudaEventRecord(g_ss.join, g_ss.s);

    bqkv_k<<<6, 256>>>(bq, bk, bv, out_loss);
    convpe_k<<<(NPDP * ND / 4 + 255) / 256, 256>>>(pe_w);
    conv4_k<<<dim3(256, 1, 4), 256>>>(
        wq, wk, wv, wo,
        p_wqkv16, p_wqkv16 + 2 * SZ_DD, p_wqkv16 + 4 * SZ_DD, p_wo16, SZ_DD);

    patch_k<<<(int)((SZ_P + 255) / 256), 256>>>(x);
    mm_k<M_PE><<<dim3(4, 64), 256>>>(p_p16, p_pew16, pe_b, pos, p_e);

    ln_k<false><<<NTOK, 128>>>(p_e, ln1_g, ln1_b, p_ln16, nullptr, nullptr);
    mm_k<M_QKV><<<dim3(4, 64, 3), 256>>>(p_ln16, p_wqkv16, p_bqkv, nullptr, p_qkv16);
    mm_k<M_SC><<<dim3(4, 2, 256), 256>>>(p_qkv16, p_qkv16 + 2 * SZ_LN,
                                         nullptr, nullptr, p_attn);
    softmax_attn_k<<<8192, 256>>>();

    // attn_w depends only on softmax output -> off the critical path
    cudaEventRecord(g_ss.attnev, 0);
    cudaStreamWaitEvent(g_ss.s, g_ss.attnev, 0);
    attnw_k<<<NTOK, 256, 0, g_ss.s>>>(out_attnw);

    mm_k<M_AV><<<dim3(1, 2, 256), 256>>>(p_attn16, p_qkv16 + 4 * SZ_LN,
                                         nullptr, nullptr, p_ctx16);
    mm_k<M_PROJ><<<dim3(4, 64), 256>>>(p_ctx16, p_wo16, bo, p_e, p_e);

    // MoE layer 1 (router fused into LN)
    ln_k<true><<<NTOK, 128>>>(p_e, ln2_g, ln2_b, p_ln16, m1_rw, m1_rb);
    dispatch_k<<<32, 256>>>();
    cudaStreamWaitEvent(0, g_ss.join, 0);
    mm_k<M_FF1><<<dim3(16, 64, 8), 256>>>(p_ln16, p_w1a, m1_b1, nullptr, p_h16);
    mm_k<M_FF2><<<dim3(4, 64, 8), 256>>>(p_h16, p_w2a, m1_b2, nullptr, p_contrib);
    combine_k<<<NTOK, 128>>>(p_o1);
    loss_k<<<1, 32>>>(out_loss);

    // MoE layer 2
    ln_k<true><<<NTOK, 128>>>(p_o1, ln3_g, ln3_b, p_ln16, m2_rw, m2_rb);
    dispatch_k<<<32, 256>>>();
    mm_k<M_FF1><<<dim3(16, 64, 8), 256>>>(p_ln16, p_w1b, m2_b1, nullptr, p_h16);
    mm_k<M_FF2><<<dim3(4, 64, 8), 256>>>(p_h16, p_w2b, m2_b2, nullptr, p_contrib);
    combine_k<<<NTOK, 128>>>(p_o2);
    loss_k<<<1, 32>>>(out_loss);

    fv1_k<<<dim3(NB, 8), 512>>>(p_contrib);
    fv2_k<<<NB, 512>>>(p_contrib, out_fv);
    logits_k<<<NB, 512>>>(cls_w, cls_b, out_logits);

    // main stream must not signal completion before side-stream attnw is done
    cudaEventRecord(g_ss.join, g_ss.s);
    cudaStreamWaitEvent(0, g_ss.join, 0);
}

// round 10
// speedup vs baseline: 1.1361x; 1.0011x over previous
#include <cuda_runtime.h>
#include <cuda_fp16.h>
#include <math.h>
#include <stdint.h>

#define NB   32
#define NS   256
#define ND   512
#define NH   8
#define NE   8
#define NHID 2048
#define NPD  588
#define NPDP 608
#define NTOK 8192
#define NA   16384

#define SZ_LN   ((size_t)NTOK * ND)
#define SZ_P    ((size_t)NTOK * NPDP)
#define SZ_ATTN ((size_t)NB * NH * NS * NS)
#define SZ_H    ((size_t)NA * NHID)
#define SZ_W    ((size_t)NE * ND * NHID)
#define SZ_DD   ((size_t)ND * ND)

// ---------------- fp32 scratch -------------------------------------------------
__device__ float g_e[NTOK * ND];
__device__ float g_attn[NB * NH * NS * NS];
__device__ float g_probs[NTOK * NE];
__device__ float g_gate[NA];
__device__ int   g_perm[NE * NA];
__device__ int   g_cnt[NE];
__device__ float g_imp[NE];
__device__ float g_contrib[NA * ND];
__device__ float g_part[NB * 8 * ND];
__device__ float g_fv[NB * ND];
__device__ float g_bqkv[3 * ND];

// ---------------- split fp16 buffers (hi at [0], lo at [SIZE] per segment) -----
__device__ __half g_p16[2 * SZ_P];
__device__ __half g_ln16[2 * SZ_LN];
__device__ __half g_qkv16[6 * SZ_LN];
__device__ __half g_attn16[2 * SZ_ATTN];
__device__ __half g_ctx16[2 * SZ_LN];
__device__ __half g_h16[2 * SZ_H];
__device__ __half g_pew16[2 * NPDP * ND];
__device__ __half g_wqkv16[6 * SZ_DD];
__device__ __half g_wo16[2 * SZ_DD];
__device__ __half g_w1a16[2 * SZ_W];
__device__ __half g_w2a16[2 * SZ_W];
__device__ __half g_w1b16[2 * SZ_W];
__device__ __half g_w2b16[2 * SZ_W];

// ---------------- persistent side stream ---------------------------------------
struct SideStream {
    cudaStream_t s;
    cudaEvent_t fork, join;
    SideStream() {
        cudaStreamCreateWithFlags(&s, cudaStreamNonBlocking);
        cudaEventCreateWithFlags(&fork, cudaEventDisableTiming);
        cudaEventCreateWithFlags(&join, cudaEventDisableTiming);
    }
};
static SideStream g_ss;

__device__ __forceinline__ float gelu_exact(float v) {
    return 0.5f * v * (1.0f + erff(v * 0.70710678118654752440f));
}
__device__ __forceinline__ void split2(float v0, float v1, __half* oh, __half* ol) {
    __half h0 = __float2half_rn(v0), h1 = __float2half_rn(v1);
    *(__half2*)oh = __halves2half2(h0, h1);
    *(__half2*)ol = __halves2half2(__float2half_rn(v0 - __half2float(h0)),
                                   __float2half_rn(v1 - __half2float(h1)));
}

// ---------------- mma.sync helpers ----------------------------------------------
__device__ __forceinline__ void ldsm4(unsigned* r, unsigned addr) {
    asm volatile("ldmatrix.sync.aligned.m8n8.x4.shared.b16 {%0,%1,%2,%3}, [%4];\n"
        : "=r"(r[0]), "=r"(r[1]), "=r"(r[2]), "=r"(r[3]) : "r"(addr));
}
__device__ __forceinline__ void ldsm4t(unsigned* r, unsigned addr) {
    asm volatile("ldmatrix.sync.aligned.m8n8.x4.trans.shared.b16 {%0,%1,%2,%3}, [%4];\n"
        : "=r"(r[0]), "=r"(r[1]), "=r"(r[2]), "=r"(r[3]) : "r"(addr));
}
__device__ __forceinline__ void mma16816(float* c, const unsigned* a, const unsigned* b) {
    asm volatile("mma.sync.aligned.m16n8k16.row.col.f32.f16.f16.f32 "
        "{%0,%1,%2,%3}, {%4,%5,%6,%7}, {%8,%9}, {%0,%1,%2,%3};\n"
        : "+f"(c[0]), "+f"(c[1]), "+f"(c[2]), "+f"(c[3])
        : "r"(a[0]), "r"(a[1]), "r"(a[2]), "r"(a[3]), "r"(b[0]), "r"(b[1]));
}
__device__ __forceinline__ void cpa16(unsigned dst, const void* src, bool p) {
    int sz = p ? 16 : 0;
    asm volatile("cp.async.cg.shared.global [%0], [%1], 16, %2;\n"
        :: "r"(dst), "l"(src), "r"(sz));
}

// ---------------- modes --------------------------------------------------------
#define M_PE   0
#define M_QKV  1
#define M_PROJ 2
#define M_SC   3
#define M_AV   4
#define M_FF1  5
#define M_FF2  6

template <int MODE>
__global__ __launch_bounds__(256) void mm_k(
    const __half* __restrict__ Ag, const __half* __restrict__ Bg,
    const float* __restrict__ bias, const float* __restrict__ extra,
    void* __restrict__ Og)
{
    constexpr int K   = (MODE == M_PE) ? NPDP : (MODE == M_SC) ? 64 :
                        (MODE == M_AV) ? 256 : (MODE == M_FF2) ? 2048 : 512;
    constexpr int LDA = K;
    constexpr int LDB = (MODE == M_SC || MODE == M_AV) ? 64 :
                        (MODE == M_FF1) ? 2048 : 512;
    constexpr bool NT = (MODE == M_SC);
    constexpr bool GATHER = (MODE == M_FF1) || (MODE == M_FF2);
    constexpr int SHIFT = (MODE == M_FF1) ? 1 : 0;
    constexpr int BN = (MODE == M_AV || MODE == M_SC) ? 64 : 128;
    constexpr int WN = BN / 4;
    constexpr int NF = WN / 8;
    constexpr int KT = K / 16;
    constexpr size_t ALO =
        (MODE == M_PE)  ? SZ_P :
        (MODE == M_SC || MODE == M_QKV || MODE == M_PROJ || MODE == M_FF1) ? SZ_LN :
        (MODE == M_AV)  ? SZ_ATTN : SZ_H;
    constexpr size_t BLO =
        (MODE == M_PE)  ? (size_t)NPDP * ND :
        (MODE == M_QKV || MODE == M_PROJ) ? SZ_DD :
        (MODE == M_SC || MODE == M_AV) ? SZ_LN : SZ_W;
    constexpr size_t OLO =
        (MODE == M_QKV || MODE == M_AV) ? SZ_LN : SZ_H;
    constexpr int AST = 128 * 24;
    constexpr int BST = NT ? BN * 24 : 16 * BN;

    __shared__ __align__(16) __half As[2][2][AST];
    __shared__ __align__(16) __half Bs[2][2][BST];
    __shared__ int s_idx[128];

    int tid = threadIdx.x;
    int bz = blockIdx.z;
    int row0 = blockIdx.y * 128, col0 = blockIdx.x * BN;

    const __half* Ah = Ag;
    const __half* Bh = Bg;
    if (MODE == M_SC)  { Ah += (size_t)bz * 256 * 64; Bh += (size_t)bz * 256 * 64; }
    if (MODE == M_AV)  { Ah += (size_t)bz * 65536;    Bh += (size_t)bz * 256 * 64; }
    if (MODE == M_QKV) { Bh += (size_t)bz * 2 * SZ_DD; }
    if (MODE == M_FF1) { Bh += (size_t)bz * 512 * 2048; }
    if (MODE == M_FF2) { Bh += (size_t)bz * 2048 * 512; }
    const __half* Al = Ah + ALO;
    const __half* Bl = Bh + BLO;

    if (GATHER) {
        int cnt = g_cnt[bz];
        if (row0 >= cnt) return;
        if (tid < 128) {
            int r = row0 + tid;
            s_idx[tid] = (r < cnt) ? g_perm[bz * NA + r] : -1;
        }
        __syncthreads();
    }

    int a_row = tid >> 1, a_ch = tid & 1;
    unsigned a_dst = (unsigned)((a_row * 24 + a_ch * 8) * 2);
    const __half* a_srch; const __half* a_srcl; bool a_pred;
    if (GATHER) {
        int a = s_idx[a_row];
        a_pred = (a >= 0);
        size_t off = a_pred ? (size_t)(a >> SHIFT) * LDA + a_ch * 8 : 0;
        a_srch = Ah + off; a_srcl = Al + off;
    } else {
        a_pred = true;
        size_t off = (size_t)(row0 + a_row) * LDA + a_ch * 8;
        a_srch = Ah + off; a_srcl = Al + off;
    }
    unsigned b_dst = 0; const __half* b_srch = Bh; const __half* b_srcl = Bh;
    bool b_val;
    if (!NT) {
        b_val = tid < (16 * BN / 8);
        int row = tid / (BN / 8), cn = tid % (BN / 8);
        int sw = cn ^ (row & 7);
        b_dst = (unsigned)((row * BN + sw * 8) * 2);
        size_t off = (size_t)row * LDB + col0 + cn * 8;
        b_srch = Bh + off; b_srcl = Bl + off;
    } else {
        b_val = tid < (BN * 2);
        int nr = tid >> 1, ch = tid & 1;
        b_dst = (unsigned)((nr * 24 + ch * 8) * 2);
        size_t off = (size_t)(col0 + nr) * LDB + ch * 8;
        b_srch = Bh + off; b_srcl = Bl + off;
    }

    unsigned as_base = (unsigned)__cvta_generic_to_shared(&As[0][0][0]);
    unsigned bs_base = (unsigned)__cvta_generic_to_shared(&Bs[0][0][0]);

    auto issue = [&](int kt, int buf) {
        unsigned abh = as_base + (buf * 2 + 0) * AST * 2;
        unsigned abl = as_base + (buf * 2 + 1) * AST * 2;
        cpa16(abh + a_dst, a_srch + (size_t)kt * 16, a_pred);
        cpa16(abl + a_dst, a_srcl + (size_t)kt * 16, a_pred);
        if (b_val) {
            unsigned bbh = bs_base + (buf * 2 + 0) * BST * 2;
            unsigned bbl = bs_base + (buf * 2 + 1) * BST * 2;
            size_t off = NT ? (size_t)kt * 16 : (size_t)kt * 16 * LDB;
            cpa16(bbh + b_dst, b_srch + off, true);
            cpa16(bbl + b_dst, b_srcl + off, true);
        }
        asm volatile("cp.async.commit_group;\n");
    };

    int lane = tid & 31;
    int warp = tid >> 5;
    int wm = warp >> 2, wn = warp & 3;

    float acc[4][NF][4];
#pragma unroll
    for (int i = 0; i < 4; i++)
#pragma unroll
        for (int j = 0; j < NF; j++)
#pragma unroll
            for (int t = 0; t < 4; t++) acc[i][j][t] = 0.f;

    issue(0, 0);
#pragma unroll 1
    for (int kt = 0; kt < KT; kt++) {
        int buf = kt & 1;
        if (kt + 1 < KT) {
            issue(kt + 1, buf ^ 1);
            asm volatile("cp.async.wait_group 1;\n");
        } else {
            asm volatile("cp.async.wait_group 0;\n");
        }
        __syncthreads();
        unsigned abh = as_base + (buf * 2 + 0) * AST * 2;
        unsigned abl = as_base + (buf * 2 + 1) * AST * 2;
        unsigned bbh = bs_base + (buf * 2 + 0) * BST * 2;
        unsigned bbl = bs_base + (buf * 2 + 1) * BST * 2;

        unsigned ah[4][4], al[4][4];
#pragma unroll
        for (int i = 0; i < 4; i++) {
            int m = wm * 64 + i * 16 + (lane & 15);
            int ch = lane >> 4;
            unsigned ad = (unsigned)((m * 24 + ch * 8) * 2);
            ldsm4(ah[i], abh + ad);
            ldsm4(al[i], abl + ad);
        }
        unsigned brh[2 * NF], brl[2 * NF];
#pragma unroll
        for (int jj = 0; jj < NF / 2; jj++) {
            int n0 = wn * WN + jj * 16;
            if (!NT) {
                int k = lane & 15;
                int cn = (n0 >> 3) + (lane >> 4);
                int sw = cn ^ (k & 7);
                unsigned bd = (unsigned)((k * BN + sw * 8) * 2);
                ldsm4t(&brh[jj * 4], bbh + bd);
                ldsm4t(&brl[jj * 4], bbl + bd);
            } else {
                int n = n0 + ((lane >> 4) << 3) + (lane & 7);
                int ch = (lane >> 3) & 1;
                unsigned bd = (unsigned)((n * 24 + ch * 8) * 2);
                ldsm4(&brh[jj * 4], bbh + bd);
                ldsm4(&brl[jj * 4], bbl + bd);
            }
        }
#pragma unroll
        for (int i = 0; i < 4; i++)
#pragma unroll
            for (int j = 0; j < NF; j++) {
                mma16816(acc[i][j], ah[i], &brh[j * 2]);
                mma16816(acc[i][j], al[i], &brh[j * 2]);
                mma16816(acc[i][j], ah[i], &brl[j * 2]);
            }
        __syncthreads();
    }

    int rl = lane >> 2, cp2 = (lane & 3) * 2;
#pragma unroll
    for (int i = 0; i < 4; i++) {
#pragma unroll
        for (int hh = 0; hh < 2; hh++) {
            int rr = wm * 64 + i * 16 + rl + hh * 8;
            int r = row0 + rr;
            int aidx = 0;
            if (GATHER) {
                aidx = s_idx[rr];
                if (aidx < 0) continue;
            }
#pragma unroll
            for (int j = 0; j < NF; j++) {
                int c = col0 + wn * WN + j * 8 + cp2;
                float v0 = acc[i][j][hh * 2 + 0];
                float v1 = acc[i][j][hh * 2 + 1];
                if (MODE == M_PE) {
                    float* O = (float*)Og;
                    v0 += bias[c]     + extra[(size_t)(r & 255) * 512 + c];
                    v1 += bias[c + 1] + extra[(size_t)(r & 255) * 512 + c + 1];
                    O[(size_t)r * 512 + c] = v0;
                    O[(size_t)r * 512 + c + 1] = v1;
                } else if (MODE == M_QKV) {
                    __half* O = (__half*)Og + (size_t)bz * 2 * SZ_LN;
                    const float* bi = bias + bz * 512;
                    v0 += bi[c]; v1 += bi[c + 1];
                    int b = r >> 8, s = r & 255, hd = c >> 6, ii = c & 63;
                    size_t o = (size_t)(((b << 3) + hd) * 256 + s) * 64 + ii;
                    split2(v0, v1, O + o, O + OLO + o);
                } else if (MODE == M_PROJ) {
                    float* O = (float*)Og;
                    v0 += bias[c]     + extra[(size_t)r * 512 + c];
                    v1 += bias[c + 1] + extra[(size_t)r * 512 + c + 1];
                    O[(size_t)r * 512 + c] = v0;
                    O[(size_t)r * 512 + c + 1] = v1;
                } else if (MODE == M_SC) {
                    float* O = (float*)Og + (size_t)bz * 65536;
                    O[(size_t)r * 256 + c] = v0 * 0.125f;
                    O[(size_t)r * 256 + c + 1] = v1 * 0.125f;
                } else if (MODE == M_AV) {
                    __half* O = (__half*)Og;
                    int b = bz >> 3, hd = bz & 7;
                    size_t o = (size_t)((b << 8) + r) * 512 + (hd << 6) + c;
                    split2(v0, v1, O + o, O + OLO + o);
                } else if (MODE == M_FF1) {
                    __half* O = (__half*)Og;
                    const float* bi = bias + bz * 2048;
                    v0 = gelu_exact(v0 + bi[c]);
                    v1 = gelu_exact(v1 + bi[c + 1]);
                    size_t o = (size_t)aidx * 2048 + c;
                    split2(v0, v1, O + o, O + OLO + o);
                } else {
                    float* O = (float*)Og;
                    const float* bi = bias + bz * 512;
                    O[(size_t)aidx * 512 + c] = v0 + bi[c];
                    O[(size_t)aidx * 512 + c + 1] = v1 + bi[c + 1];
                }
            }
        }
    }
}

// ---------------- conversions ---------------------------------------------------
struct __align__(8) h2x2 { __half2 a, b; };

__device__ __forceinline__ void conv_elem4(const float* in, __half* outh, size_t n,
                                           size_t i) {
    float4 f = *(const float4*)(in + i);
    h2x2 H, L;
    H.a = __floats2half2_rn(f.x, f.y);
    H.b = __floats2half2_rn(f.z, f.w);
    float2 f0 = __half22float2(H.a), f1 = __half22float2(H.b);
    L.a = __floats2half2_rn(f.x - f0.x, f.y - f0.y);
    L.b = __floats2half2_rn(f.z - f1.x, f.w - f1.y);
    *(h2x2*)(outh + i) = H;
    *(h2x2*)(outh + n + i) = L;
}

__global__ __launch_bounds__(256) void conv4_k(
    const float* __restrict__ s0, const float* __restrict__ s1,
    const float* __restrict__ s2, const float* __restrict__ s3,
    __half* __restrict__ d0, __half* __restrict__ d1,
    __half* __restrict__ d2, __half* __restrict__ d3, size_t n)
{
    const float* src = (blockIdx.z == 0) ? s0 : (blockIdx.z == 1) ? s1 :
                       (blockIdx.z == 2) ? s2 : s3;
    __half* dst = (blockIdx.z == 0) ? d0 : (blockIdx.z == 1) ? d1 :
                  (blockIdx.z == 2) ? d2 : d3;
    size_t i = ((size_t)blockIdx.x * 256 + threadIdx.x) * 4;
    if (i < n) conv_elem4(src, dst, n, i);
}

__global__ __launch_bounds__(256) void convpe_k(const float* __restrict__ w) {
    int i = (blockIdx.x * 256 + threadIdx.x) * 4;
    if (i >= NPDP * ND) return;
    int j = i >> 9;
    float4 f = make_float4(0.f, 0.f, 0.f, 0.f);
    if (j < NPD) f = *(const float4*)(w + i);
    h2x2 H, L;
    H.a = __floats2half2_rn(f.x, f.y);
    H.b = __floats2half2_rn(f.z, f.w);
    float2 f0 = __half22float2(H.a), f1 = __half22float2(H.b);
    L.a = __floats2half2_rn(f.x - f0.x, f.y - f0.y);
    L.b = __floats2half2_rn(f.z - f1.x, f.w - f1.y);
    *(h2x2*)(g_pew16 + i) = H;
    *(h2x2*)(g_pew16 + NPDP * ND + i) = L;
}

// bqkv gather + global init (counters, loss)
__global__ void bqkv_k(const float* __restrict__ bq, const float* __restrict__ bk,
                       const float* __restrict__ bv, float* out_loss) {
    int i = blockIdx.x * 256 + threadIdx.x;
    if (blockIdx.x == 0 && threadIdx.x < 8) { g_cnt[threadIdx.x] = 0; g_imp[threadIdx.x] = 0.f; }
    if (i == 0) out_loss[0] = 0.f;
    if (i >= 1536) return;
    g_bqkv[i] = (i < 512) ? bq[i] : (i < 1024) ? bk[i - 512] : bv[i - 1024];
}

// ---------------- patch gather --------------------------------------------------
__global__ void patch_k(const float* __restrict__ x) {
    size_t idx = (size_t)blockIdx.x * 256 + threadIdx.x;
    if (idx >= SZ_P) return;
    int j = (int)(idx % NPDP);
    int rs = (int)(idx / NPDP);
    float f = 0.f;
    if (j < NPD) {
        int b = rs >> 8, s = rs & 255;
        int hi = s >> 4, wi = s & 15;
        int c = j % 3;
        int pp = j / 3;
        int p1 = pp / 14, p2 = pp % 14;
        f = x[(((size_t)(b * 3 + c)) * 224 + hi * 14 + p1) * 224 + wi * 14 + p2];
    }
    __half h = __float2half_rn(f);
    g_p16[idx] = h;
    g_p16[SZ_P + idx] = __float2half_rn(f - __half2float(h));
}

// ---------------- shared LN+router body -----------------------------------------
template <bool ROUTER>
__device__ __forceinline__ void ln_body(
    int row, int tid, float4 v,
    const float* __restrict__ gw, const float* __restrict__ bw,
    __half* __restrict__ out16,
    const float* __restrict__ rw, const float* __restrict__ rb)
{
    float s = v.x + v.y + v.z + v.w;
    float q = v.x * v.x + v.y * v.y + v.z * v.z + v.w * v.w;
    __shared__ float ss[4], sq[4];
    for (int o = 16; o > 0; o >>= 1) {
        s += __shfl_xor_sync(0xffffffffu, s, o);
        q += __shfl_xor_sync(0xffffffffu, q, o);
    }
    if ((tid & 31) == 0) { ss[tid >> 5] = s; sq[tid >> 5] = q; }
    __syncthreads();
    s = ss[0] + ss[1] + ss[2] + ss[3];
    q = sq[0] + sq[1] + sq[2] + sq[3];
    float mean = s * (1.f / 512.f);
    float var  = q * (1.f / 512.f) - mean * mean;
    float inv  = rsqrtf(var + 1e-5f);
    float4 g4 = ((const float4*)gw)[tid];
    float4 b4 = ((const float4*)bw)[tid];
    float4 o;
    o.x = (v.x - mean) * inv * g4.x + b4.x;
    o.y = (v.y - mean) * inv * g4.y + b4.y;
    o.z = (v.z - mean) * inv * g4.z + b4.z;
    o.w = (v.w - mean) * inv * g4.w + b4.w;
    size_t base = (size_t)row * 512 + tid * 4;
    split2(o.x, o.y, out16 + base,     out16 + SZ_LN + base);
    split2(o.z, o.w, out16 + base + 2, out16 + SZ_LN + base + 2);

    if (ROUTER) {
        int k0 = tid * 4;
        float acc[8];
        const float4* r0 = (const float4*)(rw + (size_t)(k0 + 0) * 8);
        const float4* r1 = (const float4*)(rw + (size_t)(k0 + 1) * 8);
        const float4* r2 = (const float4*)(rw + (size_t)(k0 + 2) * 8);
        const float4* r3 = (const float4*)(rw + (size_t)(k0 + 3) * 8);
        float4 w0a = r0[0], w0b = r0[1];
        float4 w1a = r1[0], w1b = r1[1];
        float4 w2a = r2[0], w2b = r2[1];
        float4 w3a = r3[0], w3b = r3[1];
        acc[0] = o.x * w0a.x + o.y * w1a.x + o.z * w2a.x + o.w * w3a.x;
        acc[1] = o.x * w0a.y + o.y * w1a.y + o.z * w2a.y + o.w * w3a.y;
        acc[2] = o.x * w0a.z + o.y * w1a.z + o.z * w2a.z + o.w * w3a.z;
        acc[3] = o.x * w0a.w + o.y * w1a.w + o.z * w2a.w + o.w * w3a.w;
        acc[4] = o.x * w0b.x + o.y * w1b.x + o.z * w2b.x + o.w * w3b.x;
        acc[5] = o.x * w0b.y + o.y * w1b.y + o.z * w2b.y + o.w * w3b.y;
        acc[6] = o.x * w0b.z + o.y * w1b.z + o.z * w2b.z + o.w * w3b.z;
        acc[7] = o.x * w0b.w + o.y * w1b.w + o.z * w2b.w + o.w * w3b.w;
#pragma unroll
        for (int e = 0; e < 8; e++)
            for (int of = 16; of > 0; of >>= 1)
                acc[e] += __shfl_xor_sync(0xffffffffu, acc[e], of);
        __shared__ float sred[4][8];
        if ((tid & 31) == 0)
#pragma unroll
            for (int e = 0; e < 8; e++) sred[tid >> 5][e] = acc[e];
        __syncthreads();
        if (tid == 0) {
            float l[8]; float mx = -1e30f;
#pragma unroll
            for (int e = 0; e < 8; e++) {
                l[e] = sred[0][e] + sred[1][e] + sred[2][e] + sred[3][e] + rb[e];
                mx = fmaxf(mx, l[e]);
            }
            float sum = 0.f;
#pragma unroll
            for (int e = 0; e < 8; e++) { l[e] = __expf(l[e] - mx); sum += l[e]; }
            float is = 1.f / sum;
#pragma unroll
            for (int e = 0; e < 8; e++) g_probs[row * 8 + e] = l[e] * is;
        }
    }
}

// LayerNorm from fp32 input (+ optional fused router)
template <bool ROUTER>
__global__ __launch_bounds__(128) void ln_k(
    const float* __restrict__ in, const float* __restrict__ gw,
    const float* __restrict__ bw, __half* __restrict__ out16,
    const float* __restrict__ rw, const float* __restrict__ rb)
{
    int row = blockIdx.x, tid = threadIdx.x;
    float4 v = ((const float4*)(in + (size_t)row * 512))[tid];
    ln_body<ROUTER>(row, tid, v, gw, bw, out16, rw, rb);
}

// combine (top-2 MoE outputs) fused with LN (+ router) — o1 never materialized
__global__ __launch_bounds__(128) void cln_k(
    const float* __restrict__ gw, const float* __restrict__ bw,
    __half* __restrict__ out16,
    const float* __restrict__ rw, const float* __restrict__ rb)
{
    int row = blockIdx.x, tid = threadIdx.x;
    float g1 = g_gate[2 * row], g2 = g_gate[2 * row + 1];
    float4 a = ((const float4*)(g_contrib + (size_t)(2 * row) * 512))[tid];
    float4 b = ((const float4*)(g_contrib + (size_t)(2 * row + 1) * 512))[tid];
    float4 v;
    v.x = g1 * a.x + g2 * b.x; v.y = g1 * a.y + g2 * b.y;
    v.z = g1 * a.z + g2 * b.z; v.w = g1 * a.w + g2 * b.w;
    ln_body<true>(row, tid, v, gw, bw, out16, rw, rb);
}

// layer-2 combine fused into fv partial sum — o2 never materialized
__global__ __launch_bounds__(512) void fvc_k(float* __restrict__ part) {
    int b = blockIdx.x, seg = blockIdx.y, d = threadIdx.x;
    int t0 = b * 256 + seg * 32;
    float s = 0.f;
    for (int ss = 0; ss < 32; ss++) {
        int t = t0 + ss;
        float g1 = g_gate[2 * t], g2 = g_gate[2 * t + 1];
        s += g1 * g_contrib[(size_t)(2 * t) * 512 + d]
           + g2 * g_contrib[(size_t)(2 * t + 1) * 512 + d];
    }
    part[(size_t)(b * 8 + seg) * 512 + d] = s;
}

// ---------------- softmax over attn rows ----------------------------------------
__global__ __launch_bounds__(256) void softmax_attn_k() {
    int row  = (blockIdx.x << 3) + (threadIdx.x >> 5);
    int lane = threadIdx.x & 31;
    const float4* p = (const float4*)(g_attn + (size_t)row * 256);
    float4 a = p[lane], b = p[lane + 32];
    float m = fmaxf(fmaxf(fmaxf(a.x, a.y), fmaxf(a.z, a.w)),
                    fmaxf(fmaxf(b.x, b.y), fmaxf(b.z, b.w)));
    for (int o = 16; o > 0; o >>= 1) m = fmaxf(m, __shfl_xor_sync(0xffffffffu, m, o));
    a.x = __expf(a.x - m); a.y = __expf(a.y - m);
    a.z = __expf(a.z - m); a.w = __expf(a.w - m);
    b.x = __expf(b.x - m); b.y = __expf(b.y - m);
    b.z = __expf(b.z - m); b.w = __expf(b.w - m);
    float s = a.x + a.y + a.z + a.w + b.x + b.y + b.z + b.w;
    for (int o = 16; o > 0; o >>= 1) s += __shfl_xor_sync(0xffffffffu, s, o);
    float inv = 1.f / s;
    a.x *= inv; a.y *= inv; a.z *= inv; a.w *= inv;
    b.x *= inv; b.y *= inv; b.z *= inv; b.w *= inv;
    size_t base = (size_t)row * 256;
    split2(a.x, a.y, g_attn16 + base + lane * 4,     g_attn16 + SZ_ATTN + base + lane * 4);
    split2(a.z, a.w, g_attn16 + base + lane * 4 + 2, g_attn16 + SZ_ATTN + base + lane * 4 + 2);
    split2(b.x, b.y, g_attn16 + base + 128 + lane * 4,     g_attn16 + SZ_ATTN + base + 128 + lane * 4);
    split2(b.z, b.w, g_attn16 + base + 128 + lane * 4 + 2, g_attn16 + SZ_ATTN + base + 128 + lane * 4 + 2);
}

// ---------------- attn_w --------------------------------------------------------
__global__ __launch_bounds__(256) void attnw_k(float* __restrict__ out) {
    int bq = blockIdx.x, tid = threadIdx.x;
    int b = bq >> 8, qr = bq & 255;
    float s = 0.f;
#pragma unroll
    for (int h = 0; h < 8; h++) {
        size_t off = ((size_t)((b << 3) + h)) * 65536 + (qr << 8) + tid;
        s += __half2float(g_attn16[off]) + __half2float(g_attn16[SZ_ATTN + off]);
    }
    s *= 0.125f;
    __shared__ float red[8];
    float m = s;
    for (int o = 16; o > 0; o >>= 1) m = fmaxf(m, __shfl_xor_sync(0xffffffffu, m, o));
    if ((tid & 31) == 0) red[tid >> 5] = m;
    __syncthreads();
    m = red[0];
#pragma unroll
    for (int w = 1; w < 8; w++) m = fmaxf(m, red[w]);
    float ex = __expf(s - m);
    float sum = ex;
    __syncthreads();
    for (int o = 16; o > 0; o >>= 1) sum += __shfl_xor_sync(0xffffffffu, sum, o);
    if ((tid & 31) == 0) red[tid >> 5] = sum;
    __syncthreads();
    sum = red[0] + red[1] + red[2] + red[3] + red[4] + red[5] + red[6] + red[7];
    out[(size_t)bq * 256 + tid] = ex / sum;
}

// ---------------- dispatch / loss -----------------------------------------------
__global__ __launch_bounds__(256) void dispatch_k() {
    __shared__ int   s_cnt[8];
    __shared__ float s_imp[8];
    __shared__ int   s_base[8];
    int tid = threadIdx.x;
    if (tid < 8) { s_cnt[tid] = 0; s_imp[tid] = 0.f; }
    __syncthreads();
    int t = blockIdx.x * 256 + tid;
    float p[8];
#pragma unroll
    for (int e = 0; e < 8; e++) { p[e] = g_probs[t * 8 + e]; atomicAdd(&s_imp[e], p[e]); }
    int e1 = 0; float v1 = p[0];
#pragma unroll
    for (int e = 1; e < 8; e++) if (p[e] > v1) { v1 = p[e]; e1 = e; }
    int e2 = -1; float v2 = -1e30f;
#pragma unroll
    for (int e = 0; e < 8; e++) if (e != e1 && p[e] > v2) { v2 = p[e]; e2 = e; }
    int lp1 = atomicAdd(&s_cnt[e1], 1);
    int lp2 = atomicAdd(&s_cnt[e2], 1);
    __syncthreads();
    if (tid < 8) {
        s_base[tid] = atomicAdd(&g_cnt[tid], s_cnt[tid]);
        atomicAdd(&g_imp[tid], s_imp[tid]);
    }
    __syncthreads();
    g_perm[e1 * NA + s_base[e1] + lp1] = t * 2;
    g_perm[e2 * NA + s_base[e2] + lp2] = t * 2 + 1;
    g_gate[t * 2]     = v1;
    g_gate[t * 2 + 1] = v2;
}

__global__ void loss_k(float* out_loss) {
    int tid = threadIdx.x;
    float v = 0.f;
    if (tid < 8)
        v = 8.f * ((float)g_cnt[tid] * (1.f / 8192.f)) * (g_imp[tid] * (1.f / 8192.f));
    for (int o = 16; o > 0; o >>= 1) v += __shfl_xor_sync(0xffffffffu, v, o);
    if (tid == 0) out_loss[0] += v;
    if (tid < 8) { g_cnt[tid] = 0; g_imp[tid] = 0.f; }
}

// ---------------- fv + logits ---------------------------------------------------
__global__ __launch_bounds__(512) void fv2_k(const float* __restrict__ part,
                                             float* __restrict__ out_fv) {
    int b = blockIdx.x, d = threadIdx.x;
    float s = 0.f;
#pragma unroll
    for (int seg = 0; seg < 8; seg++)
        s += part[(size_t)(b * 8 + seg) * 512 + d];
    s *= (1.f / 256.f);
    g_fv[b * 512 + d] = s;
    out_fv[b * 512 + d] = s;
}
__global__ __launch_bounds__(512) void logits_k(const float* __restrict__ W,
                                                const float* __restrict__ bias,
                                                float* __restrict__ out) {
    __shared__ float sf[512];
    int b = blockIdx.x, n = threadIdx.x;
    sf[n] = g_fv[b * 512 + n];
    __syncthreads();
    float acc = 0.f;
    for (int k = 0; k < 512; k++) acc += sf[k] * W[k * 512 + n];
    out[b * 512 + n] = acc + bias[n];
}

// ---------------- host launch ---------------------------------------------------
extern "C" void kernel_launch(void* const* d_in, const int* in_sizes, int n_in,
                              void* d_out, int out_size) {
    const float* x     = (const float*)d_in[0];
    const float* pe_w  = (const float*)d_in[1];
    const float* pe_b  = (const float*)d_in[2];
    const float* pos   = (const float*)d_in[3];
    const float* ln1_g = (const float*)d_in[4];
    const float* ln1_b = (const float*)d_in[5];
    const float* ln2_g = (const float*)d_in[6];
    const float* ln2_b = (const float*)d_in[7];
    const float* ln3_g = (const float*)d_in[8];
    const float* ln3_b = (const float*)d_in[9];
    const float* wq = (const float*)d_in[10];
    const float* bq = (const float*)d_in[11];
    const float* wk = (const float*)d_in[12];
    const float* bk = (const float*)d_in[13];
    const float* wv = (const float*)d_in[14];
    const float* bv = (const float*)d_in[15];
    const float* wo = (const float*)d_in[16];
    const float* bo = (const float*)d_in[17];
    const float* m1_rw = (const float*)d_in[18];
    const float* m1_rb = (const float*)d_in[19];
    const float* m1_w1 = (const float*)d_in[20];
    const float* m1_b1 = (const float*)d_in[21];
    const float* m1_w2 = (const float*)d_in[22];
    const float* m1_b2 = (const float*)d_in[23];
    const float* m2_rw = (const float*)d_in[24];
    const float* m2_rb = (const float*)d_in[25];
    const float* m2_w1 = (const float*)d_in[26];
    const float* m2_b1 = (const float*)d_in[27];
    const float* m2_w2 = (const float*)d_in[28];
    const float* m2_b2 = (const float*)d_in[29];
    const float* cls_w = (const float*)d_in[30];
    const float* cls_b = (const float*)d_in[31];

    float* out = (float*)d_out;
    float* out_logits = out;
    float* out_fv     = out + 16384;
    float* out_loss   = out + 32768;
    float* out_attnw  = out + 32769;

    float *p_e, *p_attn, *p_contrib, *p_part;
    __half *p_p16, *p_ln16, *p_qkv16, *p_attn16, *p_ctx16, *p_h16;
    __half *p_pew16, *p_wqkv16, *p_wo16;
    __half *p_w1a, *p_w2a, *p_w1b, *p_w2b;
    cudaGetSymbolAddress((void**)&p_e,       g_e);
    cudaGetSymbolAddress((void**)&p_attn,    g_attn);
    cudaGetSymbolAddress((void**)&p_contrib, g_contrib);
    cudaGetSymbolAddress((void**)&p_part,    g_part);
    cudaGetSymbolAddress((void**)&p_p16,     g_p16);
    cudaGetSymbolAddress((void**)&p_ln16,    g_ln16);
    cudaGetSymbolAddress((void**)&p_qkv16,   g_qkv16);
    cudaGetSymbolAddress((void**)&p_attn16,  g_attn16);
    cudaGetSymbolAddress((void**)&p_ctx16,   g_ctx16);
    cudaGetSymbolAddress((void**)&p_h16,     g_h16);
    cudaGetSymbolAddress((void**)&p_pew16,   g_pew16);
    cudaGetSymbolAddress((void**)&p_wqkv16,  g_wqkv16);
    cudaGetSymbolAddress((void**)&p_wo16,    g_wo16);
    cudaGetSymbolAddress((void**)&p_w1a,     g_w1a16);
    cudaGetSymbolAddress((void**)&p_w2a,     g_w2a16);
    cudaGetSymbolAddress((void**)&p_w1b,     g_w1b16);
    cudaGetSymbolAddress((void**)&p_w2b,     g_w2b16);
    float* p_bqkv; cudaGetSymbolAddress((void**)&p_bqkv, g_bqkv);

    // fork: big MoE weight conversions on side stream (overlaps with attention)
    cudaEventRecord(g_ss.fork, 0);
    cudaStreamWaitEvent(g_ss.s, g_ss.fork, 0);
    conv4_k<<<dim3(8192, 1, 4), 256, 0, g_ss.s>>>(
        m1_w1, m1_w2, m2_w1, m2_w2, p_w1a, p_w2a, p_w1b, p_w2b, SZ_W);
    cudaEventRecord(g_ss.join, g_ss.s);

    bqkv_k<<<6, 256>>>(bq, bk, bv, out_loss);
    convpe_k<<<(NPDP * ND / 4 + 255) / 256, 256>>>(pe_w);
    conv4_k<<<dim3(256, 1, 4), 256>>>(
        wq, wk, wv, wo,
        p_wqkv16, p_wqkv16 + 2 * SZ_DD, p_wqkv16 + 4 * SZ_DD, p_wo16, SZ_DD);

    patch_k<<<(int)((SZ_P + 255) / 256), 256>>>(x);
    mm_k<M_PE><<<dim3(4, 64), 256>>>(p_p16, p_pew16, pe_b, pos, p_e);

    ln_k<false><<<NTOK, 128>>>(p_e, ln1_g, ln1_b, p_ln16, nullptr, nullptr);
    mm_k<M_QKV><<<dim3(4, 64, 3), 256>>>(p_ln16, p_wqkv16, p_bqkv, nullptr, p_qkv16);
    mm_k<M_SC><<<dim3(4, 2, 256), 256>>>(p_qkv16, p_qkv16 + 2 * SZ_LN,
                                         nullptr, nullptr, p_attn);
    softmax_attn_k<<<8192, 256>>>();
    mm_k<M_AV><<<dim3(1, 2, 256), 256>>>(p_attn16, p_qkv16 + 4 * SZ_LN,
                                         nullptr, nullptr, p_ctx16);
    mm_k<M_PROJ><<<dim3(4, 64), 256>>>(p_ctx16, p_wo16, bo, p_e, p_e);
    attnw_k<<<NTOK, 256>>>(out_attnw);

    // MoE layer 1 (router fused into LN2)
    ln_k<true><<<NTOK, 128>>>(p_e, ln2_g, ln2_b, p_ln16, m1_rw, m1_rb);
    dispatch_k<<<32, 256>>>();
    cudaStreamWaitEvent(0, g_ss.join, 0);
    mm_k<M_FF1><<<dim3(16, 64, 8), 256>>>(p_ln16, p_w1a, m1_b1, nullptr, p_h16);
    mm_k<M_FF2><<<dim3(4, 64, 8), 256>>>(p_h16, p_w2a, m1_b2, nullptr, p_contrib);

    // combine + LN3 + layer-2 router fused; o1 never materialized
    cln_k<<<NTOK, 128>>>(ln3_g, ln3_b, p_ln16, m2_rw, m2_rb);
    loss_k<<<1, 32>>>(out_loss);

    // MoE layer 2
    dispatch_k<<<32, 256>>>();
    mm_k<M_FF1><<<dim3(16, 64, 8), 256>>>(p_ln16, p_w1b, m2_b1, nullptr, p_h16);
    mm_k<M_FF2><<<dim3(4, 64, 8), 256>>>(p_h16, p_w2b, m2_b2, nullptr, p_contrib);

    // layer-2 combine fused into fv partials; o2 never materialized
    fvc_k<<<dim3(NB, 8), 512>>>(p_part);
    loss_k<<<1, 32>>>(out_loss);
    fv2_k<<<NB, 512>>>(p_part, out_fv);
    logits_k<<<NB, 512>>>(cls_w, cls_b, out_logits);
}

// round 11
// speedup vs baseline: 1.1632x; 1.0239x over previous
#include <cuda_runtime.h>
#include <cuda_fp16.h>
#include <math.h>
#include <stdint.h>

#define NB   32
#define NS   256
#define ND   512
#define NH   8
#define NE   8
#define NHID 2048
#define NPD  588
#define NPDP 608
#define NTOK 8192
#define NA   16384

#define SZ_LN   ((size_t)NTOK * ND)
#define SZ_P    ((size_t)NTOK * NPDP)
#define SZ_ATTN ((size_t)NB * NH * NS * NS)
#define SZ_H    ((size_t)NA * NHID)
#define SZ_W    ((size_t)NE * ND * NHID)
#define SZ_DD   ((size_t)ND * ND)

// ---------------- fp32 scratch -------------------------------------------------
__device__ float g_e[NTOK * ND];
__device__ float g_attn[NB * NH * NS * NS];
__device__ float g_probs[NTOK * NE];
__device__ float g_gate[NA];
__device__ int   g_perm[NE * NA];
__device__ int   g_cnt[NE];
__device__ float g_imp[NE];
__device__ float g_contrib[NA * ND];
__device__ float g_part[NB * 8 * ND];
__device__ float g_fv[NB * ND];
__device__ float g_bqkv[3 * ND];

// ---------------- split fp16 buffers (hi at [0], lo at [SIZE] per segment) -----
__device__ __half g_p16[2 * SZ_P];
__device__ __half g_ln16[2 * SZ_LN];
__device__ __half g_qkv16[6 * SZ_LN];
__device__ __half g_attn16[2 * SZ_ATTN];
__device__ __half g_ctx16[2 * SZ_LN];
__device__ __half g_h16[2 * SZ_H];
__device__ __half g_pew16[2 * NPDP * ND];
__device__ __half g_wqkv16[6 * SZ_DD];
__device__ __half g_wo16[2 * SZ_DD];
__device__ __half g_w1a16[2 * SZ_W];
__device__ __half g_w2a16[2 * SZ_W];
__device__ __half g_w1b16[2 * SZ_W];
__device__ __half g_w2b16[2 * SZ_W];

// ---------------- persistent side stream ---------------------------------------
struct SideStream {
    cudaStream_t s;
    cudaEvent_t fork, join;
    SideStream() {
        cudaStreamCreateWithFlags(&s, cudaStreamNonBlocking);
        cudaEventCreateWithFlags(&fork, cudaEventDisableTiming);
        cudaEventCreateWithFlags(&join, cudaEventDisableTiming);
    }
};
static SideStream g_ss;

__device__ __forceinline__ float gelu_exact(float v) {
    return 0.5f * v * (1.0f + erff(v * 0.70710678118654752440f));
}
__device__ __forceinline__ void split2(float v0, float v1, __half* oh, __half* ol) {
    __half h0 = __float2half_rn(v0), h1 = __float2half_rn(v1);
    *(__half2*)oh = __halves2half2(h0, h1);
    *(__half2*)ol = __halves2half2(__float2half_rn(v0 - __half2float(h0)),
                                   __float2half_rn(v1 - __half2float(h1)));
}

// ---------------- mma.sync helpers ----------------------------------------------
__device__ __forceinline__ void ldsm4(unsigned* r, unsigned addr) {
    asm volatile("ldmatrix.sync.aligned.m8n8.x4.shared.b16 {%0,%1,%2,%3}, [%4];\n"
        : "=r"(r[0]), "=r"(r[1]), "=r"(r[2]), "=r"(r[3]) : "r"(addr));
}
__device__ __forceinline__ void ldsm4t(unsigned* r, unsigned addr) {
    asm volatile("ldmatrix.sync.aligned.m8n8.x4.trans.shared.b16 {%0,%1,%2,%3}, [%4];\n"
        : "=r"(r[0]), "=r"(r[1]), "=r"(r[2]), "=r"(r[3]) : "r"(addr));
}
__device__ __forceinline__ void mma16816(float* c, const unsigned* a, const unsigned* b) {
    asm volatile("mma.sync.aligned.m16n8k16.row.col.f32.f16.f16.f32 "
        "{%0,%1,%2,%3}, {%4,%5,%6,%7}, {%8,%9}, {%0,%1,%2,%3};\n"
        : "+f"(c[0]), "+f"(c[1]), "+f"(c[2]), "+f"(c[3])
        : "r"(a[0]), "r"(a[1]), "r"(a[2]), "r"(a[3]), "r"(b[0]), "r"(b[1]));
}
__device__ __forceinline__ void cpa16(unsigned dst, const void* src, bool p) {
    int sz = p ? 16 : 0;
    asm volatile("cp.async.cg.shared.global [%0], [%1], 16, %2;\n"
        :: "r"(dst), "l"(src), "r"(sz));
}

// ---------------- modes --------------------------------------------------------
#define M_PE   0
#define M_QKV  1
#define M_PROJ 2
#define M_SC   3
#define M_AV   4
#define M_FF1  5
#define M_FF2  6

template <int MODE>
__global__ __launch_bounds__(256) void mm_k(
    const __half* __restrict__ Ag, const __half* __restrict__ Bg,
    const float* __restrict__ bias, const float* __restrict__ extra,
    void* __restrict__ Og)
{
    constexpr int K   = (MODE == M_PE) ? NPDP : (MODE == M_SC) ? 64 :
                        (MODE == M_AV) ? 256 : (MODE == M_FF2) ? 2048 : 512;
    constexpr int LDA = K;
    constexpr int LDB = (MODE == M_SC || MODE == M_AV) ? 64 :
                        (MODE == M_FF1) ? 2048 : 512;
    constexpr bool NT = (MODE == M_SC);
    constexpr bool GATHER = (MODE == M_FF1) || (MODE == M_FF2);
    constexpr int SHIFT = (MODE == M_FF1) ? 1 : 0;
    constexpr int BN = (MODE == M_AV || MODE == M_SC) ? 64 : 128;
    constexpr int WN = BN / 4;
    constexpr int NF = WN / 8;
    constexpr int KT = K / 16;
    constexpr size_t ALO =
        (MODE == M_PE)  ? SZ_P :
        (MODE == M_SC || MODE == M_QKV || MODE == M_PROJ || MODE == M_FF1) ? SZ_LN :
        (MODE == M_AV)  ? SZ_ATTN : SZ_H;
    constexpr size_t BLO =
        (MODE == M_PE)  ? (size_t)NPDP * ND :
        (MODE == M_QKV || MODE == M_PROJ) ? SZ_DD :
        (MODE == M_SC || MODE == M_AV) ? SZ_LN : SZ_W;
    constexpr size_t OLO =
        (MODE == M_QKV || MODE == M_AV) ? SZ_LN : SZ_H;
    constexpr int AST = 128 * 24;
    constexpr int BST = NT ? BN * 24 : 16 * BN;

    __shared__ __align__(16) __half As[2][2][AST];
    __shared__ __align__(16) __half Bs[2][2][BST];
    __shared__ int s_idx[128];

    int tid = threadIdx.x;
    int bz = blockIdx.z;
    int row0 = blockIdx.y * 128, col0 = blockIdx.x * BN;

    const __half* Ah = Ag;
    const __half* Bh = Bg;
    if (MODE == M_SC)  { Ah += (size_t)bz * 256 * 64; Bh += (size_t)bz * 256 * 64; }
    if (MODE == M_AV)  { Ah += (size_t)bz * 65536;    Bh += (size_t)bz * 256 * 64; }
    if (MODE == M_QKV) { Bh += (size_t)bz * 2 * SZ_DD; }
    if (MODE == M_FF1) { Bh += (size_t)bz * 512 * 2048; }
    if (MODE == M_FF2) { Bh += (size_t)bz * 2048 * 512; }
    const __half* Al = Ah + ALO;
    const __half* Bl = Bh + BLO;

    if (GATHER) {
        int cnt = g_cnt[bz];
        if (row0 >= cnt) return;
        if (tid < 128) {
            int r = row0 + tid;
            s_idx[tid] = (r < cnt) ? g_perm[bz * NA + r] : -1;
        }
        __syncthreads();
    }

    int a_row = tid >> 1, a_ch = tid & 1;
    unsigned a_dst = (unsigned)((a_row * 24 + a_ch * 8) * 2);
    const __half* a_srch; const __half* a_srcl; bool a_pred;
    if (GATHER) {
        int a = s_idx[a_row];
        a_pred = (a >= 0);
        size_t off = a_pred ? (size_t)(a >> SHIFT) * LDA + a_ch * 8 : 0;
        a_srch = Ah + off; a_srcl = Al + off;
    } else {
        a_pred = true;
        size_t off = (size_t)(row0 + a_row) * LDA + a_ch * 8;
        a_srch = Ah + off; a_srcl = Al + off;
    }
    unsigned b_dst = 0; const __half* b_srch = Bh; const __half* b_srcl = Bh;
    bool b_val;
    if (!NT) {
        b_val = tid < (16 * BN / 8);
        int row = tid / (BN / 8), cn = tid % (BN / 8);
        int sw = cn ^ (row & 7);
        b_dst = (unsigned)((row * BN + sw * 8) * 2);
        size_t off = (size_t)row * LDB + col0 + cn * 8;
        b_srch = Bh + off; b_srcl = Bl + off;
    } else {
        b_val = tid < (BN * 2);
        int nr = tid >> 1, ch = tid & 1;
        b_dst = (unsigned)((nr * 24 + ch * 8) * 2);
        size_t off = (size_t)(col0 + nr) * LDB + ch * 8;
        b_srch = Bh + off; b_srcl = Bl + off;
    }

    unsigned as_base = (unsigned)__cvta_generic_to_shared(&As[0][0][0]);
    unsigned bs_base = (unsigned)__cvta_generic_to_shared(&Bs[0][0][0]);

    auto issue = [&](int kt, int buf) {
        unsigned abh = as_base + (buf * 2 + 0) * AST * 2;
        unsigned abl = as_base + (buf * 2 + 1) * AST * 2;
        cpa16(abh + a_dst, a_srch + (size_t)kt * 16, a_pred);
        cpa16(abl + a_dst, a_srcl + (size_t)kt * 16, a_pred);
        if (b_val) {
            unsigned bbh = bs_base + (buf * 2 + 0) * BST * 2;
            unsigned bbl = bs_base + (buf * 2 + 1) * BST * 2;
            size_t off = NT ? (size_t)kt * 16 : (size_t)kt * 16 * LDB;
            cpa16(bbh + b_dst, b_srch + off, true);
            cpa16(bbl + b_dst, b_srcl + off, true);
        }
        asm volatile("cp.async.commit_group;\n");
    };

    int lane = tid & 31;
    int warp = tid >> 5;
    int wm = warp >> 2, wn = warp & 3;

    float acc[4][NF][4];
#pragma unroll
    for (int i = 0; i < 4; i++)
#pragma unroll
        for (int j = 0; j < NF; j++)
#pragma unroll
            for (int t = 0; t < 4; t++) acc[i][j][t] = 0.f;

    issue(0, 0);
#pragma unroll 1
    for (int kt = 0; kt < KT; kt++) {
        int buf = kt & 1;
        if (kt + 1 < KT) {
            issue(kt + 1, buf ^ 1);
            asm volatile("cp.async.wait_group 1;\n");
        } else {
            asm volatile("cp.async.wait_group 0;\n");
        }
        __syncthreads();
        unsigned abh = as_base + (buf * 2 + 0) * AST * 2;
        unsigned abl = as_base + (buf * 2 + 1) * AST * 2;
        unsigned bbh = bs_base + (buf * 2 + 0) * BST * 2;
        unsigned bbl = bs_base + (buf * 2 + 1) * BST * 2;

        unsigned ah[4][4], al[4][4];
#pragma unroll
        for (int i = 0; i < 4; i++) {
            int m = wm * 64 + i * 16 + (lane & 15);
            int ch = lane >> 4;
            unsigned ad = (unsigned)((m * 24 + ch * 8) * 2);
            ldsm4(ah[i], abh + ad);
            ldsm4(al[i], abl + ad);
        }
        unsigned brh[2 * NF], brl[2 * NF];
#pragma unroll
        for (int jj = 0; jj < NF / 2; jj++) {
            int n0 = wn * WN + jj * 16;
            if (!NT) {
                int k = lane & 15;
                int cn = (n0 >> 3) + (lane >> 4);
                int sw = cn ^ (k & 7);
                unsigned bd = (unsigned)((k * BN + sw * 8) * 2);
                ldsm4t(&brh[jj * 4], bbh + bd);
                ldsm4t(&brl[jj * 4], bbl + bd);
            } else {
                int n = n0 + ((lane >> 4) << 3) + (lane & 7);
                int ch = (lane >> 3) & 1;
                unsigned bd = (unsigned)((n * 24 + ch * 8) * 2);
                ldsm4(&brh[jj * 4], bbh + bd);
                ldsm4(&brl[jj * 4], bbl + bd);
            }
        }
#pragma unroll
        for (int i = 0; i < 4; i++)
#pragma unroll
            for (int j = 0; j < NF; j++) {
                mma16816(acc[i][j], ah[i], &brh[j * 2]);
                mma16816(acc[i][j], al[i], &brh[j * 2]);
                mma16816(acc[i][j], ah[i], &brl[j * 2]);
            }
        __syncthreads();
    }

    int rl = lane >> 2, cp2 = (lane & 3) * 2;
#pragma unroll
    for (int i = 0; i < 4; i++) {
#pragma unroll
        for (int hh = 0; hh < 2; hh++) {
            int rr = wm * 64 + i * 16 + rl + hh * 8;
            int r = row0 + rr;
            int aidx = 0;
            if (GATHER) {
                aidx = s_idx[rr];
                if (aidx < 0) continue;
            }
#pragma unroll
            for (int j = 0; j < NF; j++) {
                int c = col0 + wn * WN + j * 8 + cp2;
                float v0 = acc[i][j][hh * 2 + 0];
                float v1 = acc[i][j][hh * 2 + 1];
                if (MODE == M_PE) {
                    float* O = (float*)Og;
                    v0 += bias[c]     + extra[(size_t)(r & 255) * 512 + c];
                    v1 += bias[c + 1] + extra[(size_t)(r & 255) * 512 + c + 1];
                    O[(size_t)r * 512 + c] = v0;
                    O[(size_t)r * 512 + c + 1] = v1;
                } else if (MODE == M_QKV) {
                    __half* O = (__half*)Og + (size_t)bz * 2 * SZ_LN;
                    const float* bi = bias + bz * 512;
                    v0 += bi[c]; v1 += bi[c + 1];
                    int b = r >> 8, s = r & 255, hd = c >> 6, ii = c & 63;
                    size_t o = (size_t)(((b << 3) + hd) * 256 + s) * 64 + ii;
                    split2(v0, v1, O + o, O + OLO + o);
                } else if (MODE == M_PROJ) {
                    float* O = (float*)Og;
                    v0 += bias[c]     + extra[(size_t)r * 512 + c];
                    v1 += bias[c + 1] + extra[(size_t)r * 512 + c + 1];
                    O[(size_t)r * 512 + c] = v0;
                    O[(size_t)r * 512 + c + 1] = v1;
                } else if (MODE == M_SC) {
                    float* O = (float*)Og + (size_t)bz * 65536;
                    O[(size_t)r * 256 + c] = v0 * 0.125f;
                    O[(size_t)r * 256 + c + 1] = v1 * 0.125f;
                } else if (MODE == M_AV) {
                    __half* O = (__half*)Og;
                    int b = bz >> 3, hd = bz & 7;
                    size_t o = (size_t)((b << 8) + r) * 512 + (hd << 6) + c;
                    split2(v0, v1, O + o, O + OLO + o);
                } else if (MODE == M_FF1) {
                    __half* O = (__half*)Og;
                    const float* bi = bias + bz * 2048;
                    v0 = gelu_exact(v0 + bi[c]);
                    v1 = gelu_exact(v1 + bi[c + 1]);
                    size_t o = (size_t)aidx * 2048 + c;
                    split2(v0, v1, O + o, O + OLO + o);
                } else {
                    float* O = (float*)Og;
                    const float* bi = bias + bz * 512;
                    O[(size_t)aidx * 512 + c] = v0 + bi[c];
                    O[(size_t)aidx * 512 + c + 1] = v1 + bi[c + 1];
                }
            }
        }
    }
}

// ---------------- conversions ---------------------------------------------------
struct __align__(8) h2x2 { __half2 a, b; };

__device__ __forceinline__ void conv_elem4(const float* in, __half* outh, size_t n,
                                           size_t i) {
    float4 f = *(const float4*)(in + i);
    h2x2 H, L;
    H.a = __floats2half2_rn(f.x, f.y);
    H.b = __floats2half2_rn(f.z, f.w);
    float2 f0 = __half22float2(H.a), f1 = __half22float2(H.b);
    L.a = __floats2half2_rn(f.x - f0.x, f.y - f0.y);
    L.b = __floats2half2_rn(f.z - f1.x, f.w - f1.y);
    *(h2x2*)(outh + i) = H;
    *(h2x2*)(outh + n + i) = L;
}

__global__ __launch_bounds__(256) void conv4_k(
    const float* __restrict__ s0, const float* __restrict__ s1,
    const float* __restrict__ s2, const float* __restrict__ s3,
    __half* __restrict__ d0, __half* __restrict__ d1,
    __half* __restrict__ d2, __half* __restrict__ d3, size_t n)
{
    const float* src = (blockIdx.z == 0) ? s0 : (blockIdx.z == 1) ? s1 :
                       (blockIdx.z == 2) ? s2 : s3;
    __half* dst = (blockIdx.z == 0) ? d0 : (blockIdx.z == 1) ? d1 :
                  (blockIdx.z == 2) ? d2 : d3;
    size_t i = ((size_t)blockIdx.x * 256 + threadIdx.x) * 4;
    if (i < n) conv_elem4(src, dst, n, i);
}

__global__ __launch_bounds__(256) void convpe_k(const float* __restrict__ w) {
    int i = (blockIdx.x * 256 + threadIdx.x) * 4;
    if (i >= NPDP * ND) return;
    int j = i >> 9;
    float4 f = make_float4(0.f, 0.f, 0.f, 0.f);
    if (j < NPD) f = *(const float4*)(w + i);
    h2x2 H, L;
    H.a = __floats2half2_rn(f.x, f.y);
    H.b = __floats2half2_rn(f.z, f.w);
    float2 f0 = __half22float2(H.a), f1 = __half22float2(H.b);
    L.a = __floats2half2_rn(f.x - f0.x, f.y - f0.y);
    L.b = __floats2half2_rn(f.z - f1.x, f.w - f1.y);
    *(h2x2*)(g_pew16 + i) = H;
    *(h2x2*)(g_pew16 + NPDP * ND + i) = L;
}

// bqkv gather + global init (counters, loss)
__global__ void bqkv_k(const float* __restrict__ bq, const float* __restrict__ bk,
                       const float* __restrict__ bv, float* out_loss) {
    int i = blockIdx.x * 256 + threadIdx.x;
    if (blockIdx.x == 0 && threadIdx.x < 8) { g_cnt[threadIdx.x] = 0; g_imp[threadIdx.x] = 0.f; }
    if (i == 0) out_loss[0] = 0.f;
    if (i >= 1536) return;
    g_bqkv[i] = (i < 512) ? bq[i] : (i < 1024) ? bk[i - 512] : bv[i - 1024];
}

// ---------------- patch gather --------------------------------------------------
__global__ void patch_k(const float* __restrict__ x) {
    size_t idx = (size_t)blockIdx.x * 256 + threadIdx.x;
    if (idx >= SZ_P) return;
    int j = (int)(idx % NPDP);
    int rs = (int)(idx / NPDP);
    float f = 0.f;
    if (j < NPD) {
        int b = rs >> 8, s = rs & 255;
        int hi = s >> 4, wi = s & 15;
        int c = j % 3;
        int pp = j / 3;
        int p1 = pp / 14, p2 = pp % 14;
        f = x[(((size_t)(b * 3 + c)) * 224 + hi * 14 + p1) * 224 + wi * 14 + p2];
    }
    __half h = __float2half_rn(f);
    g_p16[idx] = h;
    g_p16[SZ_P + idx] = __float2half_rn(f - __half2float(h));
}

// ---------------- LN body (fp16 split out only) ---------------------------------
__device__ __forceinline__ void ln_body(
    int row, int tid, float4 v,
    const float* __restrict__ gw, const float* __restrict__ bw,
    __half* __restrict__ out16)
{
    float s = v.x + v.y + v.z + v.w;
    float q = v.x * v.x + v.y * v.y + v.z * v.z + v.w * v.w;
    __shared__ float ss[4], sq[4];
    for (int o = 16; o > 0; o >>= 1) {
        s += __shfl_xor_sync(0xffffffffu, s, o);
        q += __shfl_xor_sync(0xffffffffu, q, o);
    }
    if ((tid & 31) == 0) { ss[tid >> 5] = s; sq[tid >> 5] = q; }
    __syncthreads();
    s = ss[0] + ss[1] + ss[2] + ss[3];
    q = sq[0] + sq[1] + sq[2] + sq[3];
    float mean = s * (1.f / 512.f);
    float var  = q * (1.f / 512.f) - mean * mean;
    float inv  = rsqrtf(var + 1e-5f);
    float4 g4 = ((const float4*)gw)[tid];
    float4 b4 = ((const float4*)bw)[tid];
    float4 o;
    o.x = (v.x - mean) * inv * g4.x + b4.x;
    o.y = (v.y - mean) * inv * g4.y + b4.y;
    o.z = (v.z - mean) * inv * g4.z + b4.z;
    o.w = (v.w - mean) * inv * g4.w + b4.w;
    size_t base = (size_t)row * 512 + tid * 4;
    split2(o.x, o.y, out16 + base,     out16 + SZ_LN + base);
    split2(o.z, o.w, out16 + base + 2, out16 + SZ_LN + base + 2);
}

// LayerNorm from fp32 input
__global__ __launch_bounds__(128) void ln_k(
    const float* __restrict__ in, const float* __restrict__ gw,
    const float* __restrict__ bw, __half* __restrict__ out16)
{
    int row = blockIdx.x, tid = threadIdx.x;
    float4 v = ((const float4*)(in + (size_t)row * 512))[tid];
    ln_body(row, tid, v, gw, bw, out16);
}

// combine (top-2 MoE outputs) fused with LN — o1 never materialized
__global__ __launch_bounds__(128) void cln_k(
    const float* __restrict__ gw, const float* __restrict__ bw,
    __half* __restrict__ out16)
{
    int row = blockIdx.x, tid = threadIdx.x;
    float g1 = g_gate[2 * row], g2 = g_gate[2 * row + 1];
    float4 a = ((const float4*)(g_contrib + (size_t)(2 * row) * 512))[tid];
    float4 b = ((const float4*)(g_contrib + (size_t)(2 * row + 1) * 512))[tid];
    float4 v;
    v.x = g1 * a.x + g2 * b.x; v.y = g1 * a.y + g2 * b.y;
    v.z = g1 * a.z + g2 * b.z; v.w = g1 * a.w + g2 * b.w;
    ln_body(row, tid, v, gw, bw, out16);
}

// layer-2 combine fused into fv partial sum — o2 never materialized
__global__ __launch_bounds__(512) void fvc_k(float* __restrict__ part) {
    int b = blockIdx.x, seg = blockIdx.y, d = threadIdx.x;
    int t0 = b * 256 + seg * 32;
    float s = 0.f;
    for (int ss = 0; ss < 32; ss++) {
        int t = t0 + ss;
        float g1 = g_gate[2 * t], g2 = g_gate[2 * t + 1];
        s += g1 * g_contrib[(size_t)(2 * t) * 512 + d]
           + g2 * g_contrib[(size_t)(2 * t + 1) * 512 + d];
    }
    part[(size_t)(b * 8 + seg) * 512 + d] = s;
}

// ---------------- MoE router (smem-staged weights, warp per token) --------------
// reads the split fp16 LN output (hi + lo = exact to 2^-22)
__global__ __launch_bounds__(256) void router_k(const __half* __restrict__ xin,
                                                const float* __restrict__ rw,
                                                const float* __restrict__ rb) {
    __shared__ float s_rw[8][512];
    __shared__ float s_rb[8];
    int tid = threadIdx.x;
    for (int i = tid; i < 4096; i += 256) s_rw[i >> 9][i & 511] = rw[(i & 511) * 8 + (i >> 9)];
    if (tid < 8) s_rb[tid] = rb[tid];
    __syncthreads();
    int t = (blockIdx.x << 3) + (tid >> 5);
    int lane = tid & 31;
    const __half* xh = xin + (size_t)t * 512;
    const __half* xl = xh + SZ_LN;
    float acc[8] = {};
    for (int k = lane * 2; k < 512; k += 64) {
        __half2 h = *(const __half2*)(xh + k);
        __half2 l = *(const __half2*)(xl + k);
        float2 hf = __half22float2(h), lf = __half22float2(l);
        float x0 = hf.x + lf.x, x1 = hf.y + lf.y;
#pragma unroll
        for (int e = 0; e < 8; e++)
            acc[e] += x0 * s_rw[e][k] + x1 * s_rw[e][k + 1];
    }
#pragma unroll
    for (int e = 0; e < 8; e++)
        for (int o = 16; o > 0; o >>= 1) acc[e] += __shfl_xor_sync(0xffffffffu, acc[e], o);
    if (lane == 0) {
        float mx = -1e30f;
#pragma unroll
        for (int e = 0; e < 8; e++) { acc[e] += s_rb[e]; mx = fmaxf(mx, acc[e]); }
        float sum = 0.f;
#pragma unroll
        for (int e = 0; e < 8; e++) { acc[e] = __expf(acc[e] - mx); sum += acc[e]; }
        float inv = 1.f / sum;
#pragma unroll
        for (int e = 0; e < 8; e++) g_probs[t * 8 + e] = acc[e] * inv;
    }
}

// ---------------- softmax over attn rows ----------------------------------------
__global__ __launch_bounds__(256) void softmax_attn_k() {
    int row  = (blockIdx.x << 3) + (threadIdx.x >> 5);
    int lane = threadIdx.x & 31;
    const float4* p = (const float4*)(g_attn + (size_t)row * 256);
    float4 a = p[lane], b = p[lane + 32];
    float m = fmaxf(fmaxf(fmaxf(a.x, a.y), fmaxf(a.z, a.w)),
                    fmaxf(fmaxf(b.x, b.y), fmaxf(b.z, b.w)));
    for (int o = 16; o > 0; o >>= 1) m = fmaxf(m, __shfl_xor_sync(0xffffffffu, m, o));
    a.x = __expf(a.x - m); a.y = __expf(a.y - m);
    a.z = __expf(a.z - m); a.w = __expf(a.w - m);
    b.x = __expf(b.x - m); b.y = __expf(b.y - m);
    b.z = __expf(b.z - m); b.w = __expf(b.w - m);
    float s = a.x + a.y + a.z + a.w + b.x + b.y + b.z + b.w;
    for (int o = 16; o > 0; o >>= 1) s += __shfl_xor_sync(0xffffffffu, s, o);
    float inv = 1.f / s;
    a.x *= inv; a.y *= inv; a.z *= inv; a.w *= inv;
    b.x *= inv; b.y *= inv; b.z *= inv; b.w *= inv;
    size_t base = (size_t)row * 256;
    split2(a.x, a.y, g_attn16 + base + lane * 4,     g_attn16 + SZ_ATTN + base + lane * 4);
    split2(a.z, a.w, g_attn16 + base + lane * 4 + 2, g_attn16 + SZ_ATTN + base + lane * 4 + 2);
    split2(b.x, b.y, g_attn16 + base + 128 + lane * 4,     g_attn16 + SZ_ATTN + base + 128 + lane * 4);
    split2(b.z, b.w, g_attn16 + base + 128 + lane * 4 + 2, g_attn16 + SZ_ATTN + base + 128 + lane * 4 + 2);
}

// ---------------- attn_w --------------------------------------------------------
__global__ __launch_bounds__(256) void attnw_k(float* __restrict__ out) {
    int bq = blockIdx.x, tid = threadIdx.x;
    int b = bq >> 8, qr = bq & 255;
    float s = 0.f;
#pragma unroll
    for (int h = 0; h < 8; h++) {
        size_t off = ((size_t)((b << 3) + h)) * 65536 + (qr << 8) + tid;
        s += __half2float(g_attn16[off]) + __half2float(g_attn16[SZ_ATTN + off]);
    }
    s *= 0.125f;
    __shared__ float red[8];
    float m = s;
    for (int o = 16; o > 0; o >>= 1) m = fmaxf(m, __shfl_xor_sync(0xffffffffu, m, o));
    if ((tid & 31) == 0) red[tid >> 5] = m;
    __syncthreads();
    m = red[0];
#pragma unroll
    for (int w = 1; w < 8; w++) m = fmaxf(m, red[w]);
    float ex = __expf(s - m);
    float sum = ex;
    __syncthreads();
    for (int o = 16; o > 0; o >>= 1) sum += __shfl_xor_sync(0xffffffffu, sum, o);
    if ((tid & 31) == 0) red[tid >> 5] = sum;
    __syncthreads();
    sum = red[0] + red[1] + red[2] + red[3] + red[4] + red[5] + red[6] + red[7];
    out[(size_t)bq * 256 + tid] = ex / sum;
}

// ---------------- dispatch / loss -----------------------------------------------
__global__ __launch_bounds__(256) void dispatch_k() {
    __shared__ int   s_cnt[8];
    __shared__ float s_imp[8];
    __shared__ int   s_base[8];
    int tid = threadIdx.x;
    if (tid < 8) { s_cnt[tid] = 0; s_imp[tid] = 0.f; }
    __syncthreads();
    int t = blockIdx.x * 256 + tid;
    float p[8];
#pragma unroll
    for (int e = 0; e < 8; e++) { p[e] = g_probs[t * 8 + e]; atomicAdd(&s_imp[e], p[e]); }
    int e1 = 0; float v1 = p[0];
#pragma unroll
    for (int e = 1; e < 8; e++) if (p[e] > v1) { v1 = p[e]; e1 = e; }
    int e2 = -1; float v2 = -1e30f;
#pragma unroll
    for (int e = 0; e < 8; e++) if (e != e1 && p[e] > v2) { v2 = p[e]; e2 = e; }
    int lp1 = atomicAdd(&s_cnt[e1], 1);
    int lp2 = atomicAdd(&s_cnt[e2], 1);
    __syncthreads();
    if (tid < 8) {
        s_base[tid] = atomicAdd(&g_cnt[tid], s_cnt[tid]);
        atomicAdd(&g_imp[tid], s_imp[tid]);
    }
    __syncthreads();
    g_perm[e1 * NA + s_base[e1] + lp1] = t * 2;
    g_perm[e2 * NA + s_base[e2] + lp2] = t * 2 + 1;
    g_gate[t * 2]     = v1;
    g_gate[t * 2 + 1] = v2;
}

__global__ void loss_k(float* out_loss) {
    int tid = threadIdx.x;
    float v = 0.f;
    if (tid < 8)
        v = 8.f * ((float)g_cnt[tid] * (1.f / 8192.f)) * (g_imp[tid] * (1.f / 8192.f));
    for (int o = 16; o > 0; o >>= 1) v += __shfl_xor_sync(0xffffffffu, v, o);
    if (tid == 0) out_loss[0] += v;
    if (tid < 8) { g_cnt[tid] = 0; g_imp[tid] = 0.f; }
}

// ---------------- fv + logits ---------------------------------------------------
__global__ __launch_bounds__(512) void fv2_k(const float* __restrict__ part,
                                             float* __restrict__ out_fv) {
    int b = blockIdx.x, d = threadIdx.x;
    float s = 0.f;
#pragma unroll
    for (int seg = 0; seg < 8; seg++)
        s += part[(size_t)(b * 8 + seg) * 512 + d];
    s *= (1.f / 256.f);
    g_fv[b * 512 + d] = s;
    out_fv[b * 512 + d] = s;
}
__global__ __launch_bounds__(512) void logits_k(const float* __restrict__ W,
                                                const float* __restrict__ bias,
                                                float* __restrict__ out) {
    __shared__ float sf[512];
    int b = blockIdx.x, n = threadIdx.x;
    sf[n] = g_fv[b * 512 + n];
    __syncthreads();
    float acc = 0.f;
    for (int k = 0; k < 512; k++) acc += sf[k] * W[k * 512 + n];
    out[b * 512 + n] = acc + bias[n];
}

// ---------------- host launch ---------------------------------------------------
extern "C" void kernel_launch(void* const* d_in, const int* in_sizes, int n_in,
                              void* d_out, int out_size) {
    const float* x     = (const float*)d_in[0];
    const float* pe_w  = (const float*)d_in[1];
    const float* pe_b  = (const float*)d_in[2];
    const float* pos   = (const float*)d_in[3];
    const float* ln1_g = (const float*)d_in[4];
    const float* ln1_b = (const float*)d_in[5];
    const float* ln2_g = (const float*)d_in[6];
    const float* ln2_b = (const float*)d_in[7];
    const float* ln3_g = (const float*)d_in[8];
    const float* ln3_b = (const float*)d_in[9];
    const float* wq = (const float*)d_in[10];
    const float* bq = (const float*)d_in[11];
    const float* wk = (const float*)d_in[12];
    const float* bk = (const float*)d_in[13];
    const float* wv = (const float*)d_in[14];
    const float* bv = (const float*)d_in[15];
    const float* wo = (const float*)d_in[16];
    const float* bo = (const float*)d_in[17];
    const float* m1_rw = (const float*)d_in[18];
    const float* m1_rb = (const float*)d_in[19];
    const float* m1_w1 = (const float*)d_in[20];
    const float* m1_b1 = (const float*)d_in[21];
    const float* m1_w2 = (const float*)d_in[22];
    const float* m1_b2 = (const float*)d_in[23];
    const float* m2_rw = (const float*)d_in[24];
    const float* m2_rb = (const float*)d_in[25];
    const float* m2_w1 = (const float*)d_in[26];
    const float* m2_b1 = (const float*)d_in[27];
    const float* m2_w2 = (const float*)d_in[28];
    const float* m2_b2 = (const float*)d_in[29];
    const float* cls_w = (const float*)d_in[30];
    const float* cls_b = (const float*)d_in[31];

    float* out = (float*)d_out;
    float* out_logits = out;
    float* out_fv     = out + 16384;
    float* out_loss   = out + 32768;
    float* out_attnw  = out + 32769;

    float *p_e, *p_attn, *p_contrib, *p_part;
    __half *p_p16, *p_ln16, *p_qkv16, *p_attn16, *p_ctx16, *p_h16;
    __half *p_pew16, *p_wqkv16, *p_wo16;
    __half *p_w1a, *p_w2a, *p_w1b, *p_w2b;
    cudaGetSymbolAddress((void**)&p_e,       g_e);
    cudaGetSymbolAddress((void**)&p_attn,    g_attn);
    cudaGetSymbolAddress((void**)&p_contrib, g_contrib);
    cudaGetSymbolAddress((void**)&p_part,    g_part);
    cudaGetSymbolAddress((void**)&p_p16,     g_p16);
    cudaGetSymbolAddress((void**)&p_ln16,    g_ln16);
    cudaGetSymbolAddress((void**)&p_qkv16,   g_qkv16);
    cudaGetSymbolAddress((void**)&p_attn16,  g_attn16);
    cudaGetSymbolAddress((void**)&p_ctx16,   g_ctx16);
    cudaGetSymbolAddress((void**)&p_h16,     g_h16);
    cudaGetSymbolAddress((void**)&p_pew16,   g_pew16);
    cudaGetSymbolAddress((void**)&p_wqkv16,  g_wqkv16);
    cudaGetSymbolAddress((void**)&p_wo16,    g_wo16);
    cudaGetSymbolAddress((void**)&p_w1a,     g_w1a16);
    cudaGetSymbolAddress((void**)&p_w2a,     g_w2a16);
    cudaGetSymbolAddress((void**)&p_w1b,     g_w1b16);
    cudaGetSymbolAddress((void**)&p_w2b,     g_w2b16);
    float* p_bqkv; cudaGetSymbolAddress((void**)&p_bqkv, g_bqkv);

    // fork: big MoE weight conversions on side stream (overlaps with attention)
    cudaEventRecord(g_ss.fork, 0);
    cudaStreamWaitEvent(g_ss.s, g_ss.fork, 0);
    conv4_k<<<dim3(8192, 1, 4), 256, 0, g_ss.s>>>(
        m1_w1, m1_w2, m2_w1, m2_w2, p_w1a, p_w2a, p_w1b, p_w2b, SZ_W);
    cudaEventRecord(g_ss.join, g_ss.s);

    bqkv_k<<<6, 256>>>(bq, bk, bv, out_loss);
    convpe_k<<<(NPDP * ND / 4 + 255) / 256, 256>>>(pe_w);
    conv4_k<<<dim3(256, 1, 4), 256>>>(
        wq, wk, wv, wo,
        p_wqkv16, p_wqkv16 + 2 * SZ_DD, p_wqkv16 + 4 * SZ_DD, p_wo16, SZ_DD);

    patch_k<<<(int)((SZ_P + 255) / 256), 256>>>(x);
    mm_k<M_PE><<<dim3(4, 64), 256>>>(p_p16, p_pew16, pe_b, pos, p_e);

    ln_k<<<NTOK, 128>>>(p_e, ln1_g, ln1_b, p_ln16);
    mm_k<M_QKV><<<dim3(4, 64, 3), 256>>>(p_ln16, p_wqkv16, p_bqkv, nullptr, p_qkv16);
    mm_k<M_SC><<<dim3(4, 2, 256), 256>>>(p_qkv16, p_qkv16 + 2 * SZ_LN,
                                         nullptr, nullptr, p_attn);
    softmax_attn_k<<<8192, 256>>>();
    mm_k<M_AV><<<dim3(1, 2, 256), 256>>>(p_attn16, p_qkv16 + 4 * SZ_LN,
                                         nullptr, nullptr, p_ctx16);
    mm_k<M_PROJ><<<dim3(4, 64), 256>>>(p_ctx16, p_wo16, bo, p_e, p_e);
    attnw_k<<<NTOK, 256>>>(out_attnw);

    // MoE layer 1
    ln_k<<<NTOK, 128>>>(p_e, ln2_g, ln2_b, p_ln16);
    router_k<<<1024, 256>>>(p_ln16, m1_rw, m1_rb);
    dispatch_k<<<32, 256>>>();
    cudaStreamWaitEvent(0, g_ss.join, 0);
    mm_k<M_FF1><<<dim3(16, 64, 8), 256>>>(p_ln16, p_w1a, m1_b1, nullptr, p_h16);
    mm_k<M_FF2><<<dim3(4, 64, 8), 256>>>(p_h16, p_w2a, m1_b2, nullptr, p_contrib);

    // combine + LN3 fused; o1 never materialized
    cln_k<<<NTOK, 128>>>(ln3_g, ln3_b, p_ln16);
    loss_k<<<1, 32>>>(out_loss);

    // MoE layer 2
    router_k<<<1024, 256>>>(p_ln16, m2_rw, m2_rb);
    dispatch_k<<<32, 256>>>();
    mm_k<M_FF1><<<dim3(16, 64, 8), 256>>>(p_ln16, p_w1b, m2_b1, nullptr, p_h16);
    mm_k<M_FF2><<<dim3(4, 64, 8), 256>>>(p_h16, p_w2b, m2_b2, nullptr, p_contrib);

    // layer-2 combine fused into fv partials; o2 never materialized
    fvc_k<<<dim3(NB, 8), 512>>>(p_part);
    loss_k<<<1, 32>>>(out_loss);
    fv2_k<<<NB, 512>>>(p_part, out_fv);
    logits_k<<<NB, 512>>>(cls_w, cls_b, out_logits);
}

// round 12
// speedup vs baseline: 1.1636x; 1.0003x over previous
#include <cuda_runtime.h>
#include <cuda_fp16.h>
#include <math.h>
#include <stdint.h>

#define NB   32
#define NS   256
#define ND   512
#define NH   8
#define NE   8
#define NHID 2048
#define NPD  588
#define NPDP 608
#define NTOK 8192
#define NA   16384

#define SZ_LN   ((size_t)NTOK * ND)
#define SZ_P    ((size_t)NTOK * NPDP)
#define SZ_ATTN ((size_t)NB * NH * NS * NS)
#define SZ_H    ((size_t)NA * NHID)
#define SZ_W    ((size_t)NE * ND * NHID)
#define SZ_DD   ((size_t)ND * ND)

// ---------------- fp32 scratch -------------------------------------------------
__device__ float g_e[NTOK * ND];
__device__ float g_attn[NB * NH * NS * NS];
__device__ float g_probs[NTOK * NE];
__device__ float g_gate[NA];
__device__ int   g_perm[NE * NA];
__device__ int   g_cnt[NE];
__device__ float g_imp[NE];
__device__ float g_contrib[NA * ND];
__device__ float g_part[NB * 8 * ND];
__device__ float g_fv[NB * ND];
__device__ float g_bqkv[3 * ND];

// ---------------- split fp16 buffers (hi at [0], lo at [SIZE] per segment) -----
__device__ __half g_p16[2 * SZ_P];
__device__ __half g_ln16[2 * SZ_LN];
__device__ __half g_qkv16[6 * SZ_LN];
__device__ __half g_attn16[2 * SZ_ATTN];
__device__ __half g_ctx16[2 * SZ_LN];
__device__ __half g_h16[2 * SZ_H];
__device__ __half g_pew16[2 * NPDP * ND];
__device__ __half g_wqkv16[6 * SZ_DD];
__device__ __half g_wo16[2 * SZ_DD];
__device__ __half g_w1a16[2 * SZ_W];
__device__ __half g_w2a16[2 * SZ_W];
__device__ __half g_w1b16[2 * SZ_W];
__device__ __half g_w2b16[2 * SZ_W];

// ---------------- persistent side stream ---------------------------------------
struct SideStream {
    cudaStream_t s;
    cudaEvent_t fork, join;
    SideStream() {
        cudaStreamCreateWithFlags(&s, cudaStreamNonBlocking);
        cudaEventCreateWithFlags(&fork, cudaEventDisableTiming);
        cudaEventCreateWithFlags(&join, cudaEventDisableTiming);
    }
};
static SideStream g_ss;

__device__ __forceinline__ float gelu_exact(float v) {
    return 0.5f * v * (1.0f + erff(v * 0.70710678118654752440f));
}
__device__ __forceinline__ void split2(float v0, float v1, __half* oh, __half* ol) {
    __half h0 = __float2half_rn(v0), h1 = __float2half_rn(v1);
    *(__half2*)oh = __halves2half2(h0, h1);
    *(__half2*)ol = __halves2half2(__float2half_rn(v0 - __half2float(h0)),
                                   __float2half_rn(v1 - __half2float(h1)));
}

// ---------------- mma.sync helpers ----------------------------------------------
__device__ __forceinline__ void ldsm4(unsigned* r, unsigned addr) {
    asm volatile("ldmatrix.sync.aligned.m8n8.x4.shared.b16 {%0,%1,%2,%3}, [%4];\n"
        : "=r"(r[0]), "=r"(r[1]), "=r"(r[2]), "=r"(r[3]) : "r"(addr));
}
__device__ __forceinline__ void ldsm4t(unsigned* r, unsigned addr) {
    asm volatile("ldmatrix.sync.aligned.m8n8.x4.trans.shared.b16 {%0,%1,%2,%3}, [%4];\n"
        : "=r"(r[0]), "=r"(r[1]), "=r"(r[2]), "=r"(r[3]) : "r"(addr));
}
__device__ __forceinline__ void mma16816(float* c, const unsigned* a, const unsigned* b) {
    asm volatile("mma.sync.aligned.m16n8k16.row.col.f32.f16.f16.f32 "
        "{%0,%1,%2,%3}, {%4,%5,%6,%7}, {%8,%9}, {%0,%1,%2,%3};\n"
        : "+f"(c[0]), "+f"(c[1]), "+f"(c[2]), "+f"(c[3])
        : "r"(a[0]), "r"(a[1]), "r"(a[2]), "r"(a[3]), "r"(b[0]), "r"(b[1]));
}
__device__ __forceinline__ void cpa16(unsigned dst, const void* src, bool p) {
    int sz = p ? 16 : 0;
    asm volatile("cp.async.cg.shared.global [%0], [%1], 16, %2;\n"
        :: "r"(dst), "l"(src), "r"(sz));
}

// ---------------- modes --------------------------------------------------------
#define M_PE   0
#define M_QKV  1
#define M_PROJ 2
#define M_SC   3
#define M_AV   4
#define M_FF1  5
#define M_FF2  6

template <int MODE>
__global__ __launch_bounds__(256) void mm_k(
    const __half* __restrict__ Ag, const __half* __restrict__ Bg,
    const float* __restrict__ bias, const float* __restrict__ extra,
    void* __restrict__ Og)
{
    constexpr int K   = (MODE == M_PE) ? NPDP : (MODE == M_SC) ? 64 :
                        (MODE == M_AV) ? 256 : (MODE == M_FF2) ? 2048 : 512;
    constexpr int LDA = K;
    constexpr int LDB = (MODE == M_SC || MODE == M_AV) ? 64 :
                        (MODE == M_FF1) ? 2048 : 512;
    constexpr bool NT = (MODE == M_SC);
    constexpr bool GATHER = (MODE == M_FF1) || (MODE == M_FF2);
    constexpr int SHIFT = (MODE == M_FF1) ? 1 : 0;
    constexpr int BN = (MODE == M_AV || MODE == M_SC) ? 64 : 128;
    constexpr int WN = BN / 4;
    constexpr int NF = WN / 8;
    constexpr int KT = K / 16;
    constexpr size_t ALO =
        (MODE == M_PE)  ? SZ_P :
        (MODE == M_SC || MODE == M_QKV || MODE == M_PROJ || MODE == M_FF1) ? SZ_LN :
        (MODE == M_AV)  ? SZ_ATTN : SZ_H;
    constexpr size_t BLO =
        (MODE == M_PE)  ? (size_t)NPDP * ND :
        (MODE == M_QKV || MODE == M_PROJ) ? SZ_DD :
        (MODE == M_SC || MODE == M_AV) ? SZ_LN : SZ_W;
    constexpr size_t OLO =
        (MODE == M_QKV || MODE == M_AV) ? SZ_LN : SZ_H;
    constexpr int AST = 128 * 24;
    constexpr int BST = NT ? BN * 24 : 16 * BN;

    __shared__ __align__(16) __half As[2][2][AST];
    __shared__ __align__(16) __half Bs[2][2][BST];
    __shared__ int s_idx[128];

    int tid = threadIdx.x;
    int bz = blockIdx.z;
    int row0 = blockIdx.y * 128, col0 = blockIdx.x * BN;

    const __half* Ah = Ag;
    const __half* Bh = Bg;
    if (MODE == M_SC)  { Ah += (size_t)bz * 256 * 64; Bh += (size_t)bz * 256 * 64; }
    if (MODE == M_AV)  { Ah += (size_t)bz * 65536;    Bh += (size_t)bz * 256 * 64; }
    if (MODE == M_QKV) { Bh += (size_t)bz * 2 * SZ_DD; }
    if (MODE == M_FF1) { Bh += (size_t)bz * 512 * 2048; }
    if (MODE == M_FF2) { Bh += (size_t)bz * 2048 * 512; }
    const __half* Al = Ah + ALO;
    const __half* Bl = Bh + BLO;

    if (GATHER) {
        int cnt = g_cnt[bz];
        if (row0 >= cnt) return;
        if (tid < 128) {
            int r = row0 + tid;
            s_idx[tid] = (r < cnt) ? g_perm[bz * NA + r] : -1;
        }
        __syncthreads();
    }

    int a_row = tid >> 1, a_ch = tid & 1;
    unsigned a_dst = (unsigned)((a_row * 24 + a_ch * 8) * 2);
    const __half* a_srch; const __half* a_srcl; bool a_pred;
    if (GATHER) {
        int a = s_idx[a_row];
        a_pred = (a >= 0);
        size_t off = a_pred ? (size_t)(a >> SHIFT) * LDA + a_ch * 8 : 0;
        a_srch = Ah + off; a_srcl = Al + off;
    } else {
        a_pred = true;
        size_t off = (size_t)(row0 + a_row) * LDA + a_ch * 8;
        a_srch = Ah + off; a_srcl = Al + off;
    }
    unsigned b_dst = 0; const __half* b_srch = Bh; const __half* b_srcl = Bh;
    bool b_val;
    if (!NT) {
        b_val = tid < (16 * BN / 8);
        int row = tid / (BN / 8), cn = tid % (BN / 8);
        int sw = cn ^ (row & 7);
        b_dst = (unsigned)((row * BN + sw * 8) * 2);
        size_t off = (size_t)row * LDB + col0 + cn * 8;
        b_srch = Bh + off; b_srcl = Bl + off;
    } else {
        b_val = tid < (BN * 2);
        int nr = tid >> 1, ch = tid & 1;
        b_dst = (unsigned)((nr * 24 + ch * 8) * 2);
        size_t off = (size_t)(col0 + nr) * LDB + ch * 8;
        b_srch = Bh + off; b_srcl = Bl + off;
    }

    unsigned as_base = (unsigned)__cvta_generic_to_shared(&As[0][0][0]);
    unsigned bs_base = (unsigned)__cvta_generic_to_shared(&Bs[0][0][0]);

    auto issue = [&](int kt, int buf) {
        unsigned abh = as_base + (buf * 2 + 0) * AST * 2;
        unsigned abl = as_base + (buf * 2 + 1) * AST * 2;
        cpa16(abh + a_dst, a_srch + (size_t)kt * 16, a_pred);
        cpa16(abl + a_dst, a_srcl + (size_t)kt * 16, a_pred);
        if (b_val) {
            unsigned bbh = bs_base + (buf * 2 + 0) * BST * 2;
            unsigned bbl = bs_base + (buf * 2 + 1) * BST * 2;
            size_t off = NT ? (size_t)kt * 16 : (size_t)kt * 16 * LDB;
            cpa16(bbh + b_dst, b_srch + off, true);
            cpa16(bbl + b_dst, b_srcl + off, true);
        }
        asm volatile("cp.async.commit_group;\n");
    };

    int lane = tid & 31;
    int warp = tid >> 5;
    int wm = warp >> 2, wn = warp & 3;

    float acc[4][NF][4];
#pragma unroll
    for (int i = 0; i < 4; i++)
#pragma unroll
        for (int j = 0; j < NF; j++)
#pragma unroll
            for (int t = 0; t < 4; t++) acc[i][j][t] = 0.f;

    issue(0, 0);
#pragma unroll 1
    for (int kt = 0; kt < KT; kt++) {
        int buf = kt & 1;
        if (kt + 1 < KT) {
            issue(kt + 1, buf ^ 1);
            asm volatile("cp.async.wait_group 1;\n");
        } else {
            asm volatile("cp.async.wait_group 0;\n");
        }
        __syncthreads();
        unsigned abh = as_base + (buf * 2 + 0) * AST * 2;
        unsigned abl = as_base + (buf * 2 + 1) * AST * 2;
        unsigned bbh = bs_base + (buf * 2 + 0) * BST * 2;
        unsigned bbl = bs_base + (buf * 2 + 1) * BST * 2;

        unsigned ah[4][4], al[4][4];
#pragma unroll
        for (int i = 0; i < 4; i++) {
            int m = wm * 64 + i * 16 + (lane & 15);
            int ch = lane >> 4;
            unsigned ad = (unsigned)((m * 24 + ch * 8) * 2);
            ldsm4(ah[i], abh + ad);
            ldsm4(al[i], abl + ad);
        }
        unsigned brh[2 * NF], brl[2 * NF];
#pragma unroll
        for (int jj = 0; jj < NF / 2; jj++) {
            int n0 = wn * WN + jj * 16;
            if (!NT) {
                int k = lane & 15;
                int cn = (n0 >> 3) + (lane >> 4);
                int sw = cn ^ (k & 7);
                unsigned bd = (unsigned)((k * BN + sw * 8) * 2);
                ldsm4t(&brh[jj * 4], bbh + bd);
                ldsm4t(&brl[jj * 4], bbl + bd);
            } else {
                int n = n0 + ((lane >> 4) << 3) + (lane & 7);
                int ch = (lane >> 3) & 1;
                unsigned bd = (unsigned)((n * 24 + ch * 8) * 2);
                ldsm4(&brh[jj * 4], bbh + bd);
                ldsm4(&brl[jj * 4], bbl + bd);
            }
        }
#pragma unroll
        for (int i = 0; i < 4; i++)
#pragma unroll
            for (int j = 0; j < NF; j++) {
                mma16816(acc[i][j], ah[i], &brh[j * 2]);
                mma16816(acc[i][j], al[i], &brh[j * 2]);
                mma16816(acc[i][j], ah[i], &brl[j * 2]);
            }
        __syncthreads();
    }

    int rl = lane >> 2, cp2 = (lane & 3) * 2;
#pragma unroll
    for (int i = 0; i < 4; i++) {
#pragma unroll
        for (int hh = 0; hh < 2; hh++) {
            int rr = wm * 64 + i * 16 + rl + hh * 8;
            int r = row0 + rr;
            int aidx = 0;
            if (GATHER) {
                aidx = s_idx[rr];
                if (aidx < 0) continue;
            }
#pragma unroll
            for (int j = 0; j < NF; j++) {
                int c = col0 + wn * WN + j * 8 + cp2;
                float v0 = acc[i][j][hh * 2 + 0];
                float v1 = acc[i][j][hh * 2 + 1];
                if (MODE == M_PE) {
                    float* O = (float*)Og;
                    v0 += bias[c]     + extra[(size_t)(r & 255) * 512 + c];
                    v1 += bias[c + 1] + extra[(size_t)(r & 255) * 512 + c + 1];
                    O[(size_t)r * 512 + c] = v0;
                    O[(size_t)r * 512 + c + 1] = v1;
                } else if (MODE == M_QKV) {
                    __half* O = (__half*)Og + (size_t)bz * 2 * SZ_LN;
                    const float* bi = bias + bz * 512;
                    v0 += bi[c]; v1 += bi[c + 1];
                    int b = r >> 8, s = r & 255, hd = c >> 6, ii = c & 63;
                    size_t o = (size_t)(((b << 3) + hd) * 256 + s) * 64 + ii;
                    split2(v0, v1, O + o, O + OLO + o);
                } else if (MODE == M_PROJ) {
                    float* O = (float*)Og;
                    v0 += bias[c]     + extra[(size_t)r * 512 + c];
                    v1 += bias[c + 1] + extra[(size_t)r * 512 + c + 1];
                    O[(size_t)r * 512 + c] = v0;
                    O[(size_t)r * 512 + c + 1] = v1;
                } else if (MODE == M_SC) {
                    float* O = (float*)Og + (size_t)bz * 65536;
                    O[(size_t)r * 256 + c] = v0 * 0.125f;
                    O[(size_t)r * 256 + c + 1] = v1 * 0.125f;
                } else if (MODE == M_AV) {
                    __half* O = (__half*)Og;
                    int b = bz >> 3, hd = bz & 7;
                    size_t o = (size_t)((b << 8) + r) * 512 + (hd << 6) + c;
                    split2(v0, v1, O + o, O + OLO + o);
                } else if (MODE == M_FF1) {
                    __half* O = (__half*)Og;
                    const float* bi = bias + bz * 2048;
                    v0 = gelu_exact(v0 + bi[c]);
                    v1 = gelu_exact(v1 + bi[c + 1]);
                    size_t o = (size_t)aidx * 2048 + c;
                    split2(v0, v1, O + o, O + OLO + o);
                } else {
                    float* O = (float*)Og;
                    const float* bi = bias + bz * 512;
                    O[(size_t)aidx * 512 + c] = v0 + bi[c];
                    O[(size_t)aidx * 512 + c + 1] = v1 + bi[c + 1];
                }
            }
        }
    }
}

// ---------------- conversions ---------------------------------------------------
struct __align__(8) h2x2 { __half2 a, b; };

__device__ __forceinline__ void conv_elem4(const float* in, __half* outh, size_t n,
                                           size_t i) {
    float4 f = *(const float4*)(in + i);
    h2x2 H, L;
    H.a = __floats2half2_rn(f.x, f.y);
    H.b = __floats2half2_rn(f.z, f.w);
    float2 f0 = __half22float2(H.a), f1 = __half22float2(H.b);
    L.a = __floats2half2_rn(f.x - f0.x, f.y - f0.y);
    L.b = __floats2half2_rn(f.z - f1.x, f.w - f1.y);
    *(h2x2*)(outh + i) = H;
    *(h2x2*)(outh + n + i) = L;
}

__global__ __launch_bounds__(256) void conv4_k(
    const float* __restrict__ s0, const float* __restrict__ s1,
    const float* __restrict__ s2, const float* __restrict__ s3,
    __half* __restrict__ d0, __half* __restrict__ d1,
    __half* __restrict__ d2, __half* __restrict__ d3, size_t n)
{
    const float* src = (blockIdx.z == 0) ? s0 : (blockIdx.z == 1) ? s1 :
                       (blockIdx.z == 2) ? s2 : s3;
    __half* dst = (blockIdx.z == 0) ? d0 : (blockIdx.z == 1) ? d1 :
                  (blockIdx.z == 2) ? d2 : d3;
    size_t i = ((size_t)blockIdx.x * 256 + threadIdx.x) * 4;
    if (i < n) conv_elem4(src, dst, n, i);
}

__global__ __launch_bounds__(256) void convpe_k(const float* __restrict__ w) {
    int i = (blockIdx.x * 256 + threadIdx.x) * 4;
    if (i >= NPDP * ND) return;
    int j = i >> 9;
    float4 f = make_float4(0.f, 0.f, 0.f, 0.f);
    if (j < NPD) f = *(const float4*)(w + i);
    h2x2 H, L;
    H.a = __floats2half2_rn(f.x, f.y);
    H.b = __floats2half2_rn(f.z, f.w);
    float2 f0 = __half22float2(H.a), f1 = __half22float2(H.b);
    L.a = __floats2half2_rn(f.x - f0.x, f.y - f0.y);
    L.b = __floats2half2_rn(f.z - f1.x, f.w - f1.y);
    *(h2x2*)(g_pew16 + i) = H;
    *(h2x2*)(g_pew16 + NPDP * ND + i) = L;
}

// bqkv gather + global init (counters, loss)
__global__ void bqkv_k(const float* __restrict__ bq, const float* __restrict__ bk,
                       const float* __restrict__ bv, float* out_loss) {
    int i = blockIdx.x * 256 + threadIdx.x;
    if (blockIdx.x == 0 && threadIdx.x < 8) { g_cnt[threadIdx.x] = 0; g_imp[threadIdx.x] = 0.f; }
    if (i == 0) out_loss[0] = 0.f;
    if (i >= 1536) return;
    g_bqkv[i] = (i < 512) ? bq[i] : (i < 1024) ? bk[i - 512] : bv[i - 1024];
}

// ---------------- patch gather (coalesced, smem-staged) -------------------------
// one block per token; read in (c,p1,p2) order (contiguous p2 runs),
// stage to smem in patch-dim order, write g_p16 hi/lo coalesced.
__global__ __launch_bounds__(256) void patch_k(const float* __restrict__ x) {
    __shared__ float sp[NPD];
    int t = blockIdx.x;            // token
    int b = t >> 8, s = t & 255;
    int hi = s >> 4, wi = s & 15;
    int tid = threadIdx.x;
    const float* xb = x + ((size_t)b * 3 * 224 + hi * 14) * 224 + wi * 14;
    for (int idx = tid; idx < NPD; idx += 256) {
        int c = idx / 196, rem = idx % 196;
        int p1 = rem / 14, p2 = rem % 14;
        float f = xb[((size_t)c * 224 + p1) * 224 + p2];
        sp[(p1 * 14 + p2) * 3 + c] = f;
    }
    __syncthreads();
    size_t base = (size_t)t * NPDP;
    for (int j = tid; j < NPDP; j += 256) {
        float f = (j < NPD) ? sp[j] : 0.f;
        __half h = __float2half_rn(f);
        g_p16[base + j] = h;
        g_p16[SZ_P + base + j] = __float2half_rn(f - __half2float(h));
    }
}

// ---------------- LN body (fp16 split out only) ---------------------------------
__device__ __forceinline__ void ln_body(
    int row, int tid, float4 v,
    const float* __restrict__ gw, const float* __restrict__ bw,
    __half* __restrict__ out16)
{
    float s = v.x + v.y + v.z + v.w;
    float q = v.x * v.x + v.y * v.y + v.z * v.z + v.w * v.w;
    __shared__ float ss[4], sq[4];
    for (int o = 16; o > 0; o >>= 1) {
        s += __shfl_xor_sync(0xffffffffu, s, o);
        q += __shfl_xor_sync(0xffffffffu, q, o);
    }
    if ((tid & 31) == 0) { ss[tid >> 5] = s; sq[tid >> 5] = q; }
    __syncthreads();
    s = ss[0] + ss[1] + ss[2] + ss[3];
    q = sq[0] + sq[1] + sq[2] + sq[3];
    float mean = s * (1.f / 512.f);
    float var  = q * (1.f / 512.f) - mean * mean;
    float inv  = rsqrtf(var + 1e-5f);
    float4 g4 = ((const float4*)gw)[tid];
    float4 b4 = ((const float4*)bw)[tid];
    float4 o;
    o.x = (v.x - mean) * inv * g4.x + b4.x;
    o.y = (v.y - mean) * inv * g4.y + b4.y;
    o.z = (v.z - mean) * inv * g4.z + b4.z;
    o.w = (v.w - mean) * inv * g4.w + b4.w;
    size_t base = (size_t)row * 512 + tid * 4;
    split2(o.x, o.y, out16 + base,     out16 + SZ_LN + base);
    split2(o.z, o.w, out16 + base + 2, out16 + SZ_LN + base + 2);
}

__global__ __launch_bounds__(128) void ln_k(
    const float* __restrict__ in, const float* __restrict__ gw,
    const float* __restrict__ bw, __half* __restrict__ out16)
{
    int row = blockIdx.x, tid = threadIdx.x;
    float4 v = ((const float4*)(in + (size_t)row * 512))[tid];
    ln_body(row, tid, v, gw, bw, out16);
}

__global__ __launch_bounds__(128) void cln_k(
    const float* __restrict__ gw, const float* __restrict__ bw,
    __half* __restrict__ out16)
{
    int row = blockIdx.x, tid = threadIdx.x;
    float g1 = g_gate[2 * row], g2 = g_gate[2 * row + 1];
    float4 a = ((const float4*)(g_contrib + (size_t)(2 * row) * 512))[tid];
    float4 b = ((const float4*)(g_contrib + (size_t)(2 * row + 1) * 512))[tid];
    float4 v;
    v.x = g1 * a.x + g2 * b.x; v.y = g1 * a.y + g2 * b.y;
    v.z = g1 * a.z + g2 * b.z; v.w = g1 * a.w + g2 * b.w;
    ln_body(row, tid, v, gw, bw, out16);
}

__global__ __launch_bounds__(512) void fvc_k(float* __restrict__ part) {
    int b = blockIdx.x, seg = blockIdx.y, d = threadIdx.x;
    int t0 = b * 256 + seg * 32;
    float s = 0.f;
    for (int ss = 0; ss < 32; ss++) {
        int t = t0 + ss;
        float g1 = g_gate[2 * t], g2 = g_gate[2 * t + 1];
        s += g1 * g_contrib[(size_t)(2 * t) * 512 + d]
           + g2 * g_contrib[(size_t)(2 * t + 1) * 512 + d];
    }
    part[(size_t)(b * 8 + seg) * 512 + d] = s;
}

// ---------------- MoE router ----------------------------------------------------
__global__ __launch_bounds__(256) void router_k(const __half* __restrict__ xin,
                                                const float* __restrict__ rw,
                                                const float* __restrict__ rb) {
    __shared__ float s_rw[8][512];
    __shared__ float s_rb[8];
    int tid = threadIdx.x;
    for (int i = tid; i < 4096; i += 256) s_rw[i >> 9][i & 511] = rw[(i & 511) * 8 + (i >> 9)];
    if (tid < 8) s_rb[tid] = rb[tid];
    __syncthreads();
    int t = (blockIdx.x << 3) + (tid >> 5);
    int lane = tid & 31;
    const __half* xh = xin + (size_t)t * 512;
    const __half* xl = xh + SZ_LN;
    float acc[8] = {};
    for (int k = lane * 2; k < 512; k += 64) {
        __half2 h = *(const __half2*)(xh + k);
        __half2 l = *(const __half2*)(xl + k);
        float2 hf = __half22float2(h), lf = __half22float2(l);
        float x0 = hf.x + lf.x, x1 = hf.y + lf.y;
#pragma unroll
        for (int e = 0; e < 8; e++)
            acc[e] += x0 * s_rw[e][k] + x1 * s_rw[e][k + 1];
    }
#pragma unroll
    for (int e = 0; e < 8; e++)
        for (int o = 16; o > 0; o >>= 1) acc[e] += __shfl_xor_sync(0xffffffffu, acc[e], o);
    if (lane == 0) {
        float mx = -1e30f;
#pragma unroll
        for (int e = 0; e < 8; e++) { acc[e] += s_rb[e]; mx = fmaxf(mx, acc[e]); }
        float sum = 0.f;
#pragma unroll
        for (int e = 0; e < 8; e++) { acc[e] = __expf(acc[e] - mx); sum += acc[e]; }
        float inv = 1.f / sum;
#pragma unroll
        for (int e = 0; e < 8; e++) g_probs[t * 8 + e] = acc[e] * inv;
    }
}

// ---------------- softmax over attn rows ----------------------------------------
__global__ __launch_bounds__(256) void softmax_attn_k() {
    int row  = (blockIdx.x << 3) + (threadIdx.x >> 5);
    int lane = threadIdx.x & 31;
    const float4* p = (const float4*)(g_attn + (size_t)row * 256);
    float4 a = p[lane], b = p[lane + 32];
    float m = fmaxf(fmaxf(fmaxf(a.x, a.y), fmaxf(a.z, a.w)),
                    fmaxf(fmaxf(b.x, b.y), fmaxf(b.z, b.w)));
    for (int o = 16; o > 0; o >>= 1) m = fmaxf(m, __shfl_xor_sync(0xffffffffu, m, o));
    a.x = __expf(a.x - m); a.y = __expf(a.y - m);
    a.z = __expf(a.z - m); a.w = __expf(a.w - m);
    b.x = __expf(b.x - m); b.y = __expf(b.y - m);
    b.z = __expf(b.z - m); b.w = __expf(b.w - m);
    float s = a.x + a.y + a.z + a.w + b.x + b.y + b.z + b.w;
    for (int o = 16; o > 0; o >>= 1) s += __shfl_xor_sync(0xffffffffu, s, o);
    float inv = 1.f / s;
    a.x *= inv; a.y *= inv; a.z *= inv; a.w *= inv;
    b.x *= inv; b.y *= inv; b.z *= inv; b.w *= inv;
    size_t base = (size_t)row * 256;
    split2(a.x, a.y, g_attn16 + base + lane * 4,     g_attn16 + SZ_ATTN + base + lane * 4);
    split2(a.z, a.w, g_attn16 + base + lane * 4 + 2, g_attn16 + SZ_ATTN + base + lane * 4 + 2);
    split2(b.x, b.y, g_attn16 + base + 128 + lane * 4,     g_attn16 + SZ_ATTN + base + 128 + lane * 4);
    split2(b.z, b.w, g_attn16 + base + 128 + lane * 4 + 2, g_attn16 + SZ_ATTN + base + 128 + lane * 4 + 2);
}

// ---------------- attn_w --------------------------------------------------------
__global__ __launch_bounds__(256) void attnw_k(float* __restrict__ out) {
    int bq = blockIdx.x, tid = threadIdx.x;
    int b = bq >> 8, qr = bq & 255;
    float s = 0.f;
#pragma unroll
    for (int h = 0; h < 8; h++) {
        size_t off = ((size_t)((b << 3) + h)) * 65536 + (qr << 8) + tid;
        s += __half2float(g_attn16[off]) + __half2float(g_attn16[SZ_ATTN + off]);
    }
    s *= 0.125f;
    __shared__ float red[8];
    float m = s;
    for (int o = 16; o > 0; o >>= 1) m = fmaxf(m, __shfl_xor_sync(0xffffffffu, m, o));
    if ((tid & 31) == 0) red[tid >> 5] = m;
    __syncthreads();
    m = red[0];
#pragma unroll
    for (int w = 1; w < 8; w++) m = fmaxf(m, red[w]);
    float ex = __expf(s - m);
    float sum = ex;
    __syncthreads();
    for (int o = 16; o > 0; o >>= 1) sum += __shfl_xor_sync(0xffffffffu, sum, o);
    if ((tid & 31) == 0) red[tid >> 5] = sum;
    __syncthreads();
    sum = red[0] + red[1] + red[2] + red[3] + red[4] + red[5] + red[6] + red[7];
    out[(size_t)bq * 256 + tid] = ex / sum;
}

// ---------------- dispatch / loss -----------------------------------------------
__global__ __launch_bounds__(256) void dispatch_k() {
    __shared__ int   s_cnt[8];
    __shared__ float s_imp[8];
    __shared__ int   s_base[8];
    int tid = threadIdx.x;
    if (tid < 8) { s_cnt[tid] = 0; s_imp[tid] = 0.f; }
    __syncthreads();
    int t = blockIdx.x * 256 + tid;
    float p[8];
#pragma unroll
    for (int e = 0; e < 8; e++) { p[e] = g_probs[t * 8 + e]; atomicAdd(&s_imp[e], p[e]); }
    int e1 = 0; float v1 = p[0];
#pragma unroll
    for (int e = 1; e < 8; e++) if (p[e] > v1) { v1 = p[e]; e1 = e; }
    int e2 = -1; float v2 = -1e30f;
#pragma unroll
    for (int e = 0; e < 8; e++) if (e != e1 && p[e] > v2) { v2 = p[e]; e2 = e; }
    int lp1 = atomicAdd(&s_cnt[e1], 1);
    int lp2 = atomicAdd(&s_cnt[e2], 1);
    __syncthreads();
    if (tid < 8) {
        s_base[tid] = atomicAdd(&g_cnt[tid], s_cnt[tid]);
        atomicAdd(&g_imp[tid], s_imp[tid]);
    }
    __syncthreads();
    g_perm[e1 * NA + s_base[e1] + lp1] = t * 2;
    g_perm[e2 * NA + s_base[e2] + lp2] = t * 2 + 1;
    g_gate[t * 2]     = v1;
    g_gate[t * 2 + 1] = v2;
}

__global__ void loss_k(float* out_loss) {
    int tid = threadIdx.x;
    float v = 0.f;
    if (tid < 8)
        v = 8.f * ((float)g_cnt[tid] * (1.f / 8192.f)) * (g_imp[tid] * (1.f / 8192.f));
    for (int o = 16; o > 0; o >>= 1) v += __shfl_xor_sync(0xffffffffu, v, o);
    if (tid == 0) out_loss[0] += v;
    if (tid < 8) { g_cnt[tid] = 0; g_imp[tid] = 0.f; }
}

// ---------------- fv + logits ---------------------------------------------------
__global__ __launch_bounds__(512) void fv2_k(const float* __restrict__ part,
                                             float* __restrict__ out_fv) {
    int b = blockIdx.x, d = threadIdx.x;
    float s = 0.f;
#pragma unroll
    for (int seg = 0; seg < 8; seg++)
        s += part[(size_t)(b * 8 + seg) * 512 + d];
    s *= (1.f / 256.f);
    g_fv[b * 512 + d] = s;
    out_fv[b * 512 + d] = s;
}
__global__ __launch_bounds__(512) void logits_k(const float* __restrict__ W,
                                                const float* __restrict__ bias,
                                                float* __restrict__ out) {
    __shared__ float sf[512];
    int b = blockIdx.x, n = threadIdx.x;
    sf[n] = g_fv[b * 512 + n];
    __syncthreads();
    float acc = 0.f;
    for (int k = 0; k < 512; k++) acc += sf[k] * W[k * 512 + n];
    out[b * 512 + n] = acc + bias[n];
}

// ---------------- host launch ---------------------------------------------------
extern "C" void kernel_launch(void* const* d_in, const int* in_sizes, int n_in,
                              void* d_out, int out_size) {
    const float* x     = (const float*)d_in[0];
    const float* pe_w  = (const float*)d_in[1];
    const float* pe_b  = (const float*)d_in[2];
    const float* pos   = (const float*)d_in[3];
    const float* ln1_g = (const float*)d_in[4];
    const float* ln1_b = (const float*)d_in[5];
    const float* ln2_g = (const float*)d_in[6];
    const float* ln2_b = (const float*)d_in[7];
    const float* ln3_g = (const float*)d_in[8];
    const float* ln3_b = (const float*)d_in[9];
    const float* wq = (const float*)d_in[10];
    const float* bq = (const float*)d_in[11];
    const float* wk = (const float*)d_in[12];
    const float* bk = (const float*)d_in[13];
    const float* wv = (const float*)d_in[14];
    const float* bv = (const float*)d_in[15];
    const float* wo = (const float*)d_in[16];
    const float* bo = (const float*)d_in[17];
    const float* m1_rw = (const float*)d_in[18];
    const float* m1_rb = (const float*)d_in[19];
    const float* m1_w1 = (const float*)d_in[20];
    const float* m1_b1 = (const float*)d_in[21];
    const float* m1_w2 = (const float*)d_in[22];
    const float* m1_b2 = (const float*)d_in[23];
    const float* m2_rw = (const float*)d_in[24];
    const float* m2_rb = (const float*)d_in[25];
    const float* m2_w1 = (const float*)d_in[26];
    const float* m2_b1 = (const float*)d_in[27];
    const float* m2_w2 = (const float*)d_in[28];
    const float* m2_b2 = (const float*)d_in[29];
    const float* cls_w = (const float*)d_in[30];
    const float* cls_b = (const float*)d_in[31];

    float* out = (float*)d_out;
    float* out_logits = out;
    float* out_fv     = out + 16384;
    float* out_loss   = out + 32768;
    float* out_attnw  = out + 32769;

    float *p_e, *p_attn, *p_contrib, *p_part;
    __half *p_p16, *p_ln16, *p_qkv16, *p_attn16, *p_ctx16, *p_h16;
    __half *p_pew16, *p_wqkv16, *p_wo16;
    __half *p_w1a, *p_w2a, *p_w1b, *p_w2b;
    cudaGetSymbolAddress((void**)&p_e,       g_e);
    cudaGetSymbolAddress((void**)&p_attn,    g_attn);
    cudaGetSymbolAddress((void**)&p_contrib, g_contrib);
    cudaGetSymbolAddress((void**)&p_part,    g_part);
    cudaGetSymbolAddress((void**)&p_p16,     g_p16);
    cudaGetSymbolAddress((void**)&p_ln16,    g_ln16);
    cudaGetSymbolAddress((void**)&p_qkv16,   g_qkv16);
    cudaGetSymbolAddress((void**)&p_attn16,  g_attn16);
    cudaGetSymbolAddress((void**)&p_ctx16,   g_ctx16);
    cudaGetSymbolAddress((void**)&p_h16,     g_h16);
    cudaGetSymbolAddress((void**)&p_pew16,   g_pew16);
    cudaGetSymbolAddress((void**)&p_wqkv16,  g_wqkv16);
    cudaGetSymbolAddress((void**)&p_wo16,    g_wo16);
    cudaGetSymbolAddress((void**)&p_w1a,     g_w1a16);
    cudaGetSymbolAddress((void**)&p_w2a,     g_w2a16);
    cudaGetSymbolAddress((void**)&p_w1b,     g_w1b16);
    cudaGetSymbolAddress((void**)&p_w2b,     g_w2b16);
    float* p_bqkv; cudaGetSymbolAddress((void**)&p_bqkv, g_bqkv);

    // fork: big MoE weight conversions on side stream (overlaps with attention)
    cudaEventRecord(g_ss.fork, 0);
    cudaStreamWaitEvent(g_ss.s, g_ss.fork, 0);
    conv4_k<<<dim3(8192, 1, 4), 256, 0, g_ss.s>>>(
        m1_w1, m1_w2, m2_w1, m2_w2, p_w1a, p_w2a, p_w1b, p_w2b, SZ_W);
    cudaEventRecord(g_ss.join, g_ss.s);

    // PE dependencies first so the PE GEMM can start ASAP
    patch_k<<<NTOK, 256>>>(x);
    convpe_k<<<(NPDP * ND / 4 + 255) / 256, 256>>>(pe_w);
    mm_k<M_PE><<<dim3(4, 64), 256>>>(p_p16, p_pew16, pe_b, pos, p_e);

    // attention-weight conversions + bias gather (needed only by QKV, later)
    bqkv_k<<<6, 256>>>(bq, bk, bv, out_loss);
    conv4_k<<<dim3(256, 1, 4), 256>>>(
        wq, wk, wv, wo,
        p_wqkv16, p_wqkv16 + 2 * SZ_DD, p_wqkv16 + 4 * SZ_DD, p_wo16, SZ_DD);

    ln_k<<<NTOK, 128>>>(p_e, ln1_g, ln1_b, p_ln16);
    mm_k<M_QKV><<<dim3(4, 64, 3), 256>>>(p_ln16, p_wqkv16, p_bqkv, nullptr, p_qkv16);
    mm_k<M_SC><<<dim3(4, 2, 256), 256>>>(p_qkv16, p_qkv16 + 2 * SZ_LN,
                                         nullptr, nullptr, p_attn);
    softmax_attn_k<<<8192, 256>>>();
    mm_k<M_AV><<<dim3(1, 2, 256), 256>>>(p_attn16, p_qkv16 + 4 * SZ_LN,
                                         nullptr, nullptr, p_ctx16);
    mm_k<M_PROJ><<<dim3(4, 64), 256>>>(p_ctx16, p_wo16, bo, p_e, p_e);
    attnw_k<<<NTOK, 256>>>(out_attnw);

    // MoE layer 1
    ln_k<<<NTOK, 128>>>(p_e, ln2_g, ln2_b, p_ln16);
    router_k<<<1024, 256>>>(p_ln16, m1_rw, m1_rb);
    dispatch_k<<<32, 256>>>();
    cudaStreamWaitEvent(0, g_ss.join, 0);
    mm_k<M_FF1><<<dim3(16, 64, 8), 256>>>(p_ln16, p_w1a, m1_b1, nullptr, p_h16);
    mm_k<M_FF2><<<dim3(4, 64, 8), 256>>>(p_h16, p_w2a, m1_b2, nullptr, p_contrib);

    // combine + LN3 fused; o1 never materialized
    cln_k<<<NTOK, 128>>>(ln3_g, ln3_b, p_ln16);
    loss_k<<<1, 32>>>(out_loss);

    // MoE layer 2
    router_k<<<1024, 256>>>(p_ln16, m2_rw, m2_rb);
    dispatch_k<<<32, 256>>>();
    mm_k<M_FF1><<<dim3(16, 64, 8), 256>>>(p_ln16, p_w1b, m2_b1, nullptr, p_h16);
    mm_k<M_FF2><<<dim3(4, 64, 8), 256>>>(p_h16, p_w2b, m2_b2, nullptr, p_contrib);

    // layer-2 combine fused into fv partials; o2 never materialized
    fvc_k<<<dim3(NB, 8), 512>>>(p_part);
    loss_k<<<1, 32>>>(out_loss);
    fv2_k<<<NB, 512>>>(p_part, out_fv);
    logits_k<<<NB, 512>>>(cls_w, cls_b, out_logits);
}

// round 13
// speedup vs baseline: 1.1650x; 1.0012x over previous
#include <cuda_runtime.h>
#include <cuda_fp16.h>
#include <math.h>
#include <stdint.h>

#define NB   32
#define NS   256
#define ND   512
#define NH   8
#define NE   8
#define NHID 2048
#define NPD  588
#define NPDP 608
#define NTOK 8192
#define NA   16384

#define SZ_LN   ((size_t)NTOK * ND)
#define SZ_P    ((size_t)NTOK * NPDP)
#define SZ_ATTN ((size_t)NB * NH * NS * NS)
#define SZ_H    ((size_t)NA * NHID)
#define SZ_W    ((size_t)NE * ND * NHID)
#define SZ_DD   ((size_t)ND * ND)

// ---------------- fp32 scratch -------------------------------------------------
__device__ float g_e[NTOK * ND];
__device__ float g_attn[NB * NH * NS * NS];
__device__ float g_probs[NTOK * NE];
__device__ float g_gate[NA];
__device__ int   g_perm[NE * NA];
__device__ int   g_cnt[NE];
__device__ float g_imp[NE];
__device__ float g_contrib[NA * ND];
__device__ float g_part[NB * 8 * ND];
__device__ float g_fv[NB * ND];
__device__ float g_bqkv[3 * ND];

// ---------------- split fp16 buffers (hi at [0], lo at [SIZE] per segment) -----
__device__ __half g_p16[2 * SZ_P];
__device__ __half g_ln16[2 * SZ_LN];
__device__ __half g_qkv16[6 * SZ_LN];
__device__ __half g_attn16[2 * SZ_ATTN];
__device__ __half g_ctx16[2 * SZ_LN];
__device__ __half g_h16[2 * SZ_H];
__device__ __half g_pew16[2 * NPDP * ND];
__device__ __half g_wqkv16[6 * SZ_DD];
__device__ __half g_wo16[2 * SZ_DD];
__device__ __half g_w1a16[2 * SZ_W];
__device__ __half g_w2a16[2 * SZ_W];
__device__ __half g_w1b16[2 * SZ_W];
__device__ __half g_w2b16[2 * SZ_W];

// ---------------- persistent side stream ---------------------------------------
struct SideStream {
    cudaStream_t s;
    cudaEvent_t fork, join;
    SideStream() {
        cudaStreamCreateWithFlags(&s, cudaStreamNonBlocking);
        cudaEventCreateWithFlags(&fork, cudaEventDisableTiming);
        cudaEventCreateWithFlags(&join, cudaEventDisableTiming);
    }
};
static SideStream g_ss;

__device__ __forceinline__ float gelu_exact(float v) {
    return 0.5f * v * (1.0f + erff(v * 0.70710678118654752440f));
}
__device__ __forceinline__ void split2(float v0, float v1, __half* oh, __half* ol) {
    __half h0 = __float2half_rn(v0), h1 = __float2half_rn(v1);
    *(__half2*)oh = __halves2half2(h0, h1);
    *(__half2*)ol = __halves2half2(__float2half_rn(v0 - __half2float(h0)),
                                   __float2half_rn(v1 - __half2float(h1)));
}

// ---------------- mma.sync helpers ----------------------------------------------
__device__ __forceinline__ void ldsm4(unsigned* r, unsigned addr) {
    asm volatile("ldmatrix.sync.aligned.m8n8.x4.shared.b16 {%0,%1,%2,%3}, [%4];\n"
        : "=r"(r[0]), "=r"(r[1]), "=r"(r[2]), "=r"(r[3]) : "r"(addr));
}
__device__ __forceinline__ void ldsm4t(unsigned* r, unsigned addr) {
    asm volatile("ldmatrix.sync.aligned.m8n8.x4.trans.shared.b16 {%0,%1,%2,%3}, [%4];\n"
        : "=r"(r[0]), "=r"(r[1]), "=r"(r[2]), "=r"(r[3]) : "r"(addr));
}
__device__ __forceinline__ void mma16816(float* c, const unsigned* a, const unsigned* b) {
    asm volatile("mma.sync.aligned.m16n8k16.row.col.f32.f16.f16.f32 "
        "{%0,%1,%2,%3}, {%4,%5,%6,%7}, {%8,%9}, {%0,%1,%2,%3};\n"
        : "+f"(c[0]), "+f"(c[1]), "+f"(c[2]), "+f"(c[3])
        : "r"(a[0]), "r"(a[1]), "r"(a[2]), "r"(a[3]), "r"(b[0]), "r"(b[1]));
}
__device__ __forceinline__ void cpa16(unsigned dst, const void* src, bool p) {
    int sz = p ? 16 : 0;
    asm volatile("cp.async.cg.shared.global [%0], [%1], 16, %2;\n"
        :: "r"(dst), "l"(src), "r"(sz));
}

// ---------------- modes --------------------------------------------------------
#define M_PE   0
#define M_QKV  1
#define M_PROJ 2
#define M_SC   3
#define M_AV   4
#define M_FF1  5
#define M_FF2  6

template <int MODE>
__global__ __launch_bounds__(256) void mm_k(
    const __half* __restrict__ Ag, const __half* __restrict__ Bg,
    const float* __restrict__ bias, const float* __restrict__ extra,
    void* __restrict__ Og)
{
    constexpr int K   = (MODE == M_PE) ? NPDP : (MODE == M_SC) ? 64 :
                        (MODE == M_AV) ? 256 : (MODE == M_FF2) ? 2048 : 512;
    constexpr int LDA = K;
    constexpr int LDB = (MODE == M_SC || MODE == M_AV) ? 64 :
                        (MODE == M_FF1) ? 2048 : 512;
    constexpr bool NT = (MODE == M_SC);
    constexpr bool GATHER = (MODE == M_FF1) || (MODE == M_FF2);
    constexpr int SHIFT = (MODE == M_FF1) ? 1 : 0;
    constexpr int BN = (MODE == M_AV || MODE == M_SC) ? 64 : 128;
    constexpr int WN = BN / 4;
    constexpr int NF = WN / 8;
    constexpr int KT = K / 16;
    constexpr size_t ALO =
        (MODE == M_PE)  ? SZ_P :
        (MODE == M_SC || MODE == M_QKV || MODE == M_PROJ || MODE == M_FF1) ? SZ_LN :
        (MODE == M_AV)  ? SZ_ATTN : SZ_H;
    constexpr size_t BLO =
        (MODE == M_PE)  ? (size_t)NPDP * ND :
        (MODE == M_QKV || MODE == M_PROJ) ? SZ_DD :
        (MODE == M_SC || MODE == M_AV) ? SZ_LN : SZ_W;
    constexpr size_t OLO =
        (MODE == M_QKV || MODE == M_AV) ? SZ_LN : SZ_H;
    constexpr int AST = 128 * 24;
    constexpr int BST = NT ? BN * 24 : 16 * BN;

    __shared__ __align__(16) __half As[2][2][AST];
    __shared__ __align__(16) __half Bs[2][2][BST];
    __shared__ int s_idx[128];

    int tid = threadIdx.x;
    int bz = blockIdx.z;
    int row0 = blockIdx.y * 128, col0 = blockIdx.x * BN;

    const __half* Ah = Ag;
    const __half* Bh = Bg;
    if (MODE == M_SC)  { Ah += (size_t)bz * 256 * 64; Bh += (size_t)bz * 256 * 64; }
    if (MODE == M_AV)  { Ah += (size_t)bz * 65536;    Bh += (size_t)bz * 256 * 64; }
    if (MODE == M_QKV) { Bh += (size_t)bz * 2 * SZ_DD; }
    if (MODE == M_FF1) { Bh += (size_t)bz * 512 * 2048; }
    if (MODE == M_FF2) { Bh += (size_t)bz * 2048 * 512; }
    const __half* Al = Ah + ALO;
    const __half* Bl = Bh + BLO;

    if (GATHER) {
        int cnt = g_cnt[bz];
        if (row0 >= cnt) return;
        if (tid < 128) {
            int r = row0 + tid;
            s_idx[tid] = (r < cnt) ? g_perm[bz * NA + r] : -1;
        }
        __syncthreads();
    }

    int a_row = tid >> 1, a_ch = tid & 1;
    unsigned a_dst = (unsigned)((a_row * 24 + a_ch * 8) * 2);
    const __half* a_srch; const __half* a_srcl; bool a_pred;
    if (GATHER) {
        int a = s_idx[a_row];
        a_pred = (a >= 0);
        size_t off = a_pred ? (size_t)(a >> SHIFT) * LDA + a_ch * 8 : 0;
        a_srch = Ah + off; a_srcl = Al + off;
    } else {
        a_pred = true;
        size_t off = (size_t)(row0 + a_row) * LDA + a_ch * 8;
        a_srch = Ah + off; a_srcl = Al + off;
    }
    unsigned b_dst = 0; const __half* b_srch = Bh; const __half* b_srcl = Bh;
    bool b_val;
    if (!NT) {
        b_val = tid < (16 * BN / 8);
        int row = tid / (BN / 8), cn = tid % (BN / 8);
        int sw = cn ^ (row & 7);
        b_dst = (unsigned)((row * BN + sw * 8) * 2);
        size_t off = (size_t)row * LDB + col0 + cn * 8;
        b_srch = Bh + off; b_srcl = Bl + off;
    } else {
        b_val = tid < (BN * 2);
        int nr = tid >> 1, ch = tid & 1;
        b_dst = (unsigned)((nr * 24 + ch * 8) * 2);
        size_t off = (size_t)(col0 + nr) * LDB + ch * 8;
        b_srch = Bh + off; b_srcl = Bl + off;
    }

    unsigned as_base = (unsigned)__cvta_generic_to_shared(&As[0][0][0]);
    unsigned bs_base = (unsigned)__cvta_generic_to_shared(&Bs[0][0][0]);

    auto issue = [&](int kt, int buf) {
        unsigned abh = as_base + (buf * 2 + 0) * AST * 2;
        unsigned abl = as_base + (buf * 2 + 1) * AST * 2;
        cpa16(abh + a_dst, a_srch + (size_t)kt * 16, a_pred);
        cpa16(abl + a_dst, a_srcl + (size_t)kt * 16, a_pred);
        if (b_val) {
            unsigned bbh = bs_base + (buf * 2 + 0) * BST * 2;
            unsigned bbl = bs_base + (buf * 2 + 1) * BST * 2;
            size_t off = NT ? (size_t)kt * 16 : (size_t)kt * 16 * LDB;
            cpa16(bbh + b_dst, b_srch + off, true);
            cpa16(bbl + b_dst, b_srcl + off, true);
        }
        asm volatile("cp.async.commit_group;\n");
    };

    int lane = tid & 31;
    int warp = tid >> 5;
    int wm = warp >> 2, wn = warp & 3;

    float acc[4][NF][4];
#pragma unroll
    for (int i = 0; i < 4; i++)
#pragma unroll
        for (int j = 0; j < NF; j++)
#pragma unroll
            for (int t = 0; t < 4; t++) acc[i][j][t] = 0.f;

    issue(0, 0);
    // single-barrier pipeline: wait(group kt) -> barrier (publishes data to all
    // warps AND retires previous compute on buf^1) -> prefetch kt+1 into buf^1
    // -> compute buf. Prefetch of kt+1 fully overlaps compute of kt.
#pragma unroll 1
    for (int kt = 0; kt < KT; kt++) {
        int buf = kt & 1;
        asm volatile("cp.async.wait_group 0;\n");
        __syncthreads();
        if (kt + 1 < KT) issue(kt + 1, buf ^ 1);
        unsigned abh = as_base + (buf * 2 + 0) * AST * 2;
        unsigned abl = as_base + (buf * 2 + 1) * AST * 2;
        unsigned bbh = bs_base + (buf * 2 + 0) * BST * 2;
        unsigned bbl = bs_base + (buf * 2 + 1) * BST * 2;

        unsigned ah[4][4], al[4][4];
#pragma unroll
        for (int i = 0; i < 4; i++) {
            int m = wm * 64 + i * 16 + (lane & 15);
            int ch = lane >> 4;
            unsigned ad = (unsigned)((m * 24 + ch * 8) * 2);
            ldsm4(ah[i], abh + ad);
            ldsm4(al[i], abl + ad);
        }
        unsigned brh[2 * NF], brl[2 * NF];
#pragma unroll
        for (int jj = 0; jj < NF / 2; jj++) {
            int n0 = wn * WN + jj * 16;
            if (!NT) {
                int k = lane & 15;
                int cn = (n0 >> 3) + (lane >> 4);
                int sw = cn ^ (k & 7);
                unsigned bd = (unsigned)((k * BN + sw * 8) * 2);
                ldsm4t(&brh[jj * 4], bbh + bd);
                ldsm4t(&brl[jj * 4], bbl + bd);
            } else {
                int n = n0 + ((lane >> 4) << 3) + (lane & 7);
                int ch = (lane >> 3) & 1;
                unsigned bd = (unsigned)((n * 24 + ch * 8) * 2);
                ldsm4(&brh[jj * 4], bbh + bd);
                ldsm4(&brl[jj * 4], bbl + bd);
            }
        }
#pragma unroll
        for (int i = 0; i < 4; i++)
#pragma unroll
            for (int j = 0; j < NF; j++) {
                mma16816(acc[i][j], ah[i], &brh[j * 2]);
                mma16816(acc[i][j], al[i], &brh[j * 2]);
                mma16816(acc[i][j], ah[i], &brl[j * 2]);
            }
    }

    int rl = lane >> 2, cp2 = (lane & 3) * 2;
#pragma unroll
    for (int i = 0; i < 4; i++) {
#pragma unroll
        for (int hh = 0; hh < 2; hh++) {
            int rr = wm * 64 + i * 16 + rl + hh * 8;
            int r = row0 + rr;
            int aidx = 0;
            if (GATHER) {
                aidx = s_idx[rr];
                if (aidx < 0) continue;
            }
#pragma unroll
            for (int j = 0; j < NF; j++) {
                int c = col0 + wn * WN + j * 8 + cp2;
                float v0 = acc[i][j][hh * 2 + 0];
                float v1 = acc[i][j][hh * 2 + 1];
                if (MODE == M_PE) {
                    float* O = (float*)Og;
                    v0 += bias[c]     + extra[(size_t)(r & 255) * 512 + c];
                    v1 += bias[c + 1] + extra[(size_t)(r & 255) * 512 + c + 1];
                    O[(size_t)r * 512 + c] = v0;
                    O[(size_t)r * 512 + c + 1] = v1;
                } else if (MODE == M_QKV) {
                    __half* O = (__half*)Og + (size_t)bz * 2 * SZ_LN;
                    const float* bi = bias + bz * 512;
                    v0 += bi[c]; v1 += bi[c + 1];
                    int b = r >> 8, s = r & 255, hd = c >> 6, ii = c & 63;
                    size_t o = (size_t)(((b << 3) + hd) * 256 + s) * 64 + ii;
                    split2(v0, v1, O + o, O + OLO + o);
                } else if (MODE == M_PROJ) {
                    float* O = (float*)Og;
                    v0 += bias[c]     + extra[(size_t)r * 512 + c];
                    v1 += bias[c + 1] + extra[(size_t)r * 512 + c + 1];
                    O[(size_t)r * 512 + c] = v0;
                    O[(size_t)r * 512 + c + 1] = v1;
                } else if (MODE == M_SC) {
                    float* O = (float*)Og + (size_t)bz * 65536;
                    O[(size_t)r * 256 + c] = v0 * 0.125f;
                    O[(size_t)r * 256 + c + 1] = v1 * 0.125f;
                } else if (MODE == M_AV) {
                    __half* O = (__half*)Og;
                    int b = bz >> 3, hd = bz & 7;
                    size_t o = (size_t)((b << 8) + r) * 512 + (hd << 6) + c;
                    split2(v0, v1, O + o, O + OLO + o);
                } else if (MODE == M_FF1) {
                    __half* O = (__half*)Og;
                    const float* bi = bias + bz * 2048;
                    v0 = gelu_exact(v0 + bi[c]);
                    v1 = gelu_exact(v1 + bi[c + 1]);
                    size_t o = (size_t)aidx * 2048 + c;
                    split2(v0, v1, O + o, O + OLO + o);
                } else {
                    float* O = (float*)Og;
                    const float* bi = bias + bz * 512;
                    O[(size_t)aidx * 512 + c] = v0 + bi[c];
                    O[(size_t)aidx * 512 + c + 1] = v1 + bi[c + 1];
                }
            }
        }
    }
}

// ---------------- conversions ---------------------------------------------------
struct __align__(8) h2x2 { __half2 a, b; };

__device__ __forceinline__ void conv_elem4(const float* in, __half* outh, size_t n,
                                           size_t i) {
    float4 f = *(const float4*)(in + i);
    h2x2 H, L;
    H.a = __floats2half2_rn(f.x, f.y);
    H.b = __floats2half2_rn(f.z, f.w);
    float2 f0 = __half22float2(H.a), f1 = __half22float2(H.b);
    L.a = __floats2half2_rn(f.x - f0.x, f.y - f0.y);
    L.b = __floats2half2_rn(f.z - f1.x, f.w - f1.y);
    *(h2x2*)(outh + i) = H;
    *(h2x2*)(outh + n + i) = L;
}

__global__ __launch_bounds__(256) void conv4_k(
    const float* __restrict__ s0, const float* __restrict__ s1,
    const float* __restrict__ s2, const float* __restrict__ s3,
    __half* __restrict__ d0, __half* __restrict__ d1,
    __half* __restrict__ d2, __half* __restrict__ d3, size_t n)
{
    const float* src = (blockIdx.z == 0) ? s0 : (blockIdx.z == 1) ? s1 :
                       (blockIdx.z == 2) ? s2 : s3;
    __half* dst = (blockIdx.z == 0) ? d0 : (blockIdx.z == 1) ? d1 :
                  (blockIdx.z == 2) ? d2 : d3;
    size_t i = ((size_t)blockIdx.x * 256 + threadIdx.x) * 4;
    if (i < n) conv_elem4(src, dst, n, i);
}

__global__ __launch_bounds__(256) void convpe_k(const float* __restrict__ w) {
    int i = (blockIdx.x * 256 + threadIdx.x) * 4;
    if (i >= NPDP * ND) return;
    int j = i >> 9;
    float4 f = make_float4(0.f, 0.f, 0.f, 0.f);
    if (j < NPD) f = *(const float4*)(w + i);
    h2x2 H, L;
    H.a = __floats2half2_rn(f.x, f.y);
    H.b = __floats2half2_rn(f.z, f.w);
    float2 f0 = __half22float2(H.a), f1 = __half22float2(H.b);
    L.a = __floats2half2_rn(f.x - f0.x, f.y - f0.y);
    L.b = __floats2half2_rn(f.z - f1.x, f.w - f1.y);
    *(h2x2*)(g_pew16 + i) = H;
    *(h2x2*)(g_pew16 + NPDP * ND + i) = L;
}

// bqkv gather + global init (counters, loss)
__global__ void bqkv_k(const float* __restrict__ bq, const float* __restrict__ bk,
                       const float* __restrict__ bv, float* out_loss) {
    int i = blockIdx.x * 256 + threadIdx.x;
    if (blockIdx.x == 0 && threadIdx.x < 8) { g_cnt[threadIdx.x] = 0; g_imp[threadIdx.x] = 0.f; }
    if (i == 0) out_loss[0] = 0.f;
    if (i >= 1536) return;
    g_bqkv[i] = (i < 512) ? bq[i] : (i < 1024) ? bk[i - 512] : bv[i - 1024];
}

// ---------------- patch gather (coalesced, smem-staged) -------------------------
__global__ __launch_bounds__(256) void patch_k(const float* __restrict__ x) {
    __shared__ float sp[NPD];
    int t = blockIdx.x;
    int b = t >> 8, s = t & 255;
    int hi = s >> 4, wi = s & 15;
    int tid = threadIdx.x;
    const float* xb = x + ((size_t)b * 3 * 224 + hi * 14) * 224 + wi * 14;
    for (int idx = tid; idx < NPD; idx += 256) {
        int c = idx / 196, rem = idx % 196;
        int p1 = rem / 14, p2 = rem % 14;
        float f = xb[((size_t)c * 224 + p1) * 224 + p2];
        sp[(p1 * 14 + p2) * 3 + c] = f;
    }
    __syncthreads();
    size_t base = (size_t)t * NPDP;
    for (int j = tid; j < NPDP; j += 256) {
        float f = (j < NPD) ? sp[j] : 0.f;
        __half h = __float2half_rn(f);
        g_p16[base + j] = h;
        g_p16[SZ_P + base + j] = __float2half_rn(f - __half2float(h));
    }
}

// ---------------- LN body (fp16 split out only) ---------------------------------
__device__ __forceinline__ void ln_body(
    int row, int tid, float4 v,
    const float* __restrict__ gw, const float* __restrict__ bw,
    __half* __restrict__ out16)
{
    float s = v.x + v.y + v.z + v.w;
    float q = v.x * v.x + v.y * v.y + v.z * v.z + v.w * v.w;
    __shared__ float ss[4], sq[4];
    for (int o = 16; o > 0; o >>= 1) {
        s += __shfl_xor_sync(0xffffffffu, s, o);
        q += __shfl_xor_sync(0xffffffffu, q, o);
    }
    if ((tid & 31) == 0) { ss[tid >> 5] = s; sq[tid >> 5] = q; }
    __syncthreads();
    s = ss[0] + ss[1] + ss[2] + ss[3];
    q = sq[0] + sq[1] + sq[2] + sq[3];
    float mean = s * (1.f / 512.f);
    float var  = q * (1.f / 512.f) - mean * mean;
    float inv  = rsqrtf(var + 1e-5f);
    float4 g4 = ((const float4*)gw)[tid];
    float4 b4 = ((const float4*)bw)[tid];
    float4 o;
    o.x = (v.x - mean) * inv * g4.x + b4.x;
    o.y = (v.y - mean) * inv * g4.y + b4.y;
    o.z = (v.z - mean) * inv * g4.z + b4.z;
    o.w = (v.w - mean) * inv * g4.w + b4.w;
    size_t base = (size_t)row * 512 + tid * 4;
    split2(o.x, o.y, out16 + base,     out16 + SZ_LN + base);
    split2(o.z, o.w, out16 + base + 2, out16 + SZ_LN + base + 2);
}

__global__ __launch_bounds__(128) void ln_k(
    const float* __restrict__ in, const float* __restrict__ gw,
    const float* __restrict__ bw, __half* __restrict__ out16)
{
    int row = blockIdx.x, tid = threadIdx.x;
    float4 v = ((const float4*)(in + (size_t)row * 512))[tid];
    ln_body(row, tid, v, gw, bw, out16);
}

__global__ __launch_bounds__(128) void cln_k(
    const float* __restrict__ gw, const float* __restrict__ bw,
    __half* __restrict__ out16)
{
    int row = blockIdx.x, tid = threadIdx.x;
    float g1 = g_gate[2 * row], g2 = g_gate[2 * row + 1];
    float4 a = ((const float4*)(g_contrib + (size_t)(2 * row) * 512))[tid];
    float4 b = ((const float4*)(g_contrib + (size_t)(2 * row + 1) * 512))[tid];
    float4 v;
    v.x = g1 * a.x + g2 * b.x; v.y = g1 * a.y + g2 * b.y;
    v.z = g1 * a.z + g2 * b.z; v.w = g1 * a.w + g2 * b.w;
    ln_body(row, tid, v, gw, bw, out16);
}

__global__ __launch_bounds__(512) void fvc_k(float* __restrict__ part) {
    int b = blockIdx.x, seg = blockIdx.y, d = threadIdx.x;
    int t0 = b * 256 + seg * 32;
    float s = 0.f;
    for (int ss = 0; ss < 32; ss++) {
        int t = t0 + ss;
        float g1 = g_gate[2 * t], g2 = g_gate[2 * t + 1];
        s += g1 * g_contrib[(size_t)(2 * t) * 512 + d]
           + g2 * g_contrib[(size_t)(2 * t + 1) * 512 + d];
    }
    part[(size_t)(b * 8 + seg) * 512 + d] = s;
}

// ---------------- MoE router ----------------------------------------------------
__global__ __launch_bounds__(256) void router_k(const __half* __restrict__ xin,
                                                const float* __restrict__ rw,
                                                const float* __restrict__ rb) {
    __shared__ float s_rw[8][512];
    __shared__ float s_rb[8];
    int tid = threadIdx.x;
    for (int i = tid; i < 4096; i += 256) s_rw[i >> 9][i & 511] = rw[(i & 511) * 8 + (i >> 9)];
    if (tid < 8) s_rb[tid] = rb[tid];
    __syncthreads();
    int t = (blockIdx.x << 3) + (tid >> 5);
    int lane = tid & 31;
    const __half* xh = xin + (size_t)t * 512;
    const __half* xl = xh + SZ_LN;
    float acc[8] = {};
    for (int k = lane * 2; k < 512; k += 64) {
        __half2 h = *(const __half2*)(xh + k);
        __half2 l = *(const __half2*)(xl + k);
        float2 hf = __half22float2(h), lf = __half22float2(l);
        float x0 = hf.x + lf.x, x1 = hf.y + lf.y;
#pragma unroll
        for (int e = 0; e < 8; e++)
            acc[e] += x0 * s_rw[e][k] + x1 * s_rw[e][k + 1];
    }
#pragma unroll
    for (int e = 0; e < 8; e++)
        for (int o = 16; o > 0; o >>= 1) acc[e] += __shfl_xor_sync(0xffffffffu, acc[e], o);
    if (lane == 0) {
        float mx = -1e30f;
#pragma unroll
        for (int e = 0; e < 8; e++) { acc[e] += s_rb[e]; mx = fmaxf(mx, acc[e]); }
        float sum = 0.f;
#pragma unroll
        for (int e = 0; e < 8; e++) { acc[e] = __expf(acc[e] - mx); sum += acc[e]; }
        float inv = 1.f / sum;
#pragma unroll
        for (int e = 0; e < 8; e++) g_probs[t * 8 + e] = acc[e] * inv;
    }
}

// ---------------- softmax over attn rows ----------------------------------------
__global__ __launch_bounds__(256) void softmax_attn_k() {
    int row  = (blockIdx.x << 3) + (threadIdx.x >> 5);
    int lane = threadIdx.x & 31;
    const float4* p = (const float4*)(g_attn + (size_t)row * 256);
    float4 a = p[lane], b = p[lane + 32];
    float m = fmaxf(fmaxf(fmaxf(a.x, a.y), fmaxf(a.z, a.w)),
                    fmaxf(fmaxf(b.x, b.y), fmaxf(b.z, b.w)));
    for (int o = 16; o > 0; o >>= 1) m = fmaxf(m, __shfl_xor_sync(0xffffffffu, m, o));
    a.x = __expf(a.x - m); a.y = __expf(a.y - m);
    a.z = __expf(a.z - m); a.w = __expf(a.w - m);
    b.x = __expf(b.x - m); b.y = __expf(b.y - m);
    b.z = __expf(b.z - m); b.w = __expf(b.w - m);
    float s = a.x + a.y + a.z + a.w + b.x + b.y + b.z + b.w;
    for (int o = 16; o > 0; o >>= 1) s += __shfl_xor_sync(0xffffffffu, s, o);
    float inv = 1.f / s;
    a.x *= inv; a.y *= inv; a.z *= inv; a.w *= inv;
    b.x *= inv; b.y *= inv; b.z *= inv; b.w *= inv;
    size_t base = (size_t)row * 256;
    split2(a.x, a.y, g_attn16 + base + lane * 4,     g_attn16 + SZ_ATTN + base + lane * 4);
    split2(a.z, a.w, g_attn16 + base + lane * 4 + 2, g_attn16 + SZ_ATTN + base + lane * 4 + 2);
    split2(b.x, b.y, g_attn16 + base + 128 + lane * 4,     g_attn16 + SZ_ATTN + base + 128 + lane * 4);
    split2(b.z, b.w, g_attn16 + base + 128 + lane * 4 + 2, g_attn16 + SZ_ATTN + base + 128 + lane * 4 + 2);
}

// ---------------- attn_w --------------------------------------------------------
__global__ __launch_bounds__(256) void attnw_k(float* __restrict__ out) {
    int bq = blockIdx.x, tid = threadIdx.x;
    int b = bq >> 8, qr = bq & 255;
    float s = 0.f;
#pragma unroll
    for (int h = 0; h < 8; h++) {
        size_t off = ((size_t)((b << 3) + h)) * 65536 + (qr << 8) + tid;
        s += __half2float(g_attn16[off]) + __half2float(g_attn16[SZ_ATTN + off]);
    }
    s *= 0.125f;
    __shared__ float red[8];
    float m = s;
    for (int o = 16; o > 0; o >>= 1) m = fmaxf(m, __shfl_xor_sync(0xffffffffu, m, o));
    if ((tid & 31) == 0) red[tid >> 5] = m;
    __syncthreads();
    m = red[0];
#pragma unroll
    for (int w = 1; w < 8; w++) m = fmaxf(m, red[w]);
    float ex = __expf(s - m);
    float sum = ex;
    __syncthreads();
    for (int o = 16; o > 0; o >>= 1) sum += __shfl_xor_sync(0xffffffffu, sum, o);
    if ((tid & 31) == 0) red[tid >> 5] = sum;
    __syncthreads();
    sum = red[0] + red[1] + red[2] + red[3] + red[4] + red[5] + red[6] + red[7];
    out[(size_t)bq * 256 + tid] = ex / sum;
}

// ---------------- dispatch / loss -----------------------------------------------
__global__ __launch_bounds__(256) void dispatch_k() {
    __shared__ int   s_cnt[8];
    __shared__ float s_imp[8];
    __shared__ int   s_base[8];
    int tid = threadIdx.x;
    if (tid < 8) { s_cnt[tid] = 0; s_imp[tid] = 0.f; }
    __syncthreads();
    int t = blockIdx.x * 256 + tid;
    float p[8];
#pragma unroll
    for (int e = 0; e < 8; e++) { p[e] = g_probs[t * 8 + e]; atomicAdd(&s_imp[e], p[e]); }
    int e1 = 0; float v1 = p[0];
#pragma unroll
    for (int e = 1; e < 8; e++) if (p[e] > v1) { v1 = p[e]; e1 = e; }
    int e2 = -1; float v2 = -1e30f;
#pragma unroll
    for (int e = 0; e < 8; e++) if (e != e1 && p[e] > v2) { v2 = p[e]; e2 = e; }
    int lp1 = atomicAdd(&s_cnt[e1], 1);
    int lp2 = atomicAdd(&s_cnt[e2], 1);
    __syncthreads();
    if (tid < 8) {
        s_base[tid] = atomicAdd(&g_cnt[tid], s_cnt[tid]);
        atomicAdd(&g_imp[tid], s_imp[tid]);
    }
    __syncthreads();
    g_perm[e1 * NA + s_base[e1] + lp1] = t * 2;
    g_perm[e2 * NA + s_base[e2] + lp2] = t * 2 + 1;
    g_gate[t * 2]     = v1;
    g_gate[t * 2 + 1] = v2;
}

__global__ void loss_k(float* out_loss) {
    int tid = threadIdx.x;
    float v = 0.f;
    if (tid < 8)
        v = 8.f * ((float)g_cnt[tid] * (1.f / 8192.f)) * (g_imp[tid] * (1.f / 8192.f));
    for (int o = 16; o > 0; o >>= 1) v += __shfl_xor_sync(0xffffffffu, v, o);
    if (tid == 0) out_loss[0] += v;
    if (tid < 8) { g_cnt[tid] = 0; g_imp[tid] = 0.f; }
}

// ---------------- fv + logits ---------------------------------------------------
__global__ __launch_bounds__(512) void fv2_k(const float* __restrict__ part,
                                             float* __restrict__ out_fv) {
    int b = blockIdx.x, d = threadIdx.x;
    float s = 0.f;
#pragma unroll
    for (int seg = 0; seg < 8; seg++)
        s += part[(size_t)(b * 8 + seg) * 512 + d];
    s *= (1.f / 256.f);
    g_fv[b * 512 + d] = s;
    out_fv[b * 512 + d] = s;
}
__global__ __launch_bounds__(512) void logits_k(const float* __restrict__ W,
                                                const float* __restrict__ bias,
                                                float* __restrict__ out) {
    __shared__ float sf[512];
    int b = blockIdx.x, n = threadIdx.x;
    sf[n] = g_fv[b * 512 + n];
    __syncthreads();
    float acc = 0.f;
    for (int k = 0; k < 512; k++) acc += sf[k] * W[k * 512 + n];
    out[b * 512 + n] = acc + bias[n];
}

// ---------------- host launch ---------------------------------------------------
extern "C" void kernel_launch(void* const* d_in, const int* in_sizes, int n_in,
                              void* d_out, int out_size) {
    const float* x     = (const float*)d_in[0];
    const float* pe_w  = (const float*)d_in[1];
    const float* pe_b  = (const float*)d_in[2];
    const float* pos   = (const float*)d_in[3];
    const float* ln1_g = (const float*)d_in[4];
    const float* ln1_b = (const float*)d_in[5];
    const float* ln2_g = (const float*)d_in[6];
    const float* ln2_b = (const float*)d_in[7];
    const float* ln3_g = (const float*)d_in[8];
    const float* ln3_b = (const float*)d_in[9];
    const float* wq = (const float*)d_in[10];
    const float* bq = (const float*)d_in[11];
    const float* wk = (const float*)d_in[12];
    const float* bk = (const float*)d_in[13];
    const float* wv = (const float*)d_in[14];
    const float* bv = (const float*)d_in[15];
    const float* wo = (const float*)d_in[16];
    const float* bo = (const float*)d_in[17];
    const float* m1_rw = (const float*)d_in[18];
    const float* m1_rb = (const float*)d_in[19];
    const float* m1_w1 = (const float*)d_in[20];
    const float* m1_b1 = (const float*)d_in[21];
    const float* m1_w2 = (const float*)d_in[22];
    const float* m1_b2 = (const float*)d_in[23];
    const float* m2_rw = (const float*)d_in[24];
    const float* m2_rb = (const float*)d_in[25];
    const float* m2_w1 = (const float*)d_in[26];
    const float* m2_b1 = (const float*)d_in[27];
    const float* m2_w2 = (const float*)d_in[28];
    const float* m2_b2 = (const float*)d_in[29];
    const float* cls_w = (const float*)d_in[30];
    const float* cls_b = (const float*)d_in[31];

    float* out = (float*)d_out;
    float* out_logits = out;
    float* out_fv     = out + 16384;
    float* out_loss   = out + 32768;
    float* out_attnw  = out + 32769;

    float *p_e, *p_attn, *p_contrib, *p_part;
    __half *p_p16, *p_ln16, *p_qkv16, *p_attn16, *p_ctx16, *p_h16;
    __half *p_pew16, *p_wqkv16, *p_wo16;
    __half *p_w1a, *p_w2a, *p_w1b, *p_w2b;
    cudaGetSymbolAddress((void**)&p_e,       g_e);
    cudaGetSymbolAddress((void**)&p_attn,    g_attn);
    cudaGetSymbolAddress((void**)&p_contrib, g_contrib);
    cudaGetSymbolAddress((void**)&p_part,    g_part);
    cudaGetSymbolAddress((void**)&p_p16,     g_p16);
    cudaGetSymbolAddress((void**)&p_ln16,    g_ln16);
    cudaGetSymbolAddress((void**)&p_qkv16,   g_qkv16);
    cudaGetSymbolAddress((void**)&p_attn16,  g_attn16);
    cudaGetSymbolAddress((void**)&p_ctx16,   g_ctx16);
    cudaGetSymbolAddress((void**)&p_h16,     g_h16);
    cudaGetSymbolAddress((void**)&p_pew16,   g_pew16);
    cudaGetSymbolAddress((void**)&p_wqkv16,  g_wqkv16);
    cudaGetSymbolAddress((void**)&p_wo16,    g_wo16);
    cudaGetSymbolAddress((void**)&p_w1a,     g_w1a16);
    cudaGetSymbolAddress((void**)&p_w2a,     g_w2a16);
    cudaGetSymbolAddress((void**)&p_w1b,     g_w1b16);
    cudaGetSymbolAddress((void**)&p_w2b,     g_w2b16);
    float* p_bqkv; cudaGetSymbolAddress((void**)&p_bqkv, g_bqkv);

    // fork: big MoE weight conversions on side stream (overlaps with attention)
    cudaEventRecord(g_ss.fork, 0);
    cudaStreamWaitEvent(g_ss.s, g_ss.fork, 0);
    conv4_k<<<dim3(8192, 1, 4), 256, 0, g_ss.s>>>(
        m1_w1, m1_w2, m2_w1, m2_w2, p_w1a, p_w2a, p_w1b, p_w2b, SZ_W);
    cudaEventRecord(g_ss.join, g_ss.s);

    // PE dependencies first so the PE GEMM can start ASAP
    patch_k<<<NTOK, 256>>>(x);
    convpe_k<<<(NPDP * ND / 4 + 255) / 256, 256>>>(pe_w);
    mm_k<M_PE><<<dim3(4, 64), 256>>>(p_p16, p_pew16, pe_b, pos, p_e);

    // attention-weight conversions + bias gather (needed only by QKV, later)
    bqkv_k<<<6, 256>>>(bq, bk, bv, out_loss);
    conv4_k<<<dim3(256, 1, 4), 256>>>(
        wq, wk, wv, wo,
        p_wqkv16, p_wqkv16 + 2 * SZ_DD, p_wqkv16 + 4 * SZ_DD, p_wo16, SZ_DD);

    ln_k<<<NTOK, 128>>>(p_e, ln1_g, ln1_b, p_ln16);
    mm_k<M_QKV><<<dim3(4, 64, 3), 256>>>(p_ln16, p_wqkv16, p_bqkv, nullptr, p_qkv16);
    mm_k<M_SC><<<dim3(4, 2, 256), 256>>>(p_qkv16, p_qkv16 + 2 * SZ_LN,
                                         nullptr, nullptr, p_attn);
    softmax_attn_k<<<8192, 256>>>();
    mm_k<M_AV><<<dim3(1, 2, 256), 256>>>(p_attn16, p_qkv16 + 4 * SZ_LN,
                                         nullptr, nullptr, p_ctx16);
    mm_k<M_PROJ><<<dim3(4, 64), 256>>>(p_ctx16, p_wo16, bo, p_e, p_e);
    attnw_k<<<NTOK, 256>>>(out_attnw);

    // MoE layer 1
    ln_k<<<NTOK, 128>>>(p_e, ln2_g, ln2_b, p_ln16);
    router_k<<<1024, 256>>>(p_ln16, m1_rw, m1_rb);
    dispatch_k<<<32, 256>>>();
    cudaStreamWaitEvent(0, g_ss.join, 0);
    mm_k<M_FF1><<<dim3(16, 64, 8), 256>>>(p_ln16, p_w1a, m1_b1, nullptr, p_h16);
    mm_k<M_FF2><<<dim3(4, 64, 8), 256>>>(p_h16, p_w2a, m1_b2, nullptr, p_contrib);

    // combine + LN3 fused; o1 never materialized
    cln_k<<<NTOK, 128>>>(ln3_g, ln3_b, p_ln16);
    loss_k<<<1, 32>>>(out_loss);

    // MoE layer 2
    router_k<<<1024, 256>>>(p_ln16, m2_rw, m2_rb);
    dispatch_k<<<32, 256>>>();
    mm_k<M_FF1><<<dim3(16, 64, 8), 256>>>(p_ln16, p_w1b, m2_b1, nullptr, p_h16);
    mm_k<M_FF2><<<dim3(4, 64, 8), 256>>>(p_h16, p_w2b, m2_b2, nullptr, p_contrib);

    // layer-2 combine fused into fv partials; o2 never materialized
    fvc_k<<<dim3(NB, 8), 512>>>(p_part);
    loss_k<<<1, 32>>>(out_loss);
    fv2_k<<<NB, 512>>>(p_part, out_fv);
    logits_k<<<NB, 512>>>(cls_w, cls_b, out_logits);
}

// round 15
// speedup vs baseline: 1.1700x; 1.0042x over previous
#include <cuda_runtime.h>
#include <cuda_fp16.h>
#include <math.h>
#include <stdint.h>

#define NB   32
#define NS   256
#define ND   512
#define NH   8
#define NE   8
#define NHID 2048
#define NPD  588
#define NPDP 608
#define NTOK 8192
#define NA   16384

#define SZ_LN   ((size_t)NTOK * ND)
#define SZ_P    ((size_t)NTOK * NPDP)
#define SZ_ATTN ((size_t)NB * NH * NS * NS)
#define SZ_H    ((size_t)NA * NHID)
#define SZ_W    ((size_t)NE * ND * NHID)
#define SZ_DD   ((size_t)ND * ND)

// ---------------- fp32 scratch -------------------------------------------------
__device__ float g_e[NTOK * ND];
__device__ float g_attn[NB * NH * NS * NS];
__device__ float g_probs[NTOK * NE];
__device__ float g_gate[NA];
__device__ int   g_perm[NE * NA];
__device__ int   g_cnt[NE];        // working counter (reset per layer)
__device__ int   g_cnt0[NE];       // layer-1 snapshot
__device__ float g_imp0[NE];       // layer-1 importance
__device__ float g_imp1[NE];       // layer-2 importance
__device__ float g_contrib[NA * ND];
__device__ float g_part[NB * 8 * ND];
__device__ float g_fv[NB * ND];
__device__ float g_bqkv[3 * ND];

// ---------------- split fp16 buffers (hi at [0], lo at [SIZE] per segment) -----
__device__ __half g_p16[2 * SZ_P];
__device__ __half g_ln16[2 * SZ_LN];
__device__ __half g_qkv16[6 * SZ_LN];
__device__ __half g_attn16[2 * SZ_ATTN];
__device__ __half g_ctx16[2 * SZ_LN];
__device__ __half g_h16[2 * SZ_H];
__device__ __half g_pew16[2 * NPDP * ND];
__device__ __half g_wqkv16[6 * SZ_DD];
__device__ __half g_wo16[2 * SZ_DD];
__device__ __half g_w1a16[2 * SZ_W];
__device__ __half g_w2a16[2 * SZ_W];
__device__ __half g_w1b16[2 * SZ_W];
__device__ __half g_w2b16[2 * SZ_W];

// ---------------- persistent side stream ---------------------------------------
struct SideStream {
    cudaStream_t s;
    cudaEvent_t fork, joinW, joinM, attnev, joinA;
    SideStream() {
        cudaStreamCreateWithFlags(&s, cudaStreamNonBlocking);
        cudaEventCreateWithFlags(&fork,   cudaEventDisableTiming);
        cudaEventCreateWithFlags(&joinW,  cudaEventDisableTiming);
        cudaEventCreateWithFlags(&joinM,  cudaEventDisableTiming);
        cudaEventCreateWithFlags(&attnev, cudaEventDisableTiming);
        cudaEventCreateWithFlags(&joinA,  cudaEventDisableTiming);
    }
};
static SideStream g_ss;

__device__ __forceinline__ float gelu_exact(float v) {
    return 0.5f * v * (1.0f + erff(v * 0.70710678118654752440f));
}
__device__ __forceinline__ void split2(float v0, float v1, __half* oh, __half* ol) {
    __half h0 = __float2half_rn(v0), h1 = __float2half_rn(v1);
    *(__half2*)oh = __halves2half2(h0, h1);
    *(__half2*)ol = __halves2half2(__float2half_rn(v0 - __half2float(h0)),
                                   __float2half_rn(v1 - __half2float(h1)));
}

// ---------------- mma.sync helpers ----------------------------------------------
__device__ __forceinline__ void ldsm4(unsigned* r, unsigned addr) {
    asm volatile("ldmatrix.sync.aligned.m8n8.x4.shared.b16 {%0,%1,%2,%3}, [%4];\n"
        : "=r"(r[0]), "=r"(r[1]), "=r"(r[2]), "=r"(r[3]) : "r"(addr));
}
__device__ __forceinline__ void ldsm4t(unsigned* r, unsigned addr) {
    asm volatile("ldmatrix.sync.aligned.m8n8.x4.trans.shared.b16 {%0,%1,%2,%3}, [%4];\n"
        : "=r"(r[0]), "=r"(r[1]), "=r"(r[2]), "=r"(r[3]) : "r"(addr));
}
__device__ __forceinline__ void mma16816(float* c, const unsigned* a, const unsigned* b) {
    asm volatile("mma.sync.aligned.m16n8k16.row.col.f32.f16.f16.f32 "
        "{%0,%1,%2,%3}, {%4,%5,%6,%7}, {%8,%9}, {%0,%1,%2,%3};\n"
        : "+f"(c[0]), "+f"(c[1]), "+f"(c[2]), "+f"(c[3])
        : "r"(a[0]), "r"(a[1]), "r"(a[2]), "r"(a[3]), "r"(b[0]), "r"(b[1]));
}
__device__ __forceinline__ void cpa16(unsigned dst, const void* src, bool p) {
    int sz = p ? 16 : 0;
    asm volatile("cp.async.cg.shared.global [%0], [%1], 16, %2;\n"
        :: "r"(dst), "l"(src), "r"(sz));
}

// ---------------- modes --------------------------------------------------------
#define M_PE   0
#define M_QKV  1
#define M_PROJ 2
#define M_SC   3
#define M_AV   4
#define M_FF1  5
#define M_FF2  6

template <int MODE>
__global__ __launch_bounds__(256) void mm_k(
    const __half* __restrict__ Ag, const __half* __restrict__ Bg,
    const float* __restrict__ bias, const float* __restrict__ extra,
    void* __restrict__ Og)
{
    constexpr int K   = (MODE == M_PE) ? NPDP : (MODE == M_SC) ? 64 :
                        (MODE == M_AV) ? 256 : (MODE == M_FF2) ? 2048 : 512;
    constexpr int LDA = K;
    constexpr int LDB = (MODE == M_SC || MODE == M_AV) ? 64 :
                        (MODE == M_FF1) ? 2048 : 512;
    constexpr bool NT = (MODE == M_SC);
    constexpr bool GATHER = (MODE == M_FF1) || (MODE == M_FF2);
    constexpr int SHIFT = (MODE == M_FF1) ? 1 : 0;
    constexpr int BN = (MODE == M_AV || MODE == M_SC) ? 64 : 128;
    constexpr int WN = BN / 4;
    constexpr int NF = WN / 8;
    constexpr int KT = K / 16;
    constexpr size_t ALO =
        (MODE == M_PE)  ? SZ_P :
        (MODE == M_SC || MODE == M_QKV || MODE == M_PROJ || MODE == M_FF1) ? SZ_LN :
        (MODE == M_AV)  ? SZ_ATTN : SZ_H;
    constexpr size_t BLO =
        (MODE == M_PE)  ? (size_t)NPDP * ND :
        (MODE == M_QKV || MODE == M_PROJ) ? SZ_DD :
        (MODE == M_SC || MODE == M_AV) ? SZ_LN : SZ_W;
    constexpr size_t OLO =
        (MODE == M_QKV || MODE == M_AV) ? SZ_LN : SZ_H;
    constexpr int AST = 128 * 24;
    constexpr int BST = NT ? BN * 24 : 16 * BN;

    __shared__ __align__(16) __half As[2][2][AST];
    __shared__ __align__(16) __half Bs[2][2][BST];
    __shared__ int s_idx[128];

    int tid = threadIdx.x;
    int bz = blockIdx.z;
    int row0 = blockIdx.y * 128, col0 = blockIdx.x * BN;

    const __half* Ah = Ag;
    const __half* Bh = Bg;
    if (MODE == M_SC)  { Ah += (size_t)bz * 256 * 64; Bh += (size_t)bz * 256 * 64; }
    if (MODE == M_AV)  { Ah += (size_t)bz * 65536;    Bh += (size_t)bz * 256 * 64; }
    if (MODE == M_QKV) { Bh += (size_t)bz * 2 * SZ_DD; }
    if (MODE == M_FF1) { Bh += (size_t)bz * 512 * 2048; }
    if (MODE == M_FF2) { Bh += (size_t)bz * 2048 * 512; }
    const __half* Al = Ah + ALO;
    const __half* Bl = Bh + BLO;

    if (GATHER) {
        int cnt = g_cnt[bz];
        if (row0 >= cnt) return;
        if (tid < 128) {
            int r = row0 + tid;
            s_idx[tid] = (r < cnt) ? g_perm[bz * NA + r] : -1;
        }
        __syncthreads();
    }

    int a_row = tid >> 1, a_ch = tid & 1;
    unsigned a_dst = (unsigned)((a_row * 24 + a_ch * 8) * 2);
    const __half* a_srch; const __half* a_srcl; bool a_pred;
    if (GATHER) {
        int a = s_idx[a_row];
        a_pred = (a >= 0);
        size_t off = a_pred ? (size_t)(a >> SHIFT) * LDA + a_ch * 8 : 0;
        a_srch = Ah + off; a_srcl = Al + off;
    } else {
        a_pred = true;
        size_t off = (size_t)(row0 + a_row) * LDA + a_ch * 8;
        a_srch = Ah + off; a_srcl = Al + off;
    }
    unsigned b_dst = 0; const __half* b_srch = Bh; const __half* b_srcl = Bh;
    bool b_val;
    if (!NT) {
        b_val = tid < (16 * BN / 8);
        int row = tid / (BN / 8), cn = tid % (BN / 8);
        int sw = cn ^ (row & 7);
        b_dst = (unsigned)((row * BN + sw * 8) * 2);
        size_t off = (size_t)row * LDB + col0 + cn * 8;
        b_srch = Bh + off; b_srcl = Bl + off;
    } else {
        b_val = tid < (BN * 2);
        int nr = tid >> 1, ch = tid & 1;
        b_dst = (unsigned)((nr * 24 + ch * 8) * 2);
        size_t off = (size_t)(col0 + nr) * LDB + ch * 8;
        b_srch = Bh + off; b_srcl = Bl + off;
    }

    unsigned as_base = (unsigned)__cvta_generic_to_shared(&As[0][0][0]);
    unsigned bs_base = (unsigned)__cvta_generic_to_shared(&Bs[0][0][0]);

    auto issue = [&](int kt, int buf) {
        unsigned abh = as_base + (buf * 2 + 0) * AST * 2;
        unsigned abl = as_base + (buf * 2 + 1) * AST * 2;
        cpa16(abh + a_dst, a_srch + (size_t)kt * 16, a_pred);
        cpa16(abl + a_dst, a_srcl + (size_t)kt * 16, a_pred);
        if (b_val) {
            unsigned bbh = bs_base + (buf * 2 + 0) * BST * 2;
            unsigned bbl = bs_base + (buf * 2 + 1) * BST * 2;
            size_t off = NT ? (size_t)kt * 16 : (size_t)kt * 16 * LDB;
            cpa16(bbh + b_dst, b_srch + off, true);
            cpa16(bbl + b_dst, b_srcl + off, true);
        }
        asm volatile("cp.async.commit_group;\n");
    };

    int lane = tid & 31;
    int warp = tid >> 5;
    int wm = warp >> 2, wn = warp & 3;

    float acc[4][NF][4];
#pragma unroll
    for (int i = 0; i < 4; i++)
#pragma unroll
        for (int j = 0; j < NF; j++)
#pragma unroll
            for (int t = 0; t < 4; t++) acc[i][j][t] = 0.f;

    issue(0, 0);
#pragma unroll 1
    for (int kt = 0; kt < KT; kt++) {
        int buf = kt & 1;
        asm volatile("cp.async.wait_group 0;\n");
        __syncthreads();
        if (kt + 1 < KT) issue(kt + 1, buf ^ 1);
        unsigned abh = as_base + (buf * 2 + 0) * AST * 2;
        unsigned abl = as_base + (buf * 2 + 1) * AST * 2;
        unsigned bbh = bs_base + (buf * 2 + 0) * BST * 2;
        unsigned bbl = bs_base + (buf * 2 + 1) * BST * 2;

        unsigned ah[4][4], al[4][4];
#pragma unroll
        for (int i = 0; i < 4; i++) {
            int m = wm * 64 + i * 16 + (lane & 15);
            int ch = lane >> 4;
            unsigned ad = (unsigned)((m * 24 + ch * 8) * 2);
            ldsm4(ah[i], abh + ad);
            ldsm4(al[i], abl + ad);
        }
        unsigned brh[2 * NF], brl[2 * NF];
#pragma unroll
        for (int jj = 0; jj < NF / 2; jj++) {
            int n0 = wn * WN + jj * 16;
            if (!NT) {
                int k = lane & 15;
                int cn = (n0 >> 3) + (lane >> 4);
                int sw = cn ^ (k & 7);
                unsigned bd = (unsigned)((k * BN + sw * 8) * 2);
                ldsm4t(&brh[jj * 4], bbh + bd);
                ldsm4t(&brl[jj * 4], bbl + bd);
            } else {
                int n = n0 + ((lane >> 4) << 3) + (lane & 7);
                int ch = (lane >> 3) & 1;
                unsigned bd = (unsigned)((n * 24 + ch * 8) * 2);
                ldsm4(&brh[jj * 4], bbh + bd);
                ldsm4(&brl[jj * 4], bbl + bd);
            }
        }
#pragma unroll
        for (int i = 0; i < 4; i++)
#pragma unroll
            for (int j = 0; j < NF; j++) {
                mma16816(acc[i][j], ah[i], &brh[j * 2]);
                mma16816(acc[i][j], al[i], &brh[j * 2]);
                mma16816(acc[i][j], ah[i], &brl[j * 2]);
            }
    }

    int rl = lane >> 2, cp2 = (lane & 3) * 2;
#pragma unroll
    for (int i = 0; i < 4; i++) {
#pragma unroll
        for (int hh = 0; hh < 2; hh++) {
            int rr = wm * 64 + i * 16 + rl + hh * 8;
            int r = row0 + rr;
            int aidx = 0;
            if (GATHER) {
                aidx = s_idx[rr];
                if (aidx < 0) continue;
            }
#pragma unroll
            for (int j = 0; j < NF; j++) {
                int c = col0 + wn * WN + j * 8 + cp2;
                float v0 = acc[i][j][hh * 2 + 0];
                float v1 = acc[i][j][hh * 2 + 1];
                if (MODE == M_PE) {
                    float* O = (float*)Og;
                    v0 += bias[c]     + extra[(size_t)(r & 255) * 512 + c];
                    v1 += bias[c + 1] + extra[(size_t)(r & 255) * 512 + c + 1];
                    O[(size_t)r * 512 + c] = v0;
                    O[(size_t)r * 512 + c + 1] = v1;
                } else if (MODE == M_QKV) {
                    __half* O = (__half*)Og + (size_t)bz * 2 * SZ_LN;
                    const float* bi = bias + bz * 512;
                    v0 += bi[c]; v1 += bi[c + 1];
                    int b = r >> 8, s = r & 255, hd = c >> 6, ii = c & 63;
                    size_t o = (size_t)(((b << 3) + hd) * 256 + s) * 64 + ii;
                    split2(v0, v1, O + o, O + OLO + o);
                } else if (MODE == M_PROJ) {
                    float* O = (float*)Og;
                    v0 += bias[c]     + extra[(size_t)r * 512 + c];
                    v1 += bias[c + 1] + extra[(size_t)r * 512 + c + 1];
                    O[(size_t)r * 512 + c] = v0;
                    O[(size_t)r * 512 + c + 1] = v1;
                } else if (MODE == M_SC) {
                    float* O = (float*)Og + (size_t)bz * 65536;
                    O[(size_t)r * 256 + c] = v0 * 0.125f;
                    O[(size_t)r * 256 + c + 1] = v1 * 0.125f;
                } else if (MODE == M_AV) {
                    __half* O = (__half*)Og;
                    int b = bz >> 3, hd = bz & 7;
                    size_t o = (size_t)((b << 8) + r) * 512 + (hd << 6) + c;
                    split2(v0, v1, O + o, O + OLO + o);
                } else if (MODE == M_FF1) {
                    __half* O = (__half*)Og;
                    const float* bi = bias + bz * 2048;
                    v0 = gelu_exact(v0 + bi[c]);
                    v1 = gelu_exact(v1 + bi[c + 1]);
                    size_t o = (size_t)aidx * 2048 + c;
                    split2(v0, v1, O + o, O + OLO + o);
                } else {
                    float* O = (float*)Og;
                    const float* bi = bias + bz * 512;
                    O[(size_t)aidx * 512 + c] = v0 + bi[c];
                    O[(size_t)aidx * 512 + c + 1] = v1 + bi[c + 1];
                }
            }
        }
    }
}

// ---------------- conversions ---------------------------------------------------
struct __align__(8) h2x2 { __half2 a, b; };

__device__ __forceinline__ void conv_elem4(const float* in, __half* outh, size_t n,
                                           size_t i) {
    float4 f = *(const float4*)(in + i);
    h2x2 H, L;
    H.a = __floats2half2_rn(f.x, f.y);
    H.b = __floats2half2_rn(f.z, f.w);
    float2 f0 = __half22float2(H.a), f1 = __half22float2(H.b);
    L.a = __floats2half2_rn(f.x - f0.x, f.y - f0.y);
    L.b = __floats2half2_rn(f.z - f1.x, f.w - f1.y);
    *(h2x2*)(outh + i) = H;
    *(h2x2*)(outh + n + i) = L;
}

__global__ __launch_bounds__(256) void conv4_k(
    const float* __restrict__ s0, const float* __restrict__ s1,
    const float* __restrict__ s2, const float* __restrict__ s3,
    __half* __restrict__ d0, __half* __restrict__ d1,
    __half* __restrict__ d2, __half* __restrict__ d3, size_t n)
{
    const float* src = (blockIdx.z == 0) ? s0 : (blockIdx.z == 1) ? s1 :
                       (blockIdx.z == 2) ? s2 : s3;
    __half* dst = (blockIdx.z == 0) ? d0 : (blockIdx.z == 1) ? d1 :
                  (blockIdx.z == 2) ? d2 : d3;
    size_t i = ((size_t)blockIdx.x * 256 + threadIdx.x) * 4;
    if (i < n) conv_elem4(src, dst, n, i);
}

__global__ __launch_bounds__(256) void convpe_k(const float* __restrict__ w) {
    int i = (blockIdx.x * 256 + threadIdx.x) * 4;
    if (i >= NPDP * ND) return;
    int j = i >> 9;
    float4 f = make_float4(0.f, 0.f, 0.f, 0.f);
    if (j < NPD) f = *(const float4*)(w + i);
    h2x2 H, L;
    H.a = __floats2half2_rn(f.x, f.y);
    H.b = __floats2half2_rn(f.z, f.w);
    float2 f0 = __half22float2(H.a), f1 = __half22float2(H.b);
    L.a = __floats2half2_rn(f.x - f0.x, f.y - f0.y);
    L.b = __floats2half2_rn(f.z - f1.x, f.w - f1.y);
    *(h2x2*)(g_pew16 + i) = H;
    *(h2x2*)(g_pew16 + NPDP * ND + i) = L;
}

// bqkv gather + global init (working counter + per-layer importance buffers)
__global__ void bqkv_k(const float* __restrict__ bq, const float* __restrict__ bk,
                       const float* __restrict__ bv) {
    int i = blockIdx.x * 256 + threadIdx.x;
    if (blockIdx.x == 0 && threadIdx.x < 8) {
        g_cnt[threadIdx.x] = 0;
        g_imp0[threadIdx.x] = 0.f;
        g_imp1[threadIdx.x] = 0.f;
    }
    if (i >= 1536) return;
    g_bqkv[i] = (i < 512) ? bq[i] : (i < 1024) ? bk[i - 512] : bv[i - 1024];
}

// ---------------- patch gather (coalesced, smem-staged) -------------------------
__global__ __launch_bounds__(256) void patch_k(const float* __restrict__ x) {
    __shared__ float sp[NPD];
    int t = blockIdx.x;
    int b = t >> 8, s = t & 255;
    int hi = s >> 4, wi = s & 15;
    int tid = threadIdx.x;
    const float* xb = x + ((size_t)b * 3 * 224 + hi * 14) * 224 + wi * 14;
    for (int idx = tid; idx < NPD; idx += 256) {
        int c = idx / 196, rem = idx % 196;
        int p1 = rem / 14, p2 = rem % 14;
        float f = xb[((size_t)c * 224 + p1) * 224 + p2];
        sp[(p1 * 14 + p2) * 3 + c] = f;
    }
    __syncthreads();
    size_t base = (size_t)t * NPDP;
    for (int j = tid; j < NPDP; j += 256) {
        float f = (j < NPD) ? sp[j] : 0.f;
        __half h = __float2half_rn(f);
        g_p16[base + j] = h;
        g_p16[SZ_P + base + j] = __float2half_rn(f - __half2float(h));
    }
}

// ---------------- LN body (fp16 split out only) ---------------------------------
__device__ __forceinline__ void ln_body(
    int row, int tid, float4 v,
    const float* __restrict__ gw, const float* __restrict__ bw,
    __half* __restrict__ out16)
{
    float s = v.x + v.y + v.z + v.w;
    float q = v.x * v.x + v.y * v.y + v.z * v.z + v.w * v.w;
    __shared__ float ss[4], sq[4];
    for (int o = 16; o > 0; o >>= 1) {
        s += __shfl_xor_sync(0xffffffffu, s, o);
        q += __shfl_xor_sync(0xffffffffu, q, o);
    }
    if ((tid & 31) == 0) { ss[tid >> 5] = s; sq[tid >> 5] = q; }
    __syncthreads();
    s = ss[0] + ss[1] + ss[2] + ss[3];
    q = sq[0] + sq[1] + sq[2] + sq[3];
    float mean = s * (1.f / 512.f);
    float var  = q * (1.f / 512.f) - mean * mean;
    float inv  = rsqrtf(var + 1e-5f);
    float4 g4 = ((const float4*)gw)[tid];
    float4 b4 = ((const float4*)bw)[tid];
    float4 o;
    o.x = (v.x - mean) * inv * g4.x + b4.x;
    o.y = (v.y - mean) * inv * g4.y + b4.y;
    o.z = (v.z - mean) * inv * g4.z + b4.z;
    o.w = (v.w - mean) * inv * g4.w + b4.w;
    size_t base = (size_t)row * 512 + tid * 4;
    split2(o.x, o.y, out16 + base,     out16 + SZ_LN + base);
    split2(o.z, o.w, out16 + base + 2, out16 + SZ_LN + base + 2);
}

__global__ __launch_bounds__(128) void ln_k(
    const float* __restrict__ in, const float* __restrict__ gw,
    const float* __restrict__ bw, __half* __restrict__ out16)
{
    int row = blockIdx.x, tid = threadIdx.x;
    float4 v = ((const float4*)(in + (size_t)row * 512))[tid];
    ln_body(row, tid, v, gw, bw, out16);
}

// combine+LN3; block 0 also snapshots layer-1 counts and resets working counter
__global__ __launch_bounds__(128) void cln_k(
    const float* __restrict__ gw, const float* __restrict__ bw,
    __half* __restrict__ out16)
{
    int row = blockIdx.x, tid = threadIdx.x;
    if (row == 0 && tid < 8) { g_cnt0[tid] = g_cnt[tid]; g_cnt[tid] = 0; }
    float g1 = g_gate[2 * row], g2 = g_gate[2 * row + 1];
    float4 a = ((const float4*)(g_contrib + (size_t)(2 * row) * 512))[tid];
    float4 b = ((const float4*)(g_contrib + (size_t)(2 * row + 1) * 512))[tid];
    float4 v;
    v.x = g1 * a.x + g2 * b.x; v.y = g1 * a.y + g2 * b.y;
    v.z = g1 * a.z + g2 * b.z; v.w = g1 * a.w + g2 * b.w;
    ln_body(row, tid, v, gw, bw, out16);
}

__global__ __launch_bounds__(512) void fvc_k(float* __restrict__ part) {
    int b = blockIdx.x, seg = blockIdx.y, d = threadIdx.x;
    int t0 = b * 256 + seg * 32;
    float s = 0.f;
    for (int ss = 0; ss < 32; ss++) {
        int t = t0 + ss;
        float g1 = g_gate[2 * t], g2 = g_gate[2 * t + 1];
        s += g1 * g_contrib[(size_t)(2 * t) * 512 + d]
           + g2 * g_contrib[(size_t)(2 * t + 1) * 512 + d];
    }
    part[(size_t)(b * 8 + seg) * 512 + d] = s;
}

// ---------------- MoE router ----------------------------------------------------
__global__ __launch_bounds__(256) void router_k(const __half* __restrict__ xin,
                                                const float* __restrict__ rw,
                                                const float* __restrict__ rb) {
    __shared__ float s_rw[8][512];
    __shared__ float s_rb[8];
    int tid = threadIdx.x;
    for (int i = tid; i < 4096; i += 256) s_rw[i >> 9][i & 511] = rw[(i & 511) * 8 + (i >> 9)];
    if (tid < 8) s_rb[tid] = rb[tid];
    __syncthreads();
    int t = (blockIdx.x << 3) + (tid >> 5);
    int lane = tid & 31;
    const __half* xh = xin + (size_t)t * 512;
    const __half* xl = xh + SZ_LN;
    float acc[8] = {};
    for (int k = lane * 2; k < 512; k += 64) {
        __half2 h = *(const __half2*)(xh + k);
        __half2 l = *(const __half2*)(xl + k);
        float2 hf = __half22float2(h), lf = __half22float2(l);
        float x0 = hf.x + lf.x, x1 = hf.y + lf.y;
#pragma unroll
        for (int e = 0; e < 8; e++)
            acc[e] += x0 * s_rw[e][k] + x1 * s_rw[e][k + 1];
    }
#pragma unroll
    for (int e = 0; e < 8; e++)
        for (int o = 16; o > 0; o >>= 1) acc[e] += __shfl_xor_sync(0xffffffffu, acc[e], o);
    if (lane == 0) {
        float mx = -1e30f;
#pragma unroll
        for (int e = 0; e < 8; e++) { acc[e] += s_rb[e]; mx = fmaxf(mx, acc[e]); }
        float sum = 0.f;
#pragma unroll
        for (int e = 0; e < 8; e++) { acc[e] = __expf(acc[e] - mx); sum += acc[e]; }
        float inv = 1.f / sum;
#pragma unroll
        for (int e = 0; e < 8; e++) g_probs[t * 8 + e] = acc[e] * inv;
    }
}

// ---------------- softmax over attn rows ----------------------------------------
__global__ __launch_bounds__(256) void softmax_attn_k() {
    int row  = (blockIdx.x << 3) + (threadIdx.x >> 5);
    int lane = threadIdx.x & 31;
    const float4* p = (const float4*)(g_attn + (size_t)row * 256);
    float4 a = p[lane], b = p[lane + 32];
    float m = fmaxf(fmaxf(fmaxf(a.x, a.y), fmaxf(a.z, a.w)),
                    fmaxf(fmaxf(b.x, b.y), fmaxf(b.z, b.w)));
    for (int o = 16; o > 0; o >>= 1) m = fmaxf(m, __shfl_xor_sync(0xffffffffu, m, o));
    a.x = __expf(a.x - m); a.y = __expf(a.y - m);
    a.z = __expf(a.z - m); a.w = __expf(a.w - m);
    b.x = __expf(b.x - m); b.y = __expf(b.y - m);
    b.z = __expf(b.z - m); b.w = __expf(b.w - m);
    float s = a.x + a.y + a.z + a.w + b.x + b.y + b.z + b.w;
    for (int o = 16; o > 0; o >>= 1) s += __shfl_xor_sync(0xffffffffu, s, o);
    float inv = 1.f / s;
    a.x *= inv; a.y *= inv; a.z *= inv; a.w *= inv;
    b.x *= inv; b.y *= inv; b.z *= inv; b.w *= inv;
    size_t base = (size_t)row * 256;
    split2(a.x, a.y, g_attn16 + base + lane * 4,     g_attn16 + SZ_ATTN + base + lane * 4);
    split2(a.z, a.w, g_attn16 + base + lane * 4 + 2, g_attn16 + SZ_ATTN + base + lane * 4 + 2);
    split2(b.x, b.y, g_attn16 + base + 128 + lane * 4,     g_attn16 + SZ_ATTN + base + 128 + lane * 4);
    split2(b.z, b.w, g_attn16 + base + 128 + lane * 4 + 2, g_attn16 + SZ_ATTN + base + 128 + lane * 4 + 2);
}

// ---------------- attn_w --------------------------------------------------------
__global__ __launch_bounds__(256) void attnw_k(float* __restrict__ out) {
    int bq = blockIdx.x, tid = threadIdx.x;
    int b = bq >> 8, qr = bq & 255;
    float s = 0.f;
#pragma unroll
    for (int h = 0; h < 8; h++) {
        size_t off = ((size_t)((b << 3) + h)) * 65536 + (qr << 8) + tid;
        s += __half2float(g_attn16[off]) + __half2float(g_attn16[SZ_ATTN + off]);
    }
    s *= 0.125f;
    __shared__ float red[8];
    float m = s;
    for (int o = 16; o > 0; o >>= 1) m = fmaxf(m, __shfl_xor_sync(0xffffffffu, m, o));
    if ((tid & 31) == 0) red[tid >> 5] = m;
    __syncthreads();
    m = red[0];
#pragma unroll
    for (int w = 1; w < 8; w++) m = fmaxf(m, red[w]);
    float ex = __expf(s - m);
    float sum = ex;
    __syncthreads();
    for (int o = 16; o > 0; o >>= 1) sum += __shfl_xor_sync(0xffffffffu, sum, o);
    if ((tid & 31) == 0) red[tid >> 5] = sum;
    __syncthreads();
    sum = red[0] + red[1] + red[2] + red[3] + red[4] + red[5] + red[6] + red[7];
    out[(size_t)bq * 256 + tid] = ex / sum;
}

// ---------------- dispatch / loss -----------------------------------------------
__global__ __launch_bounds__(256) void dispatch_k(float* __restrict__ impbuf) {
    __shared__ int   s_cnt[8];
    __shared__ float s_imp[8];
    __shared__ int   s_base[8];
    int tid = threadIdx.x;
    if (tid < 8) { s_cnt[tid] = 0; s_imp[tid] = 0.f; }
    __syncthreads();
    int t = blockIdx.x * 256 + tid;
    float p[8];
#pragma unroll
    for (int e = 0; e < 8; e++) { p[e] = g_probs[t * 8 + e]; atomicAdd(&s_imp[e], p[e]); }
    int e1 = 0; float v1 = p[0];
#pragma unroll
    for (int e = 1; e < 8; e++) if (p[e] > v1) { v1 = p[e]; e1 = e; }
    int e2 = -1; float v2 = -1e30f;
#pragma unroll
    for (int e = 0; e < 8; e++) if (e != e1 && p[e] > v2) { v2 = p[e]; e2 = e; }
    int lp1 = atomicAdd(&s_cnt[e1], 1);
    int lp2 = atomicAdd(&s_cnt[e2], 1);
    __syncthreads();
    if (tid < 8) {
        s_base[tid] = atomicAdd(&g_cnt[tid], s_cnt[tid]);
        atomicAdd(&impbuf[tid], s_imp[tid]);
    }
    __syncthreads();
    g_perm[e1 * NA + s_base[e1] + lp1] = t * 2;
    g_perm[e2 * NA + s_base[e2] + lp2] = t * 2 + 1;
    g_gate[t * 2]     = v1;
    g_gate[t * 2 + 1] = v2;
}

// single end-of-graph loss: layer-1 from snapshot, layer-2 from working counter
__global__ void loss_k(float* out_loss) {
    int tid = threadIdx.x;
    float v = 0.f;
    if (tid < 8) {
        v  = 8.f * ((float)g_cnt0[tid] * (1.f / 8192.f)) * (g_imp0[tid] * (1.f / 8192.f));
        v += 8.f * ((float)g_cnt[tid]  * (1.f / 8192.f)) * (g_imp1[tid] * (1.f / 8192.f));
    }
    for (int o = 16; o > 0; o >>= 1) v += __shfl_xor_sync(0xffffffffu, v, o);
    if (tid == 0) out_loss[0] = v;
}

// ---------------- fv + logits ---------------------------------------------------
__global__ __launch_bounds__(512) void fv2_k(const float* __restrict__ part,
                                             float* __restrict__ out_fv) {
    int b = blockIdx.x, d = threadIdx.x;
    float s = 0.f;
#pragma unroll
    for (int seg = 0; seg < 8; seg++)
        s += part[(size_t)(b * 8 + seg) * 512 + d];
    s *= (1.f / 256.f);
    g_fv[b * 512 + d] = s;
    out_fv[b * 512 + d] = s;
}
__global__ __launch_bounds__(512) void logits_k(const float* __restrict__ W,
                                                const float* __restrict__ bias,
                                                float* __restrict__ out) {
    __shared__ float sf[512];
    int b = blockIdx.x, n = threadIdx.x;
    sf[n] = g_fv[b * 512 + n];
    __syncthreads();
    float acc = 0.f;
    for (int k = 0; k < 512; k++) acc += sf[k] * W[k * 512 + n];
    out[b * 512 + n] = acc + bias[n];
}

// ---------------- host launch ---------------------------------------------------
extern "C" void kernel_launch(void* const* d_in, const int* in_sizes, int n_in,
                              void* d_out, int out_size) {
    const float* x     = (const float*)d_in[0];
    const float* pe_w  = (const float*)d_in[1];
    const float* pe_b  = (const float*)d_in[2];
    const float* pos   = (const float*)d_in[3];
    const float* ln1_g = (const float*)d_in[4];
    const float* ln1_b = (const float*)d_in[5];
    const float* ln2_g = (const float*)d_in[6];
    const float* ln2_b = (const float*)d_in[7];
    const float* ln3_g = (const float*)d_in[8];
    const float* ln3_b = (const float*)d_in[9];
    const float* wq = (const float*)d_in[10];
    const float* bq = (const float*)d_in[11];
    const float* wk = (const float*)d_in[12];
    const float* bk = (const float*)d_in[13];
    const float* wv = (const float*)d_in[14];
    const float* bv = (const float*)d_in[15];
    const float* wo = (const float*)d_in[16];
    const float* bo = (const float*)d_in[17];
    const float* m1_rw = (const float*)d_in[18];
    const float* m1_rb = (const float*)d_in[19];
    const float* m1_w1 = (const float*)d_in[20];
    const float* m1_b1 = (const float*)d_in[21];
    const float* m1_w2 = (const float*)d_in[22];
    const float* m1_b2 = (const float*)d_in[23];
    const float* m2_rw = (const float*)d_in[24];
    const float* m2_rb = (const float*)d_in[25];
    const float* m2_w1 = (const float*)d_in[26];
    const float* m2_b1 = (const float*)d_in[27];
    const float* m2_w2 = (const float*)d_in[28];
    const float* m2_b2 = (const float*)d_in[29];
    const float* cls_w = (const float*)d_in[30];
    const float* cls_b = (const float*)d_in[31];

    float* out = (float*)d_out;
    float* out_logits = out;
    float* out_fv     = out + 16384;
    float* out_loss   = out + 32768;
    float* out_attnw  = out + 32769;

    float *p_e, *p_attn, *p_contrib, *p_part;
    __half *p_p16, *p_ln16, *p_qkv16, *p_attn16, *p_ctx16, *p_h16;
    __half *p_pew16, *p_wqkv16, *p_wo16;
    __half *p_w1a, *p_w2a, *p_w1b, *p_w2b;
    float *p_imp0, *p_imp1;
    cudaGetSymbolAddress((void**)&p_e,       g_e);
    cudaGetSymbolAddress((void**)&p_attn,    g_attn);
    cudaGetSymbolAddress((void**)&p_contrib, g_contrib);
    cudaGetSymbolAddress((void**)&p_part,    g_part);
    cudaGetSymbolAddress((void**)&p_p16,     g_p16);
    cudaGetSymbolAddress((void**)&p_ln16,    g_ln16);
    cudaGetSymbolAddress((void**)&p_qkv16,   g_qkv16);
    cudaGetSymbolAddress((void**)&p_attn16,  g_attn16);
    cudaGetSymbolAddress((void**)&p_ctx16,   g_ctx16);
    cudaGetSymbolAddress((void**)&p_h16,     g_h16);
    cudaGetSymbolAddress((void**)&p_pew16,   g_pew16);
    cudaGetSymbolAddress((void**)&p_wqkv16,  g_wqkv16);
    cudaGetSymbolAddress((void**)&p_wo16,    g_wo16);
    cudaGetSymbolAddress((void**)&p_w1a,     g_w1a16);
    cudaGetSymbolAddress((void**)&p_w2a,     g_w2a16);
    cudaGetSymbolAddress((void**)&p_w1b,     g_w1b16);
    cudaGetSymbolAddress((void**)&p_w2b,     g_w2b16);
    cudaGetSymbolAddress((void**)&p_imp0,    g_imp0);
    cudaGetSymbolAddress((void**)&p_imp1,    g_imp1);
    float* p_bqkv; cudaGetSymbolAddress((void**)&p_bqkv, g_bqkv);

    // fork side stream: bqkv + attention-weight convs (early), then big MoE convs
    cudaEventRecord(g_ss.fork, 0);
    cudaStreamWaitEvent(g_ss.s, g_ss.fork, 0);
    bqkv_k<<<6, 256, 0, g_ss.s>>>(bq, bk, bv);
    conv4_k<<<dim3(256, 1, 4), 256, 0, g_ss.s>>>(
        wq, wk, wv, wo,
        p_wqkv16, p_wqkv16 + 2 * SZ_DD, p_wqkv16 + 4 * SZ_DD, p_wo16, SZ_DD);
    cudaEventRecord(g_ss.joinW, g_ss.s);
    conv4_k<<<dim3(8192, 1, 4), 256, 0, g_ss.s>>>(
        m1_w1, m1_w2, m2_w1, m2_w2, p_w1a, p_w2a, p_w1b, p_w2b, SZ_W);
    cudaEventRecord(g_ss.joinM, g_ss.s);

    // main: PE chain
    patch_k<<<NTOK, 256>>>(x);
    convpe_k<<<(NPDP * ND / 4 + 255) / 256, 256>>>(pe_w);
    mm_k<M_PE><<<dim3(4, 64), 256>>>(p_p16, p_pew16, pe_b, pos, p_e);

    ln_k<<<NTOK, 128>>>(p_e, ln1_g, ln1_b, p_ln16);
    cudaStreamWaitEvent(0, g_ss.joinW, 0);
    mm_k<M_QKV><<<dim3(4, 64, 3), 256>>>(p_ln16, p_wqkv16, p_bqkv, nullptr, p_qkv16);
    mm_k<M_SC><<<dim3(4, 2, 256), 256>>>(p_qkv16, p_qkv16 + 2 * SZ_LN,
                                         nullptr, nullptr, p_attn);
    softmax_attn_k<<<8192, 256>>>();
    cudaEventRecord(g_ss.attnev, 0);

    // side stream: attnw AFTER attnev is recorded (legal capture ordering)
    cudaStreamWaitEvent(g_ss.s, g_ss.attnev, 0);
    attnw_k<<<NTOK, 256, 0, g_ss.s>>>(out_attnw);
    cudaEventRecord(g_ss.joinA, g_ss.s);

    mm_k<M_AV><<<dim3(1, 2, 256), 256>>>(p_attn16, p_qkv16 + 4 * SZ_LN,
                                         nullptr, nullptr, p_ctx16);
    mm_k<M_PROJ><<<dim3(4, 64), 256>>>(p_ctx16, p_wo16, bo, p_e, p_e);

    // MoE layer 1
    ln_k<<<NTOK, 128>>>(p_e, ln2_g, ln2_b, p_ln16);
    router_k<<<1024, 256>>>(p_ln16, m1_rw, m1_rb);
    dispatch_k<<<32, 256>>>(p_imp0);
    cudaStreamWaitEvent(0, g_ss.joinM, 0);
    mm_k<M_FF1><<<dim3(16, 64, 8), 256>>>(p_ln16, p_w1a, m1_b1, nullptr, p_h16);
    mm_k<M_FF2><<<dim3(4, 64, 8), 256>>>(p_h16, p_w2a, m1_b2, nullptr, p_contrib);

    // combine + LN3 fused; block0 snapshots layer-1 counts + resets working counter
    cln_k<<<NTOK, 128>>>(ln3_g, ln3_b, p_ln16);

    // MoE layer 2
    router_k<<<1024, 256>>>(p_ln16, m2_rw, m2_rb);
    dispatch_k<<<32, 256>>>(p_imp1);
    mm_k<M_FF1><<<dim3(16, 64, 8), 256>>>(p_ln16, p_w1b, m2_b1, nullptr, p_h16);
    mm_k<M_FF2><<<dim3(4, 64, 8), 256>>>(p_h16, p_w2b, m2_b2, nullptr, p_contrib);

    // layer-2 combine fused into fv partials; o2 never materialized
    fvc_k<<<dim3(NB, 8), 512>>>(p_part);
    fv2_k<<<NB, 512>>>(p_part, out_fv);
    logits_k<<<NB, 512>>>(cls_w, cls_b, out_logits);
    loss_k<<<1, 32>>>(out_loss);

    // don't signal completion before side-stream attnw is done
    cudaStreamWaitEvent(0, g_ss.joinA, 0);
}

// round 16
// speedup vs baseline: 1.1754x; 1.0047x over previous
#include <cuda_runtime.h>
#include <cuda_fp16.h>
#include <math.h>
#include <stdint.h>

#define NB   32
#define NS   256
#define ND   512
#define NH   8
#define NE   8
#define NHID 2048
#define NPD  588
#define NPDP 608
#define NTOK 8192
#define NA   16384

#define SZ_LN   ((size_t)NTOK * ND)
#define SZ_P    ((size_t)NTOK * NPDP)
#define SZ_ATTN ((size_t)NB * NH * NS * NS)
#define SZ_H    ((size_t)NA * NHID)
#define SZ_W    ((size_t)NE * ND * NHID)
#define SZ_DD   ((size_t)ND * ND)

// ---------------- fp32 scratch -------------------------------------------------
__device__ float g_e[NTOK * ND];
__device__ float g_attn[NB * NH * NS * NS];
__device__ float g_probs[NTOK * NE];
__device__ float g_gate[NA];
__device__ int   g_perm[NE * NA];
__device__ int   g_cnt[NE];        // working counter (reset per layer)
__device__ int   g_cnt0[NE];       // layer-1 snapshot
__device__ float g_imp0[NE];       // layer-1 importance
__device__ float g_imp1[NE];       // layer-2 importance
__device__ float g_contrib[NA * ND];
__device__ float g_part[NB * 8 * ND];
__device__ float g_bqkv[3 * ND];

// ---------------- split fp16 buffers (hi at [0], lo at [SIZE] per segment) -----
__device__ __half g_p16[2 * SZ_P];
__device__ __half g_ln16[2 * SZ_LN];
__device__ __half g_qkv16[6 * SZ_LN];
__device__ __half g_attn16[2 * SZ_ATTN];
__device__ __half g_ctx16[2 * SZ_LN];
__device__ __half g_h16[2 * SZ_H];
__device__ __half g_pew16[2 * NPDP * ND];
__device__ __half g_wqkv16[6 * SZ_DD];
__device__ __half g_wo16[2 * SZ_DD];
__device__ __half g_w1a16[2 * SZ_W];
__device__ __half g_w2a16[2 * SZ_W];
__device__ __half g_w1b16[2 * SZ_W];
__device__ __half g_w2b16[2 * SZ_W];

// ---------------- persistent side stream ---------------------------------------
struct SideStream {
    cudaStream_t s;
    cudaEvent_t fork, joinW, joinM, attnev, joinA;
    SideStream() {
        cudaStreamCreateWithFlags(&s, cudaStreamNonBlocking);
        cudaEventCreateWithFlags(&fork,   cudaEventDisableTiming);
        cudaEventCreateWithFlags(&joinW,  cudaEventDisableTiming);
        cudaEventCreateWithFlags(&joinM,  cudaEventDisableTiming);
        cudaEventCreateWithFlags(&attnev, cudaEventDisableTiming);
        cudaEventCreateWithFlags(&joinA,  cudaEventDisableTiming);
    }
};
static SideStream g_ss;

__device__ __forceinline__ float gelu_exact(float v) {
    return 0.5f * v * (1.0f + erff(v * 0.70710678118654752440f));
}
__device__ __forceinline__ void split2(float v0, float v1, __half* oh, __half* ol) {
    __half h0 = __float2half_rn(v0), h1 = __float2half_rn(v1);
    *(__half2*)oh = __halves2half2(h0, h1);
    *(__half2*)ol = __halves2half2(__float2half_rn(v0 - __half2float(h0)),
                                   __float2half_rn(v1 - __half2float(h1)));
}

// ---------------- mma.sync helpers ----------------------------------------------
__device__ __forceinline__ void ldsm4(unsigned* r, unsigned addr) {
    asm volatile("ldmatrix.sync.aligned.m8n8.x4.shared.b16 {%0,%1,%2,%3}, [%4];\n"
        : "=r"(r[0]), "=r"(r[1]), "=r"(r[2]), "=r"(r[3]) : "r"(addr));
}
__device__ __forceinline__ void ldsm4t(unsigned* r, unsigned addr) {
    asm volatile("ldmatrix.sync.aligned.m8n8.x4.trans.shared.b16 {%0,%1,%2,%3}, [%4];\n"
        : "=r"(r[0]), "=r"(r[1]), "=r"(r[2]), "=r"(r[3]) : "r"(addr));
}
__device__ __forceinline__ void mma16816(float* c, const unsigned* a, const unsigned* b) {
    asm volatile("mma.sync.aligned.m16n8k16.row.col.f32.f16.f16.f32 "
        "{%0,%1,%2,%3}, {%4,%5,%6,%7}, {%8,%9}, {%0,%1,%2,%3};\n"
        : "+f"(c[0]), "+f"(c[1]), "+f"(c[2]), "+f"(c[3])
        : "r"(a[0]), "r"(a[1]), "r"(a[2]), "r"(a[3]), "r"(b[0]), "r"(b[1]));
}
__device__ __forceinline__ void cpa16(unsigned dst, const void* src, bool p) {
    int sz = p ? 16 : 0;
    asm volatile("cp.async.cg.shared.global [%0], [%1], 16, %2;\n"
        :: "r"(dst), "l"(src), "r"(sz));
}

// ---------------- modes --------------------------------------------------------
#define M_PE   0
#define M_QKV  1
#define M_PROJ 2
#define M_SC   3
#define M_AV   4
#define M_FF1  5
#define M_FF2  6

template <int MODE>
__global__ __launch_bounds__(256) void mm_k(
    const __half* __restrict__ Ag, const __half* __restrict__ Bg,
    const float* __restrict__ bias, const float* __restrict__ extra,
    void* __restrict__ Og)
{
    constexpr int K   = (MODE == M_PE) ? NPDP : (MODE == M_SC) ? 64 :
                        (MODE == M_AV) ? 256 : (MODE == M_FF2) ? 2048 : 512;
    constexpr int LDA = K;
    constexpr int LDB = (MODE == M_SC || MODE == M_AV) ? 64 :
                        (MODE == M_FF1) ? 2048 : 512;
    constexpr bool NT = (MODE == M_SC);
    constexpr bool GATHER = (MODE == M_FF1) || (MODE == M_FF2);
    constexpr int SHIFT = (MODE == M_FF1) ? 1 : 0;
    constexpr int BN = (MODE == M_AV || MODE == M_SC) ? 64 : 128;
    constexpr int WN = BN / 4;
    constexpr int NF = WN / 8;
    constexpr int KT = K / 16;
    constexpr size_t ALO =
        (MODE == M_PE)  ? SZ_P :
        (MODE == M_SC || MODE == M_QKV || MODE == M_PROJ || MODE == M_FF1) ? SZ_LN :
        (MODE == M_AV)  ? SZ_ATTN : SZ_H;
    constexpr size_t BLO =
        (MODE == M_PE)  ? (size_t)NPDP * ND :
        (MODE == M_QKV || MODE == M_PROJ) ? SZ_DD :
        (MODE == M_SC || MODE == M_AV) ? SZ_LN : SZ_W;
    constexpr size_t OLO =
        (MODE == M_QKV || MODE == M_AV) ? SZ_LN : SZ_H;
    constexpr int AST = 128 * 24;
    constexpr int BST = NT ? BN * 24 : 16 * BN;

    __shared__ __align__(16) __half As[2][2][AST];
    __shared__ __align__(16) __half Bs[2][2][BST];
    __shared__ int s_idx[128];

    int tid = threadIdx.x;
    int bz = blockIdx.z;
    int row0 = blockIdx.y * 128, col0 = blockIdx.x * BN;

    const __half* Ah = Ag;
    const __half* Bh = Bg;
    if (MODE == M_SC)  { Ah += (size_t)bz * 256 * 64; Bh += (size_t)bz * 256 * 64; }
    if (MODE == M_AV)  { Ah += (size_t)bz * 65536;    Bh += (size_t)bz * 256 * 64; }
    if (MODE == M_QKV) { Bh += (size_t)bz * 2 * SZ_DD; }
    if (MODE == M_FF1) { Bh += (size_t)bz * 512 * 2048; }
    if (MODE == M_FF2) { Bh += (size_t)bz * 2048 * 512; }
    const __half* Al = Ah + ALO;
    const __half* Bl = Bh + BLO;

    if (GATHER) {
        int cnt = g_cnt[bz];
        if (row0 >= cnt) return;
        if (tid < 128) {
            int r = row0 + tid;
            s_idx[tid] = (r < cnt) ? g_perm[bz * NA + r] : -1;
        }
        __syncthreads();
    }

    int a_row = tid >> 1, a_ch = tid & 1;
    unsigned a_dst = (unsigned)((a_row * 24 + a_ch * 8) * 2);
    const __half* a_srch; const __half* a_srcl; bool a_pred;
    if (GATHER) {
        int a = s_idx[a_row];
        a_pred = (a >= 0);
        size_t off = a_pred ? (size_t)(a >> SHIFT) * LDA + a_ch * 8 : 0;
        a_srch = Ah + off; a_srcl = Al + off;
    } else {
        a_pred = true;
        size_t off = (size_t)(row0 + a_row) * LDA + a_ch * 8;
        a_srch = Ah + off; a_srcl = Al + off;
    }
    unsigned b_dst = 0; const __half* b_srch = Bh; const __half* b_srcl = Bh;
    bool b_val;
    if (!NT) {
        b_val = tid < (16 * BN / 8);
        int row = tid / (BN / 8), cn = tid % (BN / 8);
        int sw = cn ^ (row & 7);
        b_dst = (unsigned)((row * BN + sw * 8) * 2);
        size_t off = (size_t)row * LDB + col0 + cn * 8;
        b_srch = Bh + off; b_srcl = Bl + off;
    } else {
        b_val = tid < (BN * 2);
        int nr = tid >> 1, ch = tid & 1;
        b_dst = (unsigned)((nr * 24 + ch * 8) * 2);
        size_t off = (size_t)(col0 + nr) * LDB + ch * 8;
        b_srch = Bh + off; b_srcl = Bl + off;
    }

    unsigned as_base = (unsigned)__cvta_generic_to_shared(&As[0][0][0]);
    unsigned bs_base = (unsigned)__cvta_generic_to_shared(&Bs[0][0][0]);

    auto issue = [&](int kt, int buf) {
        unsigned abh = as_base + (buf * 2 + 0) * AST * 2;
        unsigned abl = as_base + (buf * 2 + 1) * AST * 2;
        cpa16(abh + a_dst, a_srch + (size_t)kt * 16, a_pred);
        cpa16(abl + a_dst, a_srcl + (size_t)kt * 16, a_pred);
        if (b_val) {
            unsigned bbh = bs_base + (buf * 2 + 0) * BST * 2;
            unsigned bbl = bs_base + (buf * 2 + 1) * BST * 2;
            size_t off = NT ? (size_t)kt * 16 : (size_t)kt * 16 * LDB;
            cpa16(bbh + b_dst, b_srch + off, true);
            cpa16(bbl + b_dst, b_srcl + off, true);
        }
        asm volatile("cp.async.commit_group;\n");
    };

    int lane = tid & 31;
    int warp = tid >> 5;
    int wm = warp >> 2, wn = warp & 3;

    float acc[4][NF][4];
#pragma unroll
    for (int i = 0; i < 4; i++)
#pragma unroll
        for (int j = 0; j < NF; j++)
#pragma unroll
            for (int t = 0; t < 4; t++) acc[i][j][t] = 0.f;

    issue(0, 0);
#pragma unroll 1
    for (int kt = 0; kt < KT; kt++) {
        int buf = kt & 1;
        asm volatile("cp.async.wait_group 0;\n");
        __syncthreads();
        if (kt + 1 < KT) issue(kt + 1, buf ^ 1);
        unsigned abh = as_base + (buf * 2 + 0) * AST * 2;
        unsigned abl = as_base + (buf * 2 + 1) * AST * 2;
        unsigned bbh = bs_base + (buf * 2 + 0) * BST * 2;
        unsigned bbl = bs_base + (buf * 2 + 1) * BST * 2;

        unsigned ah[4][4], al[4][4];
#pragma unroll
        for (int i = 0; i < 4; i++) {
            int m = wm * 64 + i * 16 + (lane & 15);
            int ch = lane >> 4;
            unsigned ad = (unsigned)((m * 24 + ch * 8) * 2);
            ldsm4(ah[i], abh + ad);
            ldsm4(al[i], abl + ad);
        }
        unsigned brh[2 * NF], brl[2 * NF];
#pragma unroll
        for (int jj = 0; jj < NF / 2; jj++) {
            int n0 = wn * WN + jj * 16;
            if (!NT) {
                int k = lane & 15;
                int cn = (n0 >> 3) + (lane >> 4);
                int sw = cn ^ (k & 7);
                unsigned bd = (unsigned)((k * BN + sw * 8) * 2);
                ldsm4t(&brh[jj * 4], bbh + bd);
                ldsm4t(&brl[jj * 4], bbl + bd);
            } else {
                int n = n0 + ((lane >> 4) << 3) + (lane & 7);
                int ch = (lane >> 3) & 1;
                unsigned bd = (unsigned)((n * 24 + ch * 8) * 2);
                ldsm4(&brh[jj * 4], bbh + bd);
                ldsm4(&brl[jj * 4], bbl + bd);
            }
        }
#pragma unroll
        for (int i = 0; i < 4; i++)
#pragma unroll
            for (int j = 0; j < NF; j++) {
                mma16816(acc[i][j], ah[i], &brh[j * 2]);
                mma16816(acc[i][j], al[i], &brh[j * 2]);
                mma16816(acc[i][j], ah[i], &brl[j * 2]);
            }
    }

    int rl = lane >> 2, cp2 = (lane & 3) * 2;
#pragma unroll
    for (int i = 0; i < 4; i++) {
#pragma unroll
        for (int hh = 0; hh < 2; hh++) {
            int rr = wm * 64 + i * 16 + rl + hh * 8;
            int r = row0 + rr;
            int aidx = 0;
            if (GATHER) {
                aidx = s_idx[rr];
                if (aidx < 0) continue;
            }
#pragma unroll
            for (int j = 0; j < NF; j++) {
                int c = col0 + wn * WN + j * 8 + cp2;
                float v0 = acc[i][j][hh * 2 + 0];
                float v1 = acc[i][j][hh * 2 + 1];
                if (MODE == M_PE) {
                    float* O = (float*)Og;
                    v0 += bias[c]     + extra[(size_t)(r & 255) * 512 + c];
                    v1 += bias[c + 1] + extra[(size_t)(r & 255) * 512 + c + 1];
                    O[(size_t)r * 512 + c] = v0;
                    O[(size_t)r * 512 + c + 1] = v1;
                } else if (MODE == M_QKV) {
                    __half* O = (__half*)Og + (size_t)bz * 2 * SZ_LN;
                    const float* bi = bias + bz * 512;
                    v0 += bi[c]; v1 += bi[c + 1];
                    int b = r >> 8, s = r & 255, hd = c >> 6, ii = c & 63;
                    size_t o = (size_t)(((b << 3) + hd) * 256 + s) * 64 + ii;
                    split2(v0, v1, O + o, O + OLO + o);
                } else if (MODE == M_PROJ) {
                    float* O = (float*)Og;
                    v0 += bias[c]     + extra[(size_t)r * 512 + c];
                    v1 += bias[c + 1] + extra[(size_t)r * 512 + c + 1];
                    O[(size_t)r * 512 + c] = v0;
                    O[(size_t)r * 512 + c + 1] = v1;
                } else if (MODE == M_SC) {
                    float* O = (float*)Og + (size_t)bz * 65536;
                    O[(size_t)r * 256 + c] = v0 * 0.125f;
                    O[(size_t)r * 256 + c + 1] = v1 * 0.125f;
                } else if (MODE == M_AV) {
                    __half* O = (__half*)Og;
                    int b = bz >> 3, hd = bz & 7;
                    size_t o = (size_t)((b << 8) + r) * 512 + (hd << 6) + c;
                    split2(v0, v1, O + o, O + OLO + o);
                } else if (MODE == M_FF1) {
                    __half* O = (__half*)Og;
                    const float* bi = bias + bz * 2048;
                    v0 = gelu_exact(v0 + bi[c]);
                    v1 = gelu_exact(v1 + bi[c + 1]);
                    size_t o = (size_t)aidx * 2048 + c;
                    split2(v0, v1, O + o, O + OLO + o);
                } else {
                    float* O = (float*)Og;
                    const float* bi = bias + bz * 512;
                    O[(size_t)aidx * 512 + c] = v0 + bi[c];
                    O[(size_t)aidx * 512 + c + 1] = v1 + bi[c + 1];
                }
            }
        }
    }
}

// ---------------- conversions ---------------------------------------------------
struct __align__(8) h2x2 { __half2 a, b; };

__device__ __forceinline__ void conv_elem4(const float* in, __half* outh, size_t n,
                                           size_t i) {
    float4 f = *(const float4*)(in + i);
    h2x2 H, L;
    H.a = __floats2half2_rn(f.x, f.y);
    H.b = __floats2half2_rn(f.z, f.w);
    float2 f0 = __half22float2(H.a), f1 = __half22float2(H.b);
    L.a = __floats2half2_rn(f.x - f0.x, f.y - f0.y);
    L.b = __floats2half2_rn(f.z - f1.x, f.w - f1.y);
    *(h2x2*)(outh + i) = H;
    *(h2x2*)(outh + n + i) = L;
}

__global__ __launch_bounds__(256) void conv4_k(
    const float* __restrict__ s0, const float* __restrict__ s1,
    const float* __restrict__ s2, const float* __restrict__ s3,
    __half* __restrict__ d0, __half* __restrict__ d1,
    __half* __restrict__ d2, __half* __restrict__ d3, size_t n)
{
    const float* src = (blockIdx.z == 0) ? s0 : (blockIdx.z == 1) ? s1 :
                       (blockIdx.z == 2) ? s2 : s3;
    __half* dst = (blockIdx.z == 0) ? d0 : (blockIdx.z == 1) ? d1 :
                  (blockIdx.z == 2) ? d2 : d3;
    size_t i = ((size_t)blockIdx.x * 256 + threadIdx.x) * 4;
    if (i < n) conv_elem4(src, dst, n, i);
}

__global__ __launch_bounds__(256) void convpe_k(const float* __restrict__ w) {
    int i = (blockIdx.x * 256 + threadIdx.x) * 4;
    if (i >= NPDP * ND) return;
    int j = i >> 9;
    float4 f = make_float4(0.f, 0.f, 0.f, 0.f);
    if (j < NPD) f = *(const float4*)(w + i);
    h2x2 H, L;
    H.a = __floats2half2_rn(f.x, f.y);
    H.b = __floats2half2_rn(f.z, f.w);
    float2 f0 = __half22float2(H.a), f1 = __half22float2(H.b);
    L.a = __floats2half2_rn(f.x - f0.x, f.y - f0.y);
    L.b = __floats2half2_rn(f.z - f1.x, f.w - f1.y);
    *(h2x2*)(g_pew16 + i) = H;
    *(h2x2*)(g_pew16 + NPDP * ND + i) = L;
}

// bqkv gather + global init
__global__ void bqkv_k(const float* __restrict__ bq, const float* __restrict__ bk,
                       const float* __restrict__ bv) {
    int i = blockIdx.x * 256 + threadIdx.x;
    if (blockIdx.x == 0 && threadIdx.x < 8) {
        g_cnt[threadIdx.x] = 0;
        g_imp0[threadIdx.x] = 0.f;
        g_imp1[threadIdx.x] = 0.f;
    }
    if (i >= 1536) return;
    g_bqkv[i] = (i < 512) ? bq[i] : (i < 1024) ? bk[i - 512] : bv[i - 1024];
}

// ---------------- patch gather (ALU-lean: one thread per (p1,p2)) ---------------
__global__ __launch_bounds__(256) void patch_k(const float* __restrict__ x) {
    __shared__ float sp[NPD];
    int t = blockIdx.x;
    int b = t >> 8, s = t & 255;
    int hi = s >> 4, wi = s & 15;
    int tid = threadIdx.x;
    const float* xb = x + ((size_t)b * 3 * 224 + hi * 14) * 224 + wi * 14;
    if (tid < 196) {
        int p1 = tid / 14, p2 = tid - p1 * 14;
        int off = p1 * 224 + p2;
        float f0 = xb[off];
        float f1 = xb[50176 + off];
        float f2 = xb[100352 + off];
        int d = tid * 3;
        sp[d] = f0; sp[d + 1] = f1; sp[d + 2] = f2;
    }
    __syncthreads();
    size_t base = (size_t)t * NPDP;
    {
        int j = tid;                       // 0..255
        float f = (j < NPD) ? sp[j] : 0.f;
        __half h = __float2half_rn(f);
        g_p16[base + j] = h;
        g_p16[SZ_P + base + j] = __float2half_rn(f - __half2float(h));
        j += 256;                          // 256..511
        f = sp[j];
        h = __float2half_rn(f);
        g_p16[base + j] = h;
        g_p16[SZ_P + base + j] = __float2half_rn(f - __half2float(h));
        j += 256;                          // 512..607
        if (j < NPDP) {
            f = (j < NPD) ? sp[j] : 0.f;
            h = __float2half_rn(f);
            g_p16[base + j] = h;
            g_p16[SZ_P + base + j] = __float2half_rn(f - __half2float(h));
        }
    }
}

// ---------------- LN body (fp16 split out only) ---------------------------------
__device__ __forceinline__ void ln_body(
    int row, int tid, float4 v,
    const float* __restrict__ gw, const float* __restrict__ bw,
    __half* __restrict__ out16)
{
    float s = v.x + v.y + v.z + v.w;
    float q = v.x * v.x + v.y * v.y + v.z * v.z + v.w * v.w;
    __shared__ float ss[4], sq[4];
    for (int o = 16; o > 0; o >>= 1) {
        s += __shfl_xor_sync(0xffffffffu, s, o);
        q += __shfl_xor_sync(0xffffffffu, q, o);
    }
    if ((tid & 31) == 0) { ss[tid >> 5] = s; sq[tid >> 5] = q; }
    __syncthreads();
    s = ss[0] + ss[1] + ss[2] + ss[3];
    q = sq[0] + sq[1] + sq[2] + sq[3];
    float mean = s * (1.f / 512.f);
    float var  = q * (1.f / 512.f) - mean * mean;
    float inv  = rsqrtf(var + 1e-5f);
    float4 g4 = ((const float4*)gw)[tid];
    float4 b4 = ((const float4*)bw)[tid];
    float4 o;
    o.x = (v.x - mean) * inv * g4.x + b4.x;
    o.y = (v.y - mean) * inv * g4.y + b4.y;
    o.z = (v.z - mean) * inv * g4.z + b4.z;
    o.w = (v.w - mean) * inv * g4.w + b4.w;
    size_t base = (size_t)row * 512 + tid * 4;
    split2(o.x, o.y, out16 + base,     out16 + SZ_LN + base);
    split2(o.z, o.w, out16 + base + 2, out16 + SZ_LN + base + 2);
}

__global__ __launch_bounds__(128) void ln_k(
    const float* __restrict__ in, const float* __restrict__ gw,
    const float* __restrict__ bw, __half* __restrict__ out16)
{
    int row = blockIdx.x, tid = threadIdx.x;
    float4 v = ((const float4*)(in + (size_t)row * 512))[tid];
    ln_body(row, tid, v, gw, bw, out16);
}

// combine+LN3; block 0 also snapshots layer-1 counts and resets working counter
__global__ __launch_bounds__(128) void cln_k(
    const float* __restrict__ gw, const float* __restrict__ bw,
    __half* __restrict__ out16)
{
    int row = blockIdx.x, tid = threadIdx.x;
    if (row == 0 && tid < 8) { g_cnt0[tid] = g_cnt[tid]; g_cnt[tid] = 0; }
    float g1 = g_gate[2 * row], g2 = g_gate[2 * row + 1];
    float4 a = ((const float4*)(g_contrib + (size_t)(2 * row) * 512))[tid];
    float4 b = ((const float4*)(g_contrib + (size_t)(2 * row + 1) * 512))[tid];
    float4 v;
    v.x = g1 * a.x + g2 * b.x; v.y = g1 * a.y + g2 * b.y;
    v.z = g1 * a.z + g2 * b.z; v.w = g1 * a.w + g2 * b.w;
    ln_body(row, tid, v, gw, bw, out16);
}

__global__ __launch_bounds__(512) void fvc_k(float* __restrict__ part) {
    int b = blockIdx.x, seg = blockIdx.y, d = threadIdx.x;
    int t0 = b * 256 + seg * 32;
    float s = 0.f;
    for (int ss = 0; ss < 32; ss++) {
        int t = t0 + ss;
        float g1 = g_gate[2 * t], g2 = g_gate[2 * t + 1];
        s += g1 * g_contrib[(size_t)(2 * t) * 512 + d]
           + g2 * g_contrib[(size_t)(2 * t + 1) * 512 + d];
    }
    part[(size_t)(b * 8 + seg) * 512 + d] = s;
}

// ---------------- MoE router ----------------------------------------------------
__global__ __launch_bounds__(256) void router_k(const __half* __restrict__ xin,
                                                const float* __restrict__ rw,
                                                const float* __restrict__ rb) {
    __shared__ float s_rw[8][512];
    __shared__ float s_rb[8];
    int tid = threadIdx.x;
    for (int i = tid; i < 4096; i += 256) s_rw[i >> 9][i & 511] = rw[(i & 511) * 8 + (i >> 9)];
    if (tid < 8) s_rb[tid] = rb[tid];
    __syncthreads();
    int t = (blockIdx.x << 3) + (tid >> 5);
    int lane = tid & 31;
    const __half* xh = xin + (size_t)t * 512;
    const __half* xl = xh + SZ_LN;
    float acc[8] = {};
    for (int k = lane * 2; k < 512; k += 64) {
        __half2 h = *(const __half2*)(xh + k);
        __half2 l = *(const __half2*)(xl + k);
        float2 hf = __half22float2(h), lf = __half22float2(l);
        float x0 = hf.x + lf.x, x1 = hf.y + lf.y;
#pragma unroll
        for (int e = 0; e < 8; e++)
            acc[e] += x0 * s_rw[e][k] + x1 * s_rw[e][k + 1];
    }
#pragma unroll
    for (int e = 0; e < 8; e++)
        for (int o = 16; o > 0; o >>= 1) acc[e] += __shfl_xor_sync(0xffffffffu, acc[e], o);
    if (lane == 0) {
        float mx = -1e30f;
#pragma unroll
        for (int e = 0; e < 8; e++) { acc[e] += s_rb[e]; mx = fmaxf(mx, acc[e]); }
        float sum = 0.f;
#pragma unroll
        for (int e = 0; e < 8; e++) { acc[e] = __expf(acc[e] - mx); sum += acc[e]; }
        float inv = 1.f / sum;
#pragma unroll
        for (int e = 0; e < 8; e++) g_probs[t * 8 + e] = acc[e] * inv;
    }
}

// ---------------- softmax over attn rows ----------------------------------------
__global__ __launch_bounds__(256) void softmax_attn_k() {
    int row  = (blockIdx.x << 3) + (threadIdx.x >> 5);
    int lane = threadIdx.x & 31;
    const float4* p = (const float4*)(g_attn + (size_t)row * 256);
    float4 a = p[lane], b = p[lane + 32];
    float m = fmaxf(fmaxf(fmaxf(a.x, a.y), fmaxf(a.z, a.w)),
                    fmaxf(fmaxf(b.x, b.y), fmaxf(b.z, b.w)));
    for (int o = 16; o > 0; o >>= 1) m = fmaxf(m, __shfl_xor_sync(0xffffffffu, m, o));
    a.x = __expf(a.x - m); a.y = __expf(a.y - m);
    a.z = __expf(a.z - m); a.w = __expf(a.w - m);
    b.x = __expf(b.x - m); b.y = __expf(b.y - m);
    b.z = __expf(b.z - m); b.w = __expf(b.w - m);
    float s = a.x + a.y + a.z + a.w + b.x + b.y + b.z + b.w;
    for (int o = 16; o > 0; o >>= 1) s += __shfl_xor_sync(0xffffffffu, s, o);
    float inv = 1.f / s;
    a.x *= inv; a.y *= inv; a.z *= inv; a.w *= inv;
    b.x *= inv; b.y *= inv; b.z *= inv; b.w *= inv;
    size_t base = (size_t)row * 256;
    split2(a.x, a.y, g_attn16 + base + lane * 4,     g_attn16 + SZ_ATTN + base + lane * 4);
    split2(a.z, a.w, g_attn16 + base + lane * 4 + 2, g_attn16 + SZ_ATTN + base + lane * 4 + 2);
    split2(b.x, b.y, g_attn16 + base + 128 + lane * 4,     g_attn16 + SZ_ATTN + base + 128 + lane * 4);
    split2(b.z, b.w, g_attn16 + base + 128 + lane * 4 + 2, g_attn16 + SZ_ATTN + base + 128 + lane * 4 + 2);
}

// ---------------- attn_w --------------------------------------------------------
__global__ __launch_bounds__(256) void attnw_k(float* __restrict__ out) {
    int bq = blockIdx.x, tid = threadIdx.x;
    int b = bq >> 8, qr = bq & 255;
    float s = 0.f;
#pragma unroll
    for (int h = 0; h < 8; h++) {
        size_t off = ((size_t)((b << 3) + h)) * 65536 + (qr << 8) + tid;
        s += __half2float(g_attn16[off]) + __half2float(g_attn16[SZ_ATTN + off]);
    }
    s *= 0.125f;
    __shared__ float red[8];
    float m = s;
    for (int o = 16; o > 0; o >>= 1) m = fmaxf(m, __shfl_xor_sync(0xffffffffu, m, o));
    if ((tid & 31) == 0) red[tid >> 5] = m;
    __syncthreads();
    m = red[0];
#pragma unroll
    for (int w = 1; w < 8; w++) m = fmaxf(m, red[w]);
    float ex = __expf(s - m);
    float sum = ex;
    __syncthreads();
    for (int o = 16; o > 0; o >>= 1) sum += __shfl_xor_sync(0xffffffffu, sum, o);
    if ((tid & 31) == 0) red[tid >> 5] = sum;
    __syncthreads();
    sum = red[0] + red[1] + red[2] + red[3] + red[4] + red[5] + red[6] + red[7];
    out[(size_t)bq * 256 + tid] = ex / sum;
}

// ---------------- dispatch / loss -----------------------------------------------
__global__ __launch_bounds__(256) void dispatch_k(float* __restrict__ impbuf) {
    __shared__ int   s_cnt[8];
    __shared__ float s_imp[8];
    __shared__ int   s_base[8];
    int tid = threadIdx.x;
    if (tid < 8) { s_cnt[tid] = 0; s_imp[tid] = 0.f; }
    __syncthreads();
    int t = blockIdx.x * 256 + tid;
    float p[8];
#pragma unroll
    for (int e = 0; e < 8; e++) { p[e] = g_probs[t * 8 + e]; atomicAdd(&s_imp[e], p[e]); }
    int e1 = 0; float v1 = p[0];
#pragma unroll
    for (int e = 1; e < 8; e++) if (p[e] > v1) { v1 = p[e]; e1 = e; }
    int e2 = -1; float v2 = -1e30f;
#pragma unroll
    for (int e = 0; e < 8; e++) if (e != e1 && p[e] > v2) { v2 = p[e]; e2 = e; }
    int lp1 = atomicAdd(&s_cnt[e1], 1);
    int lp2 = atomicAdd(&s_cnt[e2], 1);
    __syncthreads();
    if (tid < 8) {
        s_base[tid] = atomicAdd(&g_cnt[tid], s_cnt[tid]);
        atomicAdd(&impbuf[tid], s_imp[tid]);
    }
    __syncthreads();
    g_perm[e1 * NA + s_base[e1] + lp1] = t * 2;
    g_perm[e2 * NA + s_base[e2] + lp2] = t * 2 + 1;
    g_gate[t * 2]     = v1;
    g_gate[t * 2 + 1] = v2;
}

// single end-of-graph loss: layer-1 from snapshot, layer-2 from working counter
__global__ void loss_k(float* out_loss) {
    int tid = threadIdx.x;
    float v = 0.f;
    if (tid < 8) {
        v  = 8.f * ((float)g_cnt0[tid] * (1.f / 8192.f)) * (g_imp0[tid] * (1.f / 8192.f));
        v += 8.f * ((float)g_cnt[tid]  * (1.f / 8192.f)) * (g_imp1[tid] * (1.f / 8192.f));
    }
    for (int o = 16; o > 0; o >>= 1) v += __shfl_xor_sync(0xffffffffu, v, o);
    if (tid == 0) out_loss[0] = v;
}

// ---------------- fused fv + logits ---------------------------------------------
// 32 blocks x 512 threads; computes fv row into smem (+ writes out_fv), then logits.
__global__ __launch_bounds__(512) void fvlog_k(const float* __restrict__ part,
                                               const float* __restrict__ W,
                                               const float* __restrict__ bias,
                                               float* __restrict__ out_fv,
                                               float* __restrict__ out_logits) {
    __shared__ float sf[512];
    int b = blockIdx.x, d = threadIdx.x;
    float s = 0.f;
#pragma unroll
    for (int seg = 0; seg < 8; seg++)
        s += part[(size_t)(b * 8 + seg) * 512 + d];
    s *= (1.f / 256.f);
    sf[d] = s;
    out_fv[b * 512 + d] = s;
    __syncthreads();
    float acc = 0.f;
    for (int k = 0; k < 512; k++) acc += sf[k] * W[k * 512 + d];
    out_logits[b * 512 + d] = acc + bias[d];
}

// ---------------- host launch ---------------------------------------------------
extern "C" void kernel_launch(void* const* d_in, const int* in_sizes, int n_in,
                              void* d_out, int out_size) {
    const float* x     = (const float*)d_in[0];
    const float* pe_w  = (const float*)d_in[1];
    const float* pe_b  = (const float*)d_in[2];
    const float* pos   = (const float*)d_in[3];
    const float* ln1_g = (const float*)d_in[4];
    const float* ln1_b = (const float*)d_in[5];
    const float* ln2_g = (const float*)d_in[6];
    const float* ln2_b = (const float*)d_in[7];
    const float* ln3_g = (const float*)d_in[8];
    const float* ln3_b = (const float*)d_in[9];
    const float* wq = (const float*)d_in[10];
    const float* bq = (const float*)d_in[11];
    const float* wk = (const float*)d_in[12];
    const float* bk = (const float*)d_in[13];
    const float* wv = (const float*)d_in[14];
    const float* bv = (const float*)d_in[15];
    const float* wo = (const float*)d_in[16];
    const float* bo = (const float*)d_in[17];
    const float* m1_rw = (const float*)d_in[18];
    const float* m1_rb = (const float*)d_in[19];
    const float* m1_w1 = (const float*)d_in[20];
    const float* m1_b1 = (const float*)d_in[21];
    const float* m1_w2 = (const float*)d_in[22];
    const float* m1_b2 = (const float*)d_in[23];
    const float* m2_rw = (const float*)d_in[24];
    const float* m2_rb = (const float*)d_in[25];
    const float* m2_w1 = (const float*)d_in[26];
    const float* m2_b1 = (const float*)d_in[27];
    const float* m2_w2 = (const float*)d_in[28];
    const float* m2_b2 = (const float*)d_in[29];
    const float* cls_w = (const float*)d_in[30];
    const float* cls_b = (const float*)d_in[31];

    float* out = (float*)d_out;
    float* out_logits = out;
    float* out_fv     = out + 16384;
    float* out_loss   = out + 32768;
    float* out_attnw  = out + 32769;

    float *p_e, *p_attn, *p_contrib, *p_part;
    __half *p_p16, *p_ln16, *p_qkv16, *p_attn16, *p_ctx16, *p_h16;
    __half *p_pew16, *p_wqkv16, *p_wo16;
    __half *p_w1a, *p_w2a, *p_w1b, *p_w2b;
    float *p_imp0, *p_imp1;
    cudaGetSymbolAddress((void**)&p_e,       g_e);
    cudaGetSymbolAddress((void**)&p_attn,    g_attn);
    cudaGetSymbolAddress((void**)&p_contrib, g_contrib);
    cudaGetSymbolAddress((void**)&p_part,    g_part);
    cudaGetSymbolAddress((void**)&p_p16,     g_p16);
    cudaGetSymbolAddress((void**)&p_ln16,    g_ln16);
    cudaGetSymbolAddress((void**)&p_qkv16,   g_qkv16);
    cudaGetSymbolAddress((void**)&p_attn16,  g_attn16);
    cudaGetSymbolAddress((void**)&p_ctx16,   g_ctx16);
    cudaGetSymbolAddress((void**)&p_h16,     g_h16);
    cudaGetSymbolAddress((void**)&p_pew16,   g_pew16);
    cudaGetSymbolAddress((void**)&p_wqkv16,  g_wqkv16);
    cudaGetSymbolAddress((void**)&p_wo16,    g_wo16);
    cudaGetSymbolAddress((void**)&p_w1a,     g_w1a16);
    cudaGetSymbolAddress((void**)&p_w2a,     g_w2a16);
    cudaGetSymbolAddress((void**)&p_w1b,     g_w1b16);
    cudaGetSymbolAddress((void**)&p_w2b,     g_w2b16);
    cudaGetSymbolAddress((void**)&p_imp0,    g_imp0);
    cudaGetSymbolAddress((void**)&p_imp1,    g_imp1);
    float* p_bqkv; cudaGetSymbolAddress((void**)&p_bqkv, g_bqkv);

    // fork side stream: bqkv + attention-weight convs (early), then big MoE convs
    cudaEventRecord(g_ss.fork, 0);
    cudaStreamWaitEvent(g_ss.s, g_ss.fork, 0);
    bqkv_k<<<6, 256, 0, g_ss.s>>>(bq, bk, bv);
    conv4_k<<<dim3(256, 1, 4), 256, 0, g_ss.s>>>(
        wq, wk, wv, wo,
        p_wqkv16, p_wqkv16 + 2 * SZ_DD, p_wqkv16 + 4 * SZ_DD, p_wo16, SZ_DD);
    cudaEventRecord(g_ss.joinW, g_ss.s);
    conv4_k<<<dim3(8192, 1, 4), 256, 0, g_ss.s>>>(
        m1_w1, m1_w2, m2_w1, m2_w2, p_w1a, p_w2a, p_w1b, p_w2b, SZ_W);
    cudaEventRecord(g_ss.joinM, g_ss.s);

    // main: PE chain
    patch_k<<<NTOK, 256>>>(x);
    convpe_k<<<(NPDP * ND / 4 + 255) / 256, 256>>>(pe_w);
    mm_k<M_PE><<<dim3(4, 64), 256>>>(p_p16, p_pew16, pe_b, pos, p_e);

    ln_k<<<NTOK, 128>>>(p_e, ln1_g, ln1_b, p_ln16);
    cudaStreamWaitEvent(0, g_ss.joinW, 0);
    mm_k<M_QKV><<<dim3(4, 64, 3), 256>>>(p_ln16, p_wqkv16, p_bqkv, nullptr, p_qkv16);
    mm_k<M_SC><<<dim3(4, 2, 256), 256>>>(p_qkv16, p_qkv16 + 2 * SZ_LN,
                                         nullptr, nullptr, p_attn);
    softmax_attn_k<<<8192, 256>>>();
    cudaEventRecord(g_ss.attnev, 0);

    // side stream: attnw AFTER attnev is recorded (legal capture ordering)
    cudaStreamWaitEvent(g_ss.s, g_ss.attnev, 0);
    attnw_k<<<NTOK, 256, 0, g_ss.s>>>(out_attnw);
    cudaEventRecord(g_ss.joinA, g_ss.s);

    mm_k<M_AV><<<dim3(1, 2, 256), 256>>>(p_attn16, p_qkv16 + 4 * SZ_LN,
                                         nullptr, nullptr, p_ctx16);
    mm_k<M_PROJ><<<dim3(4, 64), 256>>>(p_ctx16, p_wo16, bo, p_e, p_e);

    // MoE layer 1
    ln_k<<<NTOK, 128>>>(p_e, ln2_g, ln2_b, p_ln16);
    router_k<<<1024, 256>>>(p_ln16, m1_rw, m1_rb);
    dispatch_k<<<32, 256>>>(p_imp0);
    cudaStreamWaitEvent(0, g_ss.joinM, 0);
    mm_k<M_FF1><<<dim3(16, 64, 8), 256>>>(p_ln16, p_w1a, m1_b1, nullptr, p_h16);
    mm_k<M_FF2><<<dim3(4, 64, 8), 256>>>(p_h16, p_w2a, m1_b2, nullptr, p_contrib);

    // combine + LN3 fused; block0 snapshots layer-1 counts + resets working counter
    cln_k<<<NTOK, 128>>>(ln3_g, ln3_b, p_ln16);

    // MoE layer 2
    router_k<<<1024, 256>>>(p_ln16, m2_rw, m2_rb);
    dispatch_k<<<32, 256>>>(p_imp1);
    mm_k<M_FF1><<<dim3(16, 64, 8), 256>>>(p_ln16, p_w1b, m2_b1, nullptr, p_h16);
    mm_k<M_FF2><<<dim3(4, 64, 8), 256>>>(p_h16, p_w2b, m2_b2, nullptr, p_contrib);

    // layer-2 combine fused into fv partials; o2 never materialized
    fvc_k<<<dim3(NB, 8), 512>>>(p_part);
    fvlog_k<<<NB, 512>>>(p_part, cls_w, cls_b, out_fv, out_logits);
    loss_k<<<1, 32>>>(out_loss);

    // don't signal completion before side-stream attnw is done
    cudaStreamWaitEvent(0, g_ss.joinA, 0);
}